// round 1
// baseline (speedup 1.0000x reference)
#include <cuda_runtime.h>
#include <math.h>

// Problem constants
#define TB 2
#define TS 1024
#define TD 2048
#define TH 16
#define TKV 4
#define THD 128
#define TE 8
#define TF 2048
#define TT (TB*TS)                 // 2048 tokens
#define OQKV ((TH+2*TKV)*THD)      // 3072
#define REP (TH/TKV)               // 4

// ---------------- scratch (device globals; no runtime allocation) ----------
__device__ float g_h[(size_t)TT*TD];          // LN outputs / MoE input x
__device__ float g_qkv[(size_t)TT*OQKV];      // qkv, later reused as attn-proj out
__device__ float g_scores[(size_t)TB*TH*TS*TS];
__device__ float g_attn[(size_t)TT*TH*THD];
__device__ float g_res[(size_t)TT*TD];        // residual fallback
__device__ float g_G[(size_t)TT*TF];
__device__ float g_U[(size_t)TT*TF];
__device__ int   g_elist[TE*TT];
__device__ float g_ew[TE*TT];
__device__ int   g_ecnt[TE];

// ---------------- reduction helpers ----------------
__device__ __forceinline__ float warp_sum(float v){
  #pragma unroll
  for(int o=16;o;o>>=1) v += __shfl_xor_sync(0xffffffffu, v, o);
  return v;
}
__device__ __forceinline__ float warp_max(float v){
  #pragma unroll
  for(int o=16;o;o>>=1) v = fmaxf(v, __shfl_xor_sync(0xffffffffu, v, o));
  return v;
}

// ---------------- LayerNorm ----------------
__global__ void ln_kernel(const float* __restrict__ x, const float* __restrict__ w,
                          float* __restrict__ y){
  int row = blockIdx.x;
  const float* xr = x + (size_t)row*TD;
  float* yr = y + (size_t)row*TD;
  float s=0.f, s2=0.f;
  for(int d=threadIdx.x; d<TD; d+=blockDim.x){ float v=xr[d]; s+=v; s2+=v*v; }
  __shared__ float shs[8], shs2[8];
  int lane=threadIdx.x&31, wp=threadIdx.x>>5;
  s = warp_sum(s); s2 = warp_sum(s2);
  if(!lane){ shs[wp]=s; shs2[wp]=s2; }
  __syncthreads();
  if (threadIdx.x < 32){
    float a = (threadIdx.x<8)? shs[threadIdx.x] : 0.f;
    float b = (threadIdx.x<8)? shs2[threadIdx.x] : 0.f;
    a = warp_sum(a); b = warp_sum(b);
    if(!threadIdx.x){ shs[0]=a; shs2[0]=b; }
  }
  __syncthreads();
  float mu = shs[0]*(1.f/TD);
  float var = shs2[0]*(1.f/TD) - mu*mu;
  float rstd = rsqrtf(var + 1e-5f);
  for(int d=threadIdx.x; d<TD; d+=blockDim.x)
    yr[d] = (xr[d]-mu)*rstd*w[d];
}

// ---------------- RoPE (in-place on q and k heads of qkv) ----------------
__global__ void rope_kernel(float* __restrict__ qkv,
                            const float* __restrict__ cosb,
                            const float* __restrict__ sinb){
  int idx = blockIdx.x*blockDim.x + threadIdx.x;
  const int total = TT*(TH+TKV)*(THD/2);
  if (idx >= total) return;
  int i  = idx & 63;
  int rest = idx >> 6;
  int hh = rest % (TH+TKV);
  int t  = rest / (TH+TKV);
  int s  = t % TS;
  float c  = cosb[s*THD + i];
  float sn = sinb[s*THD + i];
  float* p = qkv + (size_t)t*OQKV + hh*THD;
  float x1 = p[i], x2 = p[i+64];
  p[i]    = x1*c - x2*sn;
  p[i+64] = x2*c + x1*sn;
}

// ---------------- generic SGEMM ----------------
// C[M,N] = alpha * A[M,K] @ (BT ? B[N,K]^T : B[K,N])
// EPI 0: store. EPI 1: causal mask (col<=row ? v : -1e9). EPI 2: C[arow[m]] += aw[m]*v
// ADDR 0: plain. ADDR 1: attention scores addressing (per blockIdx.z = b*H+h).
// ADDR 2: attention PV addressing.
// GATHER: A row index via arow[].  cntp: device row count (overrides M).
template<bool BT, int EPI, int ADDR, bool GATHER>
__global__ __launch_bounds__(256) void sgemm(
    int M, int N, int Kk,
    const float* __restrict__ A, int lda,
    const float* __restrict__ B, int ldb,
    float* __restrict__ C, int ldc,
    float alpha,
    const int* __restrict__ arow,
    const float* __restrict__ aw,
    const int* __restrict__ cntp)
{
  constexpr int BM=128, BN=128, BK=8, TM=8, TN=8;
  if (ADDR==1){
    int b = blockIdx.z/TH, h = blockIdx.z%TH;
    A += (size_t)b*TS*OQKV + h*THD;
    B += (size_t)b*TS*OQKV + (TH + h/REP)*THD;
    C += (size_t)blockIdx.z*TS*TS;
  } else if (ADDR==2){
    int b = blockIdx.z/TH, h = blockIdx.z%TH;
    A += (size_t)blockIdx.z*TS*TS;
    B += (size_t)b*TS*OQKV + (TH+TKV + h/REP)*THD;
    C += (size_t)b*TS*(TH*THD) + h*THD;
  }
  int Meff = cntp ? *cntp : M;
  int row0 = blockIdx.y*BM, col0 = blockIdx.x*BN;
  if (row0 >= Meff) return;

  __shared__ float As[BK*BM];
  __shared__ float Bs[BK*BN];
  int tid = threadIdx.x;
  int aRow = tid>>1;            // 0..127
  int aCol = (tid&1)*4;         // 0 or 4
  int tr = tid>>4, tc = tid&15; // 16x16 thread grid

  float acc[TM][TN];
  #pragma unroll
  for(int i=0;i<TM;i++)
    #pragma unroll
    for(int j=0;j<TN;j++) acc[i][j]=0.f;

  for(int k0=0;k0<Kk;k0+=BK){
    // A tile -> As transposed [BK][BM]
    {
      int gm = row0 + aRow;
      float4 v = make_float4(0.f,0.f,0.f,0.f);
      if (gm < Meff){
        int src = GATHER ? arow[gm] : gm;
        v = *reinterpret_cast<const float4*>(A + (size_t)src*lda + k0 + aCol);
      }
      As[(aCol+0)*BM+aRow]=v.x;
      As[(aCol+1)*BM+aRow]=v.y;
      As[(aCol+2)*BM+aRow]=v.z;
      As[(aCol+3)*BM+aRow]=v.w;
    }
    // B tile -> Bs [BK][BN]
    if (BT){
      float4 v = *reinterpret_cast<const float4*>(B + (size_t)(col0+aRow)*ldb + k0 + aCol);
      Bs[(aCol+0)*BN+aRow]=v.x;
      Bs[(aCol+1)*BN+aRow]=v.y;
      Bs[(aCol+2)*BN+aRow]=v.z;
      Bs[(aCol+3)*BN+aRow]=v.w;
    } else {
      int bRow = tid>>5;          // 0..7
      int bCol = (tid&31)*4;      // 0..124
      float4 v = *reinterpret_cast<const float4*>(B + (size_t)(k0+bRow)*ldb + col0 + bCol);
      *reinterpret_cast<float4*>(&Bs[bRow*BN + bCol]) = v;
    }
    __syncthreads();

    #pragma unroll
    for(int k=0;k<BK;k++){
      float4 m0 = *reinterpret_cast<const float4*>(&As[k*BM + tr*TM]);
      float4 m1 = *reinterpret_cast<const float4*>(&As[k*BM + tr*TM + 4]);
      float4 n0 = *reinterpret_cast<const float4*>(&Bs[k*BN + tc*TN]);
      float4 n1 = *reinterpret_cast<const float4*>(&Bs[k*BN + tc*TN + 4]);
      float rM[8]={m0.x,m0.y,m0.z,m0.w,m1.x,m1.y,m1.z,m1.w};
      float rN[8]={n0.x,n0.y,n0.z,n0.w,n1.x,n1.y,n1.z,n1.w};
      #pragma unroll
      for(int i=0;i<TM;i++)
        #pragma unroll
        for(int j=0;j<TN;j++)
          acc[i][j] += rM[i]*rN[j];
    }
    __syncthreads();
  }

  #pragma unroll
  for(int i=0;i<TM;i++){
    int gm = row0 + tr*TM + i;
    if (gm < Meff){
      #pragma unroll
      for(int j=0;j<TN;j++){
        int gn = col0 + tc*TN + j;
        float v = acc[i][j]*alpha;
        if (EPI==0){
          C[(size_t)gm*ldc+gn] = v;
        } else if (EPI==1){
          C[(size_t)gm*ldc+gn] = (gn<=gm) ? v : -1e9f;
        } else {
          C[(size_t)arow[gm]*ldc+gn] += aw[gm]*v;
        }
      }
    }
  }
}

// ---------------- softmax over score rows ----------------
__global__ void softmax_kernel(float* __restrict__ s){
  float* r = s + (size_t)blockIdx.x*TS;
  int tid = threadIdx.x;
  int lane = tid&31, wp = tid>>5;
  __shared__ float sh[8];

  float mx = -1e30f;
  for(int d=tid; d<TS; d+=256) mx = fmaxf(mx, r[d]);
  mx = warp_max(mx);
  if(!lane) sh[wp]=mx;
  __syncthreads();
  if (tid<32){ float v=(tid<8)?sh[tid]:-1e30f; v=warp_max(v); if(!tid) sh[0]=v; }
  __syncthreads();
  mx = sh[0];
  __syncthreads();

  float sum = 0.f;
  for(int d=tid; d<TS; d+=256){ float e=__expf(r[d]-mx); r[d]=e; sum+=e; }
  sum = warp_sum(sum);
  if(!lane) sh[wp]=sum;
  __syncthreads();
  if (tid<32){ float v=(tid<8)?sh[tid]:0.f; v=warp_sum(v); if(!tid) sh[0]=v; }
  __syncthreads();
  float inv = 1.f/sh[0];
  for(int d=tid; d<TS; d+=256) r[d]*=inv;
}

// ---------------- elementwise ----------------
__global__ void add_kernel(const float* __restrict__ a, const float* __restrict__ b,
                           float* __restrict__ c, int n){
  int i = blockIdx.x*blockDim.x + threadIdx.x;
  if (i<n) c[i]=a[i]+b[i];
}
__global__ void zero_kernel(float* __restrict__ p, int n){
  int i = blockIdx.x*blockDim.x + threadIdx.x;
  if (i<n) p[i]=0.f;
}
__global__ void zero_cnt_kernel(){
  if (threadIdx.x < TE) g_ecnt[threadIdx.x]=0;
}
__global__ void silu_mul_kernel(const int* __restrict__ cntp){
  int n = (*cntp)*TF;
  int i = blockIdx.x*blockDim.x + threadIdx.x;
  if (i>=n) return;
  float g = g_G[i], u = g_U[i];
  g_G[i] = (g/(1.f+__expf(-g)))*u;
}

// ---------------- router: logits + softmax + top2 + assignment ----------------
__global__ void router_kernel(const float* __restrict__ x, const float* __restrict__ wr){
  int t = blockIdx.x;
  int tid = threadIdx.x;           // 128 threads
  const float* xr = x + (size_t)t*TD;
  float acc[TE];
  #pragma unroll
  for(int e=0;e<TE;e++) acc[e]=0.f;
  for(int d=tid; d<TD; d+=128){
    float xv = xr[d];
    #pragma unroll
    for(int e=0;e<TE;e++) acc[e] += xv*wr[e*TD+d];
  }
  __shared__ float sh[TE][4];
  int lane=tid&31, wp=tid>>5;
  #pragma unroll
  for(int e=0;e<TE;e++){
    float v = warp_sum(acc[e]);
    if(!lane) sh[e][wp]=v;
  }
  __syncthreads();
  if (tid==0){
    float lg[TE];
    float mx=-1e30f;
    #pragma unroll
    for(int e=0;e<TE;e++){ lg[e]=sh[e][0]+sh[e][1]+sh[e][2]+sh[e][3]; mx=fmaxf(mx,lg[e]); }
    float p[TE]; float s=0.f;
    #pragma unroll
    for(int e=0;e<TE;e++){ p[e]=expf(lg[e]-mx); s+=p[e]; }
    float inv=1.f/s;
    #pragma unroll
    for(int e=0;e<TE;e++) p[e]*=inv;
    int e0=0;
    #pragma unroll
    for(int e=1;e<TE;e++) if (p[e]>p[e0]) e0=e;
    int e1=-1;
    #pragma unroll
    for(int e=0;e<TE;e++){ if(e==e0) continue; if (e1<0 || p[e]>p[e1]) e1=e; }
    float w0=p[e0], w1=p[e1];
    float tot = w0+w1;
    w0/=tot; w1/=tot;
    int pos = atomicAdd(&g_ecnt[e0],1);
    g_elist[e0*TT+pos]=t; g_ew[e0*TT+pos]=w0;
    pos = atomicAdd(&g_ecnt[e1],1);
    g_elist[e1*TT+pos]=t; g_ew[e1*TT+pos]=w1;
  }
}

// ---------------- launcher ----------------
extern "C" void kernel_launch(void* const* d_in, const int* in_sizes, int n_in,
                              void* d_out, int out_size){
  const float* hidden  = (const float*)d_in[0];
  const float* cosb    = (const float*)d_in[1];
  const float* sinb    = (const float*)d_in[2];
  const float* ln1w    = (const float*)d_in[3];
  const float* ln2w    = (const float*)d_in[4];
  const float* wqkv    = (const float*)d_in[5];
  const float* wout    = (const float*)d_in[6];
  const float* wrouter = (const float*)d_in[7];
  const float* wgate   = (const float*)d_in[8];
  const float* wup     = (const float*)d_in[9];
  const float* wdown   = (const float*)d_in[10];
  float* out = (float*)d_out;

  float *p_h,*p_qkv,*p_scores,*p_attn,*p_res,*p_G,*p_U,*p_ew;
  int *p_elist,*p_ecnt;
  cudaGetSymbolAddress((void**)&p_h, g_h);
  cudaGetSymbolAddress((void**)&p_qkv, g_qkv);
  cudaGetSymbolAddress((void**)&p_scores, g_scores);
  cudaGetSymbolAddress((void**)&p_attn, g_attn);
  cudaGetSymbolAddress((void**)&p_res, g_res);
  cudaGetSymbolAddress((void**)&p_G, g_G);
  cudaGetSymbolAddress((void**)&p_U, g_U);
  cudaGetSymbolAddress((void**)&p_ew, g_ew);
  cudaGetSymbolAddress((void**)&p_elist, g_elist);
  cudaGetSymbolAddress((void**)&p_ecnt, g_ecnt);

  const int n_td = TT*TD;
  float* resid = (out_size >= 2*n_td) ? (out + (size_t)n_td) : p_res;

  // 1. LN1
  ln_kernel<<<TT,256>>>(hidden, ln1w, p_h);

  // 2. QKV = h @ w_qkv^T   (TN)
  sgemm<true,0,0,false><<<dim3(OQKV/128, TT/128, 1),256>>>(
      TT, OQKV, TD, p_h, TD, wqkv, TD, p_qkv, OQKV, 1.f, nullptr, nullptr, nullptr);

  // 3. RoPE
  {
    int total = TT*(TH+TKV)*(THD/2);
    rope_kernel<<<(total+255)/256,256>>>(p_qkv, cosb, sinb);
  }

  // 4. scores = Q @ K^T / sqrt(HD), causal mask  (TN, batched over b*H+h)
  sgemm<true,1,1,false><<<dim3(TS/128, TS/128, TB*TH),256>>>(
      TS, TS, THD, p_qkv, OQKV, p_qkv, OQKV, p_scores, TS,
      1.f/sqrtf((float)THD), nullptr, nullptr, nullptr);

  // 5. softmax
  softmax_kernel<<<TB*TH*TS,256>>>(p_scores);

  // 6. attn = P @ V   (NN, batched)
  sgemm<false,0,2,false><<<dim3(THD/128, TS/128, TB*TH),256>>>(
      TS, THD, TS, p_scores, TS, p_qkv, OQKV, p_attn, TH*THD,
      1.f, nullptr, nullptr, nullptr);

  // 7. proj = attn @ w_out^T  (TN) -> reuse g_qkv
  sgemm<true,0,0,false><<<dim3(TD/128, TT/128, 1),256>>>(
      TT, TD, TH*THD, p_attn, TH*THD, wout, TH*THD, p_qkv, TD,
      1.f, nullptr, nullptr, nullptr);

  // 8. residual = proj + hidden
  add_kernel<<<(n_td+255)/256,256>>>(p_qkv, hidden, resid, n_td);

  // 9. LN2 -> x
  ln_kernel<<<TT,256>>>(resid, ln2w, p_h);

  // 10. zero out + counts, then router
  zero_kernel<<<(n_td+255)/256,256>>>(out, n_td);
  zero_cnt_kernel<<<1,32>>>();
  router_kernel<<<TT,128>>>(p_h, wrouter);

  // 11. MoE experts
  for (int e=0; e<TE; e++){
    const int* lst = p_elist + e*TT;
    const float* wts = p_ew + e*TT;
    const int* cnt = p_ecnt + e;
    // G = gather(x) @ w_gate[e]   (NN)
    sgemm<false,0,0,true><<<dim3(TF/128, TT/128, 1),256>>>(
        TT, TF, TD, p_h, TD, wgate + (size_t)e*TD*TF, TF, p_G, TF,
        1.f, lst, nullptr, cnt);
    // U = gather(x) @ w_up[e]
    sgemm<false,0,0,true><<<dim3(TF/128, TT/128, 1),256>>>(
        TT, TF, TD, p_h, TD, wup + (size_t)e*TD*TF, TF, p_U, TF,
        1.f, lst, nullptr, cnt);
    // G = silu(G)*U
    silu_mul_kernel<<<(TT*TF+255)/256,256>>>(cnt);
    // out[token] += w * (G @ w_down[e])   (NN, scatter epilogue)
    sgemm<false,2,0,false><<<dim3(TD/128, TT/128, 1),256>>>(
        TT, TD, TF, p_G, TF, wdown + (size_t)e*TF*TD, TD, out, TD,
        1.f, lst, wts, cnt);
  }

  // ensure residual also lands in d_out second half if we used scratch path
  if (resid == p_res && out_size >= 2*n_td){
    add_kernel<<<(n_td+255)/256,256>>>(p_qkv, hidden, out + (size_t)n_td, n_td);
  }
}

// round 3
// speedup vs baseline: 1.7234x; 1.7234x over previous
#include <cuda_runtime.h>
#include <cuda_bf16.h>
#include <math.h>
#include <stdint.h>

// Problem constants
#define TS_ 1024
#define TBATCH 2
#define TD 2048
#define TH 16
#define TKV 4
#define THD 128
#define TE 8
#define TF 2048
#define TT (TBATCH*TS_)            // 2048 tokens
#define OQKV ((TH+2*TKV)*THD)      // 3072
#define REP (TH/TKV)               // 4

// ---------------- scratch (device globals) ----------
__device__ float g_h[(size_t)TT*TD];
__device__ float g_qkv[(size_t)TT*OQKV];
__device__ float g_scores[(size_t)TBATCH*TH*TS_*TS_];
__device__ float g_attn[(size_t)TT*TH*THD];
__device__ float g_res[(size_t)TT*TD];
__device__ float g_G[(size_t)TT*TF];
__device__ float g_U[(size_t)TT*TF];
__device__ int   g_elist[TE*TT];
__device__ float g_ew[TE*TT];
__device__ int   g_ecnt[TE];

// ---------------- PTX helpers (baseline ISA only — no 'a' features) --------
__device__ __forceinline__ uint32_t smem_u32(const void* p){
  uint32_t a;
  asm("{ .reg .u64 t; cvta.to.shared.u64 t, %1; cvt.u32.u64 %0, t; }" : "=r"(a) : "l"(p));
  return a;
}
__device__ __forceinline__ void ldsm_x4(uint32_t* r, uint32_t addr){
  asm volatile("ldmatrix.sync.aligned.m8n8.x4.shared.b16 {%0,%1,%2,%3}, [%4];"
    : "=r"(r[0]),"=r"(r[1]),"=r"(r[2]),"=r"(r[3]) : "r"(addr));
}
__device__ __forceinline__ void ldsm_x2(uint32_t* r, uint32_t addr){
  asm volatile("ldmatrix.sync.aligned.m8n8.x2.shared.b16 {%0,%1}, [%2];"
    : "=r"(r[0]),"=r"(r[1]) : "r"(addr));
}
__device__ __forceinline__ void mma16816(float* c, const uint32_t* a, const uint32_t* b){
  asm volatile("mma.sync.aligned.m16n8k16.row.col.f32.bf16.bf16.f32 "
    "{%0,%1,%2,%3}, {%4,%5,%6,%7}, {%8,%9}, {%0,%1,%2,%3};"
    : "+f"(c[0]),"+f"(c[1]),"+f"(c[2]),"+f"(c[3])
    : "r"(a[0]),"r"(a[1]),"r"(a[2]),"r"(a[3]), "r"(b[0]),"r"(b[1]));
}
__device__ __forceinline__ uint32_t pack_hi(float x, float y){
  __nv_bfloat162 h = __floats2bfloat162_rn(x, y);
  return *reinterpret_cast<uint32_t*>(&h);
}

// ---------------- tensor-core GEMM (mma.sync bf16, 3-term split) -----------
// C[M,N] = alpha*A[M,K] @ (BT ? B[N,K]^T : B[K,N])
// EPI 0: store. EPI 2: C[arow[m]] += aw[m]*v.  GATHER: A row via arow[].
// Tile 128x128, BK=32, 8 warps (2 x 4), warp tile 64x32.
#define APAD 40   // row stride in bf16 elems (80 bytes) - conflict-lean for ldmatrix

template<bool BT, int EPI, bool GATHER>
__global__ __launch_bounds__(256) void tgemm(
    int M, int N, int K,
    const float* __restrict__ A, int lda,
    const float* __restrict__ B, int ldb,
    float* __restrict__ C, int ldc,
    float alpha,
    const int* __restrict__ arow,
    const float* __restrict__ aw,
    const int* __restrict__ cntp)
{
  __shared__ __align__(16) unsigned short sAh[128*APAD];
  __shared__ __align__(16) unsigned short sAl[128*APAD];
  __shared__ __align__(16) unsigned short sBh[128*APAD];
  __shared__ __align__(16) unsigned short sBl[128*APAD];

  int Meff = cntp ? *cntp : M;
  int row0 = blockIdx.y*128, col0 = blockIdx.x*128;
  if (row0 >= Meff) return;

  int tid = threadIdx.x;
  int wid = tid>>5, lane = tid&31;
  int wm = wid>>2, wn = wid&3;       // 2 x 4 warps

  uint32_t baseAh = smem_u32(sAh);
  uint32_t baseAl = smem_u32(sAl);
  uint32_t baseBh = smem_u32(sBh);
  uint32_t baseBl = smem_u32(sBl);

  // ldmatrix per-lane byte offsets
  uint32_t laneA = (uint32_t)((lane&15)*(APAD*2)) + (uint32_t)((lane>>4)*16);
  uint32_t laneB = (uint32_t)((lane&7)*(APAD*2)) + (uint32_t)(((lane>>3)&1)*16);

  float acc[4][4][4];
  #pragma unroll
  for(int i=0;i<4;i++)
    #pragma unroll
    for(int j=0;j<4;j++)
      #pragma unroll
      for(int q=0;q<4;q++) acc[i][j][q]=0.f;

  const int NC = K/32;
  float4 pa[4], pb[4];

  // ---- load helpers (into registers) ----
  auto loadA = [&](int c){
    int k0 = c*32;
    #pragma unroll
    for (int i=0;i<4;i++){
      int lin = tid + i*256;
      int r = lin>>3, c4 = lin&7;
      int gm = row0 + r;
      float4 v = make_float4(0.f,0.f,0.f,0.f);
      if (gm < Meff){
        long src = GATHER ? (long)arow[gm] : (long)gm;
        v = *reinterpret_cast<const float4*>(A + src*(long)lda + k0 + c4*4);
      }
      pa[i]=v;
    }
  };
  auto loadB = [&](int c){
    int k0 = c*32;
    if (BT){
      #pragma unroll
      for (int i=0;i<4;i++){
        int lin = tid + i*256;
        int r = lin>>3, c4 = lin&7;
        pb[i] = *reinterpret_cast<const float4*>(B + (long)(col0+r)*ldb + k0 + c4*4);
      }
    } else {
      #pragma unroll
      for (int i=0;i<4;i++){
        int lin = tid + i*256;
        int kk = lin>>5, c4n = lin&31;
        pb[i] = *reinterpret_cast<const float4*>(B + (long)(k0+kk)*ldb + col0 + c4n*4);
      }
    }
  };
  auto storeA = [&](){
    #pragma unroll
    for (int i=0;i<4;i++){
      int lin = tid + i*256;
      int r = lin>>3, c4 = lin&7;
      float4 v = pa[i];
      float hx=__bfloat162float(__float2bfloat16(v.x));
      float hy=__bfloat162float(__float2bfloat16(v.y));
      float hz=__bfloat162float(__float2bfloat16(v.z));
      float hw=__bfloat162float(__float2bfloat16(v.w));
      uint32_t h01 = pack_hi(v.x, v.y), h23 = pack_hi(v.z, v.w);
      uint32_t l01 = pack_hi(v.x-hx, v.y-hy), l23 = pack_hi(v.z-hz, v.w-hw);
      int off = r*APAD + c4*4;
      *reinterpret_cast<uint2*>(&sAh[off]) = make_uint2(h01,h23);
      *reinterpret_cast<uint2*>(&sAl[off]) = make_uint2(l01,l23);
    }
  };
  auto storeB = [&](){
    if (BT){
      #pragma unroll
      for (int i=0;i<4;i++){
        int lin = tid + i*256;
        int r = lin>>3, c4 = lin&7;
        float4 v = pb[i];
        float hx=__bfloat162float(__float2bfloat16(v.x));
        float hy=__bfloat162float(__float2bfloat16(v.y));
        float hz=__bfloat162float(__float2bfloat16(v.z));
        float hw=__bfloat162float(__float2bfloat16(v.w));
        uint32_t h01 = pack_hi(v.x, v.y), h23 = pack_hi(v.z, v.w);
        uint32_t l01 = pack_hi(v.x-hx, v.y-hy), l23 = pack_hi(v.z-hz, v.w-hw);
        int off = r*APAD + c4*4;
        *reinterpret_cast<uint2*>(&sBh[off]) = make_uint2(h01,h23);
        *reinterpret_cast<uint2*>(&sBl[off]) = make_uint2(l01,l23);
      }
    } else {
      #pragma unroll
      for (int i=0;i<4;i++){
        int lin = tid + i*256;
        int kk = lin>>5, c4n = lin&31;
        float4 v = pb[i];
        float xs[4]={v.x,v.y,v.z,v.w};
        #pragma unroll
        for (int j=0;j<4;j++){
          float x = xs[j];
          __nv_bfloat16 h = __float2bfloat16(x);
          __nv_bfloat16 l = __float2bfloat16(x - __bfloat162float(h));
          int off = (c4n*4+j)*APAD + kk;
          sBh[off] = *reinterpret_cast<unsigned short*>(&h);
          sBl[off] = *reinterpret_cast<unsigned short*>(&l);
        }
      }
    }
  };

  loadA(0); loadB(0);

  for (int c = 0; c < NC; c++){
    storeA(); storeB();
    __syncthreads();
    if (c+1 < NC){ loadA(c+1); loadB(c+1); }

    #pragma unroll
    for (int ks = 0; ks < 2; ks++){
      uint32_t aH[4][4], bH[4][2];
      uint32_t rowbaseA = (uint32_t)((wm*64)*(APAD*2)) + (uint32_t)(ks*32) + laneA;
      uint32_t rowbaseB = (uint32_t)((wn*32)*(APAD*2)) + (uint32_t)(ks*32) + laneB;
      #pragma unroll
      for (int mf=0; mf<4; mf++) ldsm_x4(aH[mf], baseAh + rowbaseA + mf*16*(APAD*2));
      #pragma unroll
      for (int nf=0; nf<4; nf++) ldsm_x2(bH[nf], baseBh + rowbaseB + nf*8*(APAD*2));
      #pragma unroll
      for (int mf=0; mf<4; mf++)
        #pragma unroll
        for (int nf=0; nf<4; nf++) mma16816(acc[mf][nf], aH[mf], bH[nf]);
      {
        uint32_t aL[4][4];
        #pragma unroll
        for (int mf=0; mf<4; mf++) ldsm_x4(aL[mf], baseAl + rowbaseA + mf*16*(APAD*2));
        #pragma unroll
        for (int mf=0; mf<4; mf++)
          #pragma unroll
          for (int nf=0; nf<4; nf++) mma16816(acc[mf][nf], aL[mf], bH[nf]);
      }
      {
        uint32_t bL[4][2];
        #pragma unroll
        for (int nf=0; nf<4; nf++) ldsm_x2(bL[nf], baseBl + rowbaseB + nf*8*(APAD*2));
        #pragma unroll
        for (int mf=0; mf<4; mf++)
          #pragma unroll
          for (int nf=0; nf<4; nf++) mma16816(acc[mf][nf], aH[mf], bL[nf]);
      }
    }
    __syncthreads();
  }

  // ---- epilogue ----
  int g = lane>>2, tig = lane&3;
  #pragma unroll
  for (int mf=0; mf<4; mf++){
    int ra = row0 + wm*64 + mf*16 + g;
    int rb = ra + 8;
    #pragma unroll
    for (int nf=0; nf<4; nf++){
      int col = col0 + wn*32 + nf*8 + tig*2;
      float* cacc = acc[mf][nf];
      if (EPI == 0){
        if (ra < Meff){
          float* p = C + (size_t)ra*ldc + col;
          p[0] = cacc[0]*alpha; p[1] = cacc[1]*alpha;
        }
        if (rb < Meff){
          float* p = C + (size_t)rb*ldc + col;
          p[0] = cacc[2]*alpha; p[1] = cacc[3]*alpha;
        }
      } else {
        if (ra < Meff){
          float w = aw[ra];
          float* p = C + (size_t)arow[ra]*ldc + col;
          p[0] += w*cacc[0]*alpha; p[1] += w*cacc[1]*alpha;
        }
        if (rb < Meff){
          float w = aw[rb];
          float* p = C + (size_t)arow[rb]*ldc + col;
          p[0] += w*cacc[2]*alpha; p[1] += w*cacc[3]*alpha;
        }
      }
    }
  }
}

// ---------------- reduction helpers ----------------
__device__ __forceinline__ float warp_sum(float v){
  #pragma unroll
  for(int o=16;o;o>>=1) v += __shfl_xor_sync(0xffffffffu, v, o);
  return v;
}
__device__ __forceinline__ float warp_max(float v){
  #pragma unroll
  for(int o=16;o;o>>=1) v = fmaxf(v, __shfl_xor_sync(0xffffffffu, v, o));
  return v;
}

// ---------------- LayerNorm ----------------
__global__ void ln_kernel(const float* __restrict__ x, const float* __restrict__ w,
                          float* __restrict__ y){
  int row = blockIdx.x;
  const float* xr = x + (size_t)row*TD;
  float* yr = y + (size_t)row*TD;
  float s=0.f, s2=0.f;
  for(int d=threadIdx.x; d<TD; d+=blockDim.x){ float v=xr[d]; s+=v; s2+=v*v; }
  __shared__ float shs[8], shs2[8];
  int lane=threadIdx.x&31, wp=threadIdx.x>>5;
  s = warp_sum(s); s2 = warp_sum(s2);
  if(!lane){ shs[wp]=s; shs2[wp]=s2; }
  __syncthreads();
  if (threadIdx.x < 32){
    float a = (threadIdx.x<8)? shs[threadIdx.x] : 0.f;
    float b = (threadIdx.x<8)? shs2[threadIdx.x] : 0.f;
    a = warp_sum(a); b = warp_sum(b);
    if(!threadIdx.x){ shs[0]=a; shs2[0]=b; }
  }
  __syncthreads();
  float mu = shs[0]*(1.f/TD);
  float var = shs2[0]*(1.f/TD) - mu*mu;
  float rstd = rsqrtf(var + 1e-5f);
  for(int d=threadIdx.x; d<TD; d+=blockDim.x)
    yr[d] = (xr[d]-mu)*rstd*w[d];
}

// ---------------- RoPE ----------------
__global__ void rope_kernel(float* __restrict__ qkv,
                            const float* __restrict__ cosb,
                            const float* __restrict__ sinb){
  int idx = blockIdx.x*blockDim.x + threadIdx.x;
  const int total = TT*(TH+TKV)*(THD/2);
  if (idx >= total) return;
  int i  = idx & 63;
  int rest = idx >> 6;
  int hh = rest % (TH+TKV);
  int t  = rest / (TH+TKV);
  int s  = t % TS_;
  float c  = cosb[s*THD + i];
  float sn = sinb[s*THD + i];
  float* p = qkv + (size_t)t*OQKV + hh*THD;
  float x1 = p[i], x2 = p[i+64];
  p[i]    = x1*c - x2*sn;
  p[i+64] = x2*c + x1*sn;
}

// ---------------- fp32 SGEMM (attention only) ----------------
// ADDR 1: scores (TN, causal mask, skip fully-masked tiles)
// ADDR 2: PV (NN, K loop truncated at row0+BM)
template<bool BT, int EPI, int ADDR>
__global__ __launch_bounds__(256) void sgemm(
    int M, int N, int Kk,
    const float* __restrict__ A, int lda,
    const float* __restrict__ B, int ldb,
    float* __restrict__ C, int ldc,
    float alpha)
{
  constexpr int BM=128, BN=128, BK=8, TM=8, TN=8;
  if (ADDR==1){
    int b = blockIdx.z/TH, h = blockIdx.z%TH;
    A += (size_t)b*TS_*OQKV + h*THD;
    B += (size_t)b*TS_*OQKV + (TH + h/REP)*THD;
    C += (size_t)blockIdx.z*TS_*TS_;
  } else if (ADDR==2){
    int b = blockIdx.z/TH, h = blockIdx.z%TH;
    A += (size_t)blockIdx.z*TS_*TS_;
    B += (size_t)b*TS_*OQKV + (TH+TKV + h/REP)*THD;
    C += (size_t)b*TS_*(TH*THD) + h*THD;
  }
  int row0 = blockIdx.y*BM, col0 = blockIdx.x*BN;
  int tid = threadIdx.x;
  int tr = tid>>4, tc = tid&15;

  if (ADDR==1 && col0 > row0 + BM - 1){
    #pragma unroll
    for(int i=0;i<TM;i++){
      int gm = row0 + tr*TM + i;
      #pragma unroll
      for(int j=0;j<TN;j++) C[(size_t)gm*ldc + col0 + tc*TN + j] = -1e9f;
    }
    return;
  }

  int Klim = (ADDR==2) ? min(Kk, row0+BM) : Kk;

  __shared__ float As[BK*BM];
  __shared__ float Bs[BK*BN];
  int aRow = tid>>1;
  int aCol = (tid&1)*4;

  float acc[TM][TN];
  #pragma unroll
  for(int i=0;i<TM;i++)
    #pragma unroll
    for(int j=0;j<TN;j++) acc[i][j]=0.f;

  for(int k0=0;k0<Klim;k0+=BK){
    {
      float4 v = *reinterpret_cast<const float4*>(A + (size_t)(row0+aRow)*lda + k0 + aCol);
      As[(aCol+0)*BM+aRow]=v.x;
      As[(aCol+1)*BM+aRow]=v.y;
      As[(aCol+2)*BM+aRow]=v.z;
      As[(aCol+3)*BM+aRow]=v.w;
    }
    if (BT){
      float4 v = *reinterpret_cast<const float4*>(B + (size_t)(col0+aRow)*ldb + k0 + aCol);
      Bs[(aCol+0)*BN+aRow]=v.x;
      Bs[(aCol+1)*BN+aRow]=v.y;
      Bs[(aCol+2)*BN+aRow]=v.z;
      Bs[(aCol+3)*BN+aRow]=v.w;
    } else {
      int bRow = tid>>5;
      int bCol = (tid&31)*4;
      float4 v = *reinterpret_cast<const float4*>(B + (size_t)(k0+bRow)*ldb + col0 + bCol);
      *reinterpret_cast<float4*>(&Bs[bRow*BN + bCol]) = v;
    }
    __syncthreads();

    #pragma unroll
    for(int k=0;k<BK;k++){
      float4 m0 = *reinterpret_cast<const float4*>(&As[k*BM + tr*TM]);
      float4 m1 = *reinterpret_cast<const float4*>(&As[k*BM + tr*TM + 4]);
      float4 n0 = *reinterpret_cast<const float4*>(&Bs[k*BN + tc*TN]);
      float4 n1 = *reinterpret_cast<const float4*>(&Bs[k*BN + tc*TN + 4]);
      float rM[8]={m0.x,m0.y,m0.z,m0.w,m1.x,m1.y,m1.z,m1.w};
      float rN[8]={n0.x,n0.y,n0.z,n0.w,n1.x,n1.y,n1.z,n1.w};
      #pragma unroll
      for(int i=0;i<TM;i++)
        #pragma unroll
        for(int j=0;j<TN;j++)
          acc[i][j] += rM[i]*rN[j];
    }
    __syncthreads();
  }

  #pragma unroll
  for(int i=0;i<TM;i++){
    int gm = row0 + tr*TM + i;
    #pragma unroll
    for(int j=0;j<TN;j++){
      int gn = col0 + tc*TN + j;
      float v = acc[i][j]*alpha;
      if (EPI==1) C[(size_t)gm*ldc+gn] = (gn<=gm) ? v : -1e9f;
      else        C[(size_t)gm*ldc+gn] = v;
    }
  }
}

// ---------------- softmax ----------------
__global__ void softmax_kernel(float* __restrict__ s){
  float* r = s + (size_t)blockIdx.x*TS_;
  int tid = threadIdx.x;
  int lane = tid&31, wp = tid>>5;
  __shared__ float sh[8];

  float mx = -1e30f;
  for(int d=tid; d<TS_; d+=256) mx = fmaxf(mx, r[d]);
  mx = warp_max(mx);
  if(!lane) sh[wp]=mx;
  __syncthreads();
  if (tid<32){ float v=(tid<8)?sh[tid]:-1e30f; v=warp_max(v); if(!tid) sh[0]=v; }
  __syncthreads();
  mx = sh[0];
  __syncthreads();

  float sum = 0.f;
  for(int d=tid; d<TS_; d+=256){ float e=__expf(r[d]-mx); r[d]=e; sum+=e; }
  sum = warp_sum(sum);
  if(!lane) sh[wp]=sum;
  __syncthreads();
  if (tid<32){ float v=(tid<8)?sh[tid]:0.f; v=warp_sum(v); if(!tid) sh[0]=v; }
  __syncthreads();
  float inv = 1.f/sh[0];
  for(int d=tid; d<TS_; d+=256) r[d]*=inv;
}

// ---------------- elementwise ----------------
__global__ void add_kernel(const float* __restrict__ a, const float* __restrict__ b,
                           float* __restrict__ c, int n){
  int i = blockIdx.x*blockDim.x + threadIdx.x;
  if (i<n) c[i]=a[i]+b[i];
}
__global__ void zero_kernel(float* __restrict__ p, int n){
  int i = blockIdx.x*blockDim.x + threadIdx.x;
  if (i<n) p[i]=0.f;
}
__global__ void zero_cnt_kernel(){
  if (threadIdx.x < TE) g_ecnt[threadIdx.x]=0;
}
__global__ void silu_mul_kernel(const int* __restrict__ cntp){
  int n = (*cntp)*TF;
  int i = blockIdx.x*blockDim.x + threadIdx.x;
  if (i>=n) return;
  float g = g_G[i], u = g_U[i];
  g_G[i] = (g/(1.f+__expf(-g)))*u;
}

// ---------------- router ----------------
__global__ void router_kernel(const float* __restrict__ x, const float* __restrict__ wr){
  int t = blockIdx.x;
  int tid = threadIdx.x;
  const float* xr = x + (size_t)t*TD;
  float acc[TE];
  #pragma unroll
  for(int e=0;e<TE;e++) acc[e]=0.f;
  for(int d=tid; d<TD; d+=128){
    float xv = xr[d];
    #pragma unroll
    for(int e=0;e<TE;e++) acc[e] += xv*wr[e*TD+d];
  }
  __shared__ float sh[TE][4];
  int lane=tid&31, wp=tid>>5;
  #pragma unroll
  for(int e=0;e<TE;e++){
    float v = warp_sum(acc[e]);
    if(!lane) sh[e][wp]=v;
  }
  __syncthreads();
  if (tid==0){
    float lg[TE];
    float mx=-1e30f;
    #pragma unroll
    for(int e=0;e<TE;e++){ lg[e]=sh[e][0]+sh[e][1]+sh[e][2]+sh[e][3]; mx=fmaxf(mx,lg[e]); }
    float p[TE]; float s=0.f;
    #pragma unroll
    for(int e=0;e<TE;e++){ p[e]=expf(lg[e]-mx); s+=p[e]; }
    float inv=1.f/s;
    #pragma unroll
    for(int e=0;e<TE;e++) p[e]*=inv;
    int e0=0;
    #pragma unroll
    for(int e=1;e<TE;e++) if (p[e]>p[e0]) e0=e;
    int e1=-1;
    #pragma unroll
    for(int e=0;e<TE;e++){ if(e==e0) continue; if (e1<0 || p[e]>p[e1]) e1=e; }
    float w0=p[e0], w1=p[e1];
    float tot = w0+w1;
    w0/=tot; w1/=tot;
    int pos = atomicAdd(&g_ecnt[e0],1);
    g_elist[e0*TT+pos]=t; g_ew[e0*TT+pos]=w0;
    pos = atomicAdd(&g_ecnt[e1],1);
    g_elist[e1*TT+pos]=t; g_ew[e1*TT+pos]=w1;
  }
}

// ---------------- launcher ----------------
extern "C" void kernel_launch(void* const* d_in, const int* in_sizes, int n_in,
                              void* d_out, int out_size){
  const float* hidden  = (const float*)d_in[0];
  const float* cosb    = (const float*)d_in[1];
  const float* sinb    = (const float*)d_in[2];
  const float* ln1w    = (const float*)d_in[3];
  const float* ln2w    = (const float*)d_in[4];
  const float* wqkv    = (const float*)d_in[5];
  const float* wout    = (const float*)d_in[6];
  const float* wrouter = (const float*)d_in[7];
  const float* wgate   = (const float*)d_in[8];
  const float* wup     = (const float*)d_in[9];
  const float* wdown   = (const float*)d_in[10];
  float* out = (float*)d_out;

  float *p_h,*p_qkv,*p_scores,*p_attn,*p_res,*p_G,*p_U,*p_ew;
  int *p_elist,*p_ecnt;
  cudaGetSymbolAddress((void**)&p_h, g_h);
  cudaGetSymbolAddress((void**)&p_qkv, g_qkv);
  cudaGetSymbolAddress((void**)&p_scores, g_scores);
  cudaGetSymbolAddress((void**)&p_attn, g_attn);
  cudaGetSymbolAddress((void**)&p_res, g_res);
  cudaGetSymbolAddress((void**)&p_G, g_G);
  cudaGetSymbolAddress((void**)&p_U, g_U);
  cudaGetSymbolAddress((void**)&p_ew, g_ew);
  cudaGetSymbolAddress((void**)&p_elist, g_elist);
  cudaGetSymbolAddress((void**)&p_ecnt, g_ecnt);

  const int n_td = TT*TD;
  float* resid = (out_size >= 2*n_td) ? (out + (size_t)n_td) : p_res;

  // 1. LN1
  ln_kernel<<<TT,256>>>(hidden, ln1w, p_h);

  // 2. QKV = h @ w_qkv^T (tensor mma.sync)
  tgemm<true,0,false><<<dim3(OQKV/128, TT/128), 256>>>(
      TT, OQKV, TD, p_h, TD, wqkv, TD, p_qkv, OQKV, 1.f, nullptr, nullptr, nullptr);

  // 3. RoPE
  {
    int total = TT*(TH+TKV)*(THD/2);
    rope_kernel<<<(total+255)/256,256>>>(p_qkv, cosb, sinb);
  }

  // 4. scores (fp32, causal-skip)
  sgemm<true,1,1><<<dim3(TS_/128, TS_/128, TBATCH*TH),256>>>(
      TS_, TS_, THD, p_qkv, OQKV, p_qkv, OQKV, p_scores, TS_, 1.f/sqrtf((float)THD));

  // 5. softmax
  softmax_kernel<<<TBATCH*TH*TS_,256>>>(p_scores);

  // 6. attn = P @ V (fp32, K-truncated)
  sgemm<false,0,2><<<dim3(THD/128, TS_/128, TBATCH*TH),256>>>(
      TS_, THD, TS_, p_scores, TS_, p_qkv, OQKV, p_attn, TH*THD, 1.f);

  // 7. proj = attn @ w_out^T (tensor) -> reuse g_qkv
  tgemm<true,0,false><<<dim3(TD/128, TT/128), 256>>>(
      TT, TD, TH*THD, p_attn, TH*THD, wout, TH*THD, p_qkv, TD, 1.f, nullptr, nullptr, nullptr);

  // 8. residual
  add_kernel<<<(n_td+255)/256,256>>>(p_qkv, hidden, resid, n_td);

  // 9. LN2
  ln_kernel<<<TT,256>>>(resid, ln2w, p_h);

  // 10. zero + router
  zero_kernel<<<(n_td+255)/256,256>>>(out, n_td);
  zero_cnt_kernel<<<1,32>>>();
  router_kernel<<<TT,128>>>(p_h, wrouter);

  // 11. MoE experts (tensor)
  for (int e=0; e<TE; e++){
    const int* lst = p_elist + e*TT;
    const float* wts = p_ew + e*TT;
    const int* cnt = p_ecnt + e;
    tgemm<false,0,true><<<dim3(TF/128, TT/128), 256>>>(
        TT, TF, TD, p_h, TD, wgate + (size_t)e*TD*TF, TF, p_G, TF,
        1.f, lst, nullptr, cnt);
    tgemm<false,0,true><<<dim3(TF/128, TT/128), 256>>>(
        TT, TF, TD, p_h, TD, wup + (size_t)e*TD*TF, TF, p_U, TF,
        1.f, lst, nullptr, cnt);
    silu_mul_kernel<<<(TT*TF+255)/256,256>>>(cnt);
    tgemm<false,2,false><<<dim3(TD/128, TT/128), 256>>>(
        TT, TD, TF, p_G, TF, wdown + (size_t)e*TF*TD, TD, out, TD,
        1.f, lst, wts, cnt);
  }

  if (resid == p_res && out_size >= 2*n_td){
    add_kernel<<<(n_td+255)/256,256>>>(p_qkv, hidden, out + (size_t)n_td, n_td);
  }
}

// round 4
// speedup vs baseline: 3.0215x; 1.7532x over previous
#include <cuda_runtime.h>
#include <cuda_bf16.h>
#include <math.h>
#include <stdint.h>

// Problem constants
#define TS_ 1024
#define TBATCH 2
#define TD 2048
#define TH 16
#define TKV 4
#define THD 128
#define TE 8
#define TF 2048
#define TT (TBATCH*TS_)            // 2048 tokens
#define OQKV ((TH+2*TKV)*THD)      // 3072
#define REP (TH/TKV)               // 4

typedef unsigned short u16;

// ---------------- scratch (device globals) ----------
__device__ float g_h[(size_t)TT*TD];
__device__ float g_qkv[(size_t)TT*OQKV];
__device__ float g_scores[(size_t)TBATCH*TH*TS_*TS_];
__device__ float g_attn[(size_t)TT*TH*THD];
__device__ float g_res[(size_t)TT*TD];
__device__ float g_G[(size_t)TT*TF];
__device__ float g_U[(size_t)TT*TF];
__device__ int   g_elist[TE*TT];
__device__ float g_ew[TE*TT];
__device__ int   g_ecnt[TE];

// bf16 hi/lo split buffers
__device__ u16 g_wqkv_h[(size_t)OQKV*TD],  g_wqkv_l[(size_t)OQKV*TD];
__device__ u16 g_wout_h[(size_t)TD*TD],    g_wout_l[(size_t)TD*TD];
__device__ u16 g_wg_h[(size_t)TE*TF*TD],   g_wg_l[(size_t)TE*TF*TD];   // [e][F][D]
__device__ u16 g_wu_h[(size_t)TE*TF*TD],   g_wu_l[(size_t)TE*TF*TD];   // [e][F][D]
__device__ u16 g_wd_h[(size_t)TE*TD*TF],   g_wd_l[(size_t)TE*TD*TF];   // [e][D][F]
__device__ u16 g_xh[(size_t)TT*TD],        g_xl[(size_t)TT*TD];
__device__ u16 g_ah[(size_t)TT*TD],        g_al[(size_t)TT*TD];
__device__ u16 g_gh[(size_t)TT*TF],        g_gl[(size_t)TT*TF];

// ---------------- helpers ----------------
__device__ __forceinline__ u16 bfbits(float x){
  __nv_bfloat16 h = __float2bfloat16(x);
  return *reinterpret_cast<u16*>(&h);
}
__device__ __forceinline__ float bffloat(u16 b){
  __nv_bfloat16 h = *reinterpret_cast<__nv_bfloat16*>(&b);
  return __bfloat162float(h);
}
__device__ __forceinline__ uint32_t smem_u32(const void* p){
  uint32_t a;
  asm("{ .reg .u64 t; cvta.to.shared.u64 t, %1; cvt.u32.u64 %0, t; }" : "=r"(a) : "l"(p));
  return a;
}
__device__ __forceinline__ void ldsm_x4(uint32_t* r, uint32_t addr){
  asm volatile("ldmatrix.sync.aligned.m8n8.x4.shared.b16 {%0,%1,%2,%3}, [%4];"
    : "=r"(r[0]),"=r"(r[1]),"=r"(r[2]),"=r"(r[3]) : "r"(addr));
}
__device__ __forceinline__ void ldsm_x2(uint32_t* r, uint32_t addr){
  asm volatile("ldmatrix.sync.aligned.m8n8.x2.shared.b16 {%0,%1}, [%2];"
    : "=r"(r[0]),"=r"(r[1]) : "r"(addr));
}
__device__ __forceinline__ void mma16816(float* c, const uint32_t* a, const uint32_t* b){
  asm volatile("mma.sync.aligned.m16n8k16.row.col.f32.bf16.bf16.f32 "
    "{%0,%1,%2,%3}, {%4,%5,%6,%7}, {%8,%9}, {%0,%1,%2,%3};"
    : "+f"(c[0]),"+f"(c[1]),"+f"(c[2]),"+f"(c[3])
    : "r"(a[0]),"r"(a[1]),"r"(a[2]),"r"(a[3]), "r"(b[0]),"r"(b[1]));
}
__device__ __forceinline__ void cp16(uint32_t dst, const void* src, int ssz){
  asm volatile("cp.async.cg.shared.global [%0], [%1], 16, %2;"
    :: "r"(dst), "l"(src), "r"(ssz) : "memory");
}
__device__ __forceinline__ void cp16f(uint32_t dst, const void* src){
  asm volatile("cp.async.cg.shared.global [%0], [%1], 16;"
    :: "r"(dst), "l"(src) : "memory");
}
#define CP_COMMIT() asm volatile("cp.async.commit_group;":::"memory")
#define CP_WAIT(n)  asm volatile("cp.async.wait_group %0;"::"n"(n):"memory")

// ---------------- conversion kernels ----------------
__global__ void convsplit(const float* __restrict__ src, u16* __restrict__ h,
                          u16* __restrict__ l, int n4){
  int i = blockIdx.x*blockDim.x + threadIdx.x;
  if (i >= n4) return;
  float4 v = reinterpret_cast<const float4*>(src)[i];
  ushort4 hv, lv;
  hv.x=bfbits(v.x); hv.y=bfbits(v.y); hv.z=bfbits(v.z); hv.w=bfbits(v.w);
  lv.x=bfbits(v.x-bffloat(hv.x)); lv.y=bfbits(v.y-bffloat(hv.y));
  lv.z=bfbits(v.z-bffloat(hv.z)); lv.w=bfbits(v.w-bffloat(hv.w));
  reinterpret_cast<ushort4*>(h)[i]=hv;
  reinterpret_cast<ushort4*>(l)[i]=lv;
}

// transpose [R,C] -> [C,R], split hi/lo; batched over blockIdx.z
__global__ void transsplit(const float* __restrict__ src, u16* __restrict__ dh,
                           u16* __restrict__ dl, int R, int C){
  __shared__ float t[32][33];
  size_t off = (size_t)blockIdx.z * R * C;
  src += off; dh += off; dl += off;
  int c0 = blockIdx.x*32, r0 = blockIdx.y*32;
  int tx = threadIdx.x, ty = threadIdx.y;   // 32 x 8
  #pragma unroll
  for (int j=0;j<4;j++)
    t[ty+j*8][tx] = src[(size_t)(r0+ty+j*8)*C + c0+tx];
  __syncthreads();
  #pragma unroll
  for (int j=0;j<4;j++){
    float x = t[tx][ty+j*8];
    u16 h = bfbits(x);
    size_t o = (size_t)(c0+ty+j*8)*R + r0+tx;
    dh[o] = h;
    dl[o] = bfbits(x - bffloat(h));
  }
}

// ---------------- tensor-core GEMM (pure bf16 TN, cp.async pipelined) ------
// C[M,N] = alpha * A[M,K] @ B[N,K]^T   (A = Ah+Al, B = Bh+Bl; 3-term product)
// EPI 0: store. EPI 2: C[arow[m]] += aw[m]*v.  GATHER: A row via arow[].
// Tile 128x128x32, 8 warps (2x4), warp tile 64x32, double-buffered.
#define TPAD 80          // bytes per smem row (40 bf16)
#define MATB (128*TPAD)  // 10240 bytes per matrix tile
#define STAGEB (4*MATB)  // 40960 bytes per stage
#define TG_SMEM (2*STAGEB)

template<int EPI, bool GATHER>
__global__ __launch_bounds__(256,2) void tgemm(
    int M, int N, int K,
    const u16* __restrict__ Ah, const u16* __restrict__ Al, int lda,
    const u16* __restrict__ Bh, const u16* __restrict__ Bl, int ldb,
    float* __restrict__ C, int ldc, float alpha,
    const int* __restrict__ arow, const float* __restrict__ aw,
    const int* __restrict__ cntp)
{
  extern __shared__ __align__(16) char smem[];
  int Meff = cntp ? *cntp : M;
  int row0 = blockIdx.y*128, col0 = blockIdx.x*128;
  if (row0 >= Meff) return;

  int tid = threadIdx.x, wid = tid>>5, lane = tid&31;
  int wm = wid>>2, wn = wid&3;
  uint32_t sbase = smem_u32(smem);

  uint32_t laneA = (uint32_t)((lane&15)*TPAD) + (uint32_t)((lane>>4)*16);
  uint32_t laneB = (uint32_t)((lane&7)*TPAD)  + (uint32_t)(((lane>>3)&1)*16);

  float acc[4][4][4];
  #pragma unroll
  for(int i=0;i<4;i++)
    #pragma unroll
    for(int j=0;j<4;j++)
      #pragma unroll
      for(int q=0;q<4;q++) acc[i][j][q]=0.f;

  const int NC = K/32;

  auto issue = [&](int c){
    int s = c & 1;
    uint32_t dst0 = sbase + s*STAGEB;
    int k0 = c*32;
    #pragma unroll
    for (int it=0; it<2; it++){
      int q = tid + it*256;
      int r = q>>2, c16 = q&3;
      uint32_t doff = (uint32_t)(r*TPAD + c16*16);
      {
        int gm = row0 + r;
        int pred = gm < Meff;
        long src = 0;
        if (pred) src = GATHER ? (long)arow[gm] : (long)gm;
        long goff = src*(long)lda + k0 + c16*8;
        int ssz = pred ? 16 : 0;
        cp16(dst0 + doff,          Ah + goff, ssz);
        cp16(dst0 + MATB + doff,   Al + goff, ssz);
      }
      {
        long goff = (long)(col0+r)*ldb + k0 + c16*8;
        cp16f(dst0 + 2*MATB + doff, Bh + goff);
        cp16f(dst0 + 3*MATB + doff, Bl + goff);
      }
    }
    CP_COMMIT();
  };

  issue(0);
  for (int c = 0; c < NC; c++){
    if (c+1 < NC){ issue(c+1); CP_WAIT(1); }
    else         { CP_WAIT(0); }
    __syncthreads();

    uint32_t st = sbase + (c&1)*STAGEB;
    #pragma unroll
    for (int ks = 0; ks < 2; ks++){
      uint32_t rowA = st + (uint32_t)((wm*64)*TPAD + ks*32) + laneA;
      uint32_t rowB = st + 2*MATB + (uint32_t)((wn*32)*TPAD + ks*32) + laneB;
      uint32_t aH[4][4], bH[4][2];
      #pragma unroll
      for (int mf=0; mf<4; mf++) ldsm_x4(aH[mf], rowA + mf*16*TPAD);
      #pragma unroll
      for (int nf=0; nf<4; nf++) ldsm_x2(bH[nf], rowB + nf*8*TPAD);
      #pragma unroll
      for (int mf=0; mf<4; mf++)
        #pragma unroll
        for (int nf=0; nf<4; nf++) mma16816(acc[mf][nf], aH[mf], bH[nf]);
      {
        uint32_t aL[4][4];
        #pragma unroll
        for (int mf=0; mf<4; mf++) ldsm_x4(aL[mf], rowA + MATB + mf*16*TPAD);
        #pragma unroll
        for (int mf=0; mf<4; mf++)
          #pragma unroll
          for (int nf=0; nf<4; nf++) mma16816(acc[mf][nf], aL[mf], bH[nf]);
      }
      {
        uint32_t bL[4][2];
        #pragma unroll
        for (int nf=0; nf<4; nf++) ldsm_x2(bL[nf], rowB + MATB + nf*8*TPAD);
        #pragma unroll
        for (int mf=0; mf<4; mf++)
          #pragma unroll
          for (int nf=0; nf<4; nf++) mma16816(acc[mf][nf], aH[mf], bL[nf]);
      }
    }
    __syncthreads();
  }

  // ---- epilogue ----
  int g = lane>>2, tig = lane&3;
  #pragma unroll
  for (int mf=0; mf<4; mf++){
    int ra = row0 + wm*64 + mf*16 + g;
    int rb = ra + 8;
    #pragma unroll
    for (int nf=0; nf<4; nf++){
      int col = col0 + wn*32 + nf*8 + tig*2;
      float* cacc = acc[mf][nf];
      if (EPI == 0){
        if (ra < Meff){
          float* p = C + (size_t)ra*ldc + col;
          p[0] = cacc[0]*alpha; p[1] = cacc[1]*alpha;
        }
        if (rb < Meff){
          float* p = C + (size_t)rb*ldc + col;
          p[0] = cacc[2]*alpha; p[1] = cacc[3]*alpha;
        }
      } else {
        if (ra < Meff){
          float w = aw[ra];
          float* p = C + (size_t)arow[ra]*ldc + col;
          p[0] += w*cacc[0]*alpha; p[1] += w*cacc[1]*alpha;
        }
        if (rb < Meff){
          float w = aw[rb];
          float* p = C + (size_t)arow[rb]*ldc + col;
          p[0] += w*cacc[2]*alpha; p[1] += w*cacc[3]*alpha;
        }
      }
    }
  }
}

// ---------------- reduction helpers ----------------
__device__ __forceinline__ float warp_sum(float v){
  #pragma unroll
  for(int o=16;o;o>>=1) v += __shfl_xor_sync(0xffffffffu, v, o);
  return v;
}
__device__ __forceinline__ float warp_max(float v){
  #pragma unroll
  for(int o=16;o;o>>=1) v = fmaxf(v, __shfl_xor_sync(0xffffffffu, v, o));
  return v;
}

// ---------------- LayerNorm (fp32 out + bf16 hi/lo out) ----------------
__global__ void ln_kernel(const float* __restrict__ x, const float* __restrict__ w,
                          float* __restrict__ y, u16* __restrict__ yh, u16* __restrict__ yl){
  int row = blockIdx.x;
  const float* xr = x + (size_t)row*TD;
  float s=0.f, s2=0.f;
  for(int d=threadIdx.x; d<TD; d+=blockDim.x){ float v=xr[d]; s+=v; s2+=v*v; }
  __shared__ float shs[8], shs2[8];
  int lane=threadIdx.x&31, wp=threadIdx.x>>5;
  s = warp_sum(s); s2 = warp_sum(s2);
  if(!lane){ shs[wp]=s; shs2[wp]=s2; }
  __syncthreads();
  if (threadIdx.x < 32){
    float a = (threadIdx.x<8)? shs[threadIdx.x] : 0.f;
    float b = (threadIdx.x<8)? shs2[threadIdx.x] : 0.f;
    a = warp_sum(a); b = warp_sum(b);
    if(!threadIdx.x){ shs[0]=a; shs2[0]=b; }
  }
  __syncthreads();
  float mu = shs[0]*(1.f/TD);
  float var = shs2[0]*(1.f/TD) - mu*mu;
  float rstd = rsqrtf(var + 1e-5f);
  for(int d=threadIdx.x; d<TD; d+=blockDim.x){
    float v = (xr[d]-mu)*rstd*w[d];
    y[(size_t)row*TD + d] = v;
    u16 h = bfbits(v);
    yh[(size_t)row*TD + d] = h;
    yl[(size_t)row*TD + d] = bfbits(v - bffloat(h));
  }
}

// ---------------- RoPE ----------------
__global__ void rope_kernel(float* __restrict__ qkv,
                            const float* __restrict__ cosb,
                            const float* __restrict__ sinb){
  int idx = blockIdx.x*blockDim.x + threadIdx.x;
  const int total = TT*(TH+TKV)*(THD/2);
  if (idx >= total) return;
  int i  = idx & 63;
  int rest = idx >> 6;
  int hh = rest % (TH+TKV);
  int t  = rest / (TH+TKV);
  int s  = t % TS_;
  float c  = cosb[s*THD + i];
  float sn = sinb[s*THD + i];
  float* p = qkv + (size_t)t*OQKV + hh*THD;
  float x1 = p[i], x2 = p[i+64];
  p[i]    = x1*c - x2*sn;
  p[i+64] = x2*c + x1*sn;
}

// ---------------- fp32 SGEMM (attention only) ----------------
template<bool BT, int EPI, int ADDR>
__global__ __launch_bounds__(256) void sgemm(
    int M, int N, int Kk,
    const float* __restrict__ A, int lda,
    const float* __restrict__ B, int ldb,
    float* __restrict__ C, int ldc,
    float alpha)
{
  constexpr int BM=128, BN=128, BK=8, TM=8, TN=8;
  if (ADDR==1){
    int b = blockIdx.z/TH, h = blockIdx.z%TH;
    A += (size_t)b*TS_*OQKV + h*THD;
    B += (size_t)b*TS_*OQKV + (TH + h/REP)*THD;
    C += (size_t)blockIdx.z*TS_*TS_;
  } else if (ADDR==2){
    int b = blockIdx.z/TH, h = blockIdx.z%TH;
    A += (size_t)blockIdx.z*TS_*TS_;
    B += (size_t)b*TS_*OQKV + (TH+TKV + h/REP)*THD;
    C += (size_t)b*TS_*(TH*THD) + h*THD;
  }
  int row0 = blockIdx.y*BM, col0 = blockIdx.x*BN;
  int tid = threadIdx.x;
  int tr = tid>>4, tc = tid&15;

  if (ADDR==1 && col0 > row0 + BM - 1){
    #pragma unroll
    for(int i=0;i<TM;i++){
      int gm = row0 + tr*TM + i;
      #pragma unroll
      for(int j=0;j<TN;j++) C[(size_t)gm*ldc + col0 + tc*TN + j] = -1e9f;
    }
    return;
  }

  int Klim = (ADDR==2) ? min(Kk, row0+BM) : Kk;

  __shared__ float As[BK*BM];
  __shared__ float Bs[BK*BN];
  int aRow = tid>>1;
  int aCol = (tid&1)*4;

  float acc[TM][TN];
  #pragma unroll
  for(int i=0;i<TM;i++)
    #pragma unroll
    for(int j=0;j<TN;j++) acc[i][j]=0.f;

  for(int k0=0;k0<Klim;k0+=BK){
    {
      float4 v = *reinterpret_cast<const float4*>(A + (size_t)(row0+aRow)*lda + k0 + aCol);
      As[(aCol+0)*BM+aRow]=v.x;
      As[(aCol+1)*BM+aRow]=v.y;
      As[(aCol+2)*BM+aRow]=v.z;
      As[(aCol+3)*BM+aRow]=v.w;
    }
    if (BT){
      float4 v = *reinterpret_cast<const float4*>(B + (size_t)(col0+aRow)*ldb + k0 + aCol);
      Bs[(aCol+0)*BN+aRow]=v.x;
      Bs[(aCol+1)*BN+aRow]=v.y;
      Bs[(aCol+2)*BN+aRow]=v.z;
      Bs[(aCol+3)*BN+aRow]=v.w;
    } else {
      int bRow = tid>>5;
      int bCol = (tid&31)*4;
      float4 v = *reinterpret_cast<const float4*>(B + (size_t)(k0+bRow)*ldb + col0 + bCol);
      *reinterpret_cast<float4*>(&Bs[bRow*BN + bCol]) = v;
    }
    __syncthreads();

    #pragma unroll
    for(int k=0;k<BK;k++){
      float4 m0 = *reinterpret_cast<const float4*>(&As[k*BM + tr*TM]);
      float4 m1 = *reinterpret_cast<const float4*>(&As[k*BM + tr*TM + 4]);
      float4 n0 = *reinterpret_cast<const float4*>(&Bs[k*BN + tc*TN]);
      float4 n1 = *reinterpret_cast<const float4*>(&Bs[k*BN + tc*TN + 4]);
      float rM[8]={m0.x,m0.y,m0.z,m0.w,m1.x,m1.y,m1.z,m1.w};
      float rN[8]={n0.x,n0.y,n0.z,n0.w,n1.x,n1.y,n1.z,n1.w};
      #pragma unroll
      for(int i=0;i<TM;i++)
        #pragma unroll
        for(int j=0;j<TN;j++)
          acc[i][j] += rM[i]*rN[j];
    }
    __syncthreads();
  }

  #pragma unroll
  for(int i=0;i<TM;i++){
    int gm = row0 + tr*TM + i;
    #pragma unroll
    for(int j=0;j<TN;j++){
      int gn = col0 + tc*TN + j;
      float v = acc[i][j]*alpha;
      if (EPI==1) C[(size_t)gm*ldc+gn] = (gn<=gm) ? v : -1e9f;
      else        C[(size_t)gm*ldc+gn] = v;
    }
  }
}

// ---------------- softmax ----------------
__global__ void softmax_kernel(float* __restrict__ s){
  float* r = s + (size_t)blockIdx.x*TS_;
  int tid = threadIdx.x;
  int lane = tid&31, wp = tid>>5;
  __shared__ float sh[8];

  float mx = -1e30f;
  for(int d=tid; d<TS_; d+=256) mx = fmaxf(mx, r[d]);
  mx = warp_max(mx);
  if(!lane) sh[wp]=mx;
  __syncthreads();
  if (tid<32){ float v=(tid<8)?sh[tid]:-1e30f; v=warp_max(v); if(!tid) sh[0]=v; }
  __syncthreads();
  mx = sh[0];
  __syncthreads();

  float sum = 0.f;
  for(int d=tid; d<TS_; d+=256){ float e=__expf(r[d]-mx); r[d]=e; sum+=e; }
  sum = warp_sum(sum);
  if(!lane) sh[wp]=sum;
  __syncthreads();
  if (tid<32){ float v=(tid<8)?sh[tid]:0.f; v=warp_sum(v); if(!tid) sh[0]=v; }
  __syncthreads();
  float inv = 1.f/sh[0];
  for(int d=tid; d<TS_; d+=256) r[d]*=inv;
}

// ---------------- elementwise ----------------
__global__ void add_kernel(const float* __restrict__ a, const float* __restrict__ b,
                           float* __restrict__ c, int n){
  int i = blockIdx.x*blockDim.x + threadIdx.x;
  if (i<n) c[i]=a[i]+b[i];
}
__global__ void zero_kernel(float* __restrict__ p, int n){
  int i = blockIdx.x*blockDim.x + threadIdx.x;
  if (i<n) p[i]=0.f;
}
__global__ void zero_cnt_kernel(){
  if (threadIdx.x < TE) g_ecnt[threadIdx.x]=0;
}
__global__ void silu_mul_kernel(const int* __restrict__ cntp,
                                u16* __restrict__ gh, u16* __restrict__ gl){
  int n = (*cntp)*TF;
  int i = blockIdx.x*blockDim.x + threadIdx.x;
  if (i>=n) return;
  float g = g_G[i], u = g_U[i];
  float y = (g/(1.f+__expf(-g)))*u;
  u16 h = bfbits(y);
  gh[i] = h;
  gl[i] = bfbits(y - bffloat(h));
}

// ---------------- router ----------------
__global__ void router_kernel(const float* __restrict__ x, const float* __restrict__ wr){
  int t = blockIdx.x;
  int tid = threadIdx.x;
  const float* xr = x + (size_t)t*TD;
  float acc[TE];
  #pragma unroll
  for(int e=0;e<TE;e++) acc[e]=0.f;
  for(int d=tid; d<TD; d+=128){
    float xv = xr[d];
    #pragma unroll
    for(int e=0;e<TE;e++) acc[e] += xv*wr[e*TD+d];
  }
  __shared__ float sh[TE][4];
  int lane=tid&31, wp=tid>>5;
  #pragma unroll
  for(int e=0;e<TE;e++){
    float v = warp_sum(acc[e]);
    if(!lane) sh[e][wp]=v;
  }
  __syncthreads();
  if (tid==0){
    float lg[TE];
    float mx=-1e30f;
    #pragma unroll
    for(int e=0;e<TE;e++){ lg[e]=sh[e][0]+sh[e][1]+sh[e][2]+sh[e][3]; mx=fmaxf(mx,lg[e]); }
    float p[TE]; float s=0.f;
    #pragma unroll
    for(int e=0;e<TE;e++){ p[e]=expf(lg[e]-mx); s+=p[e]; }
    float inv=1.f/s;
    #pragma unroll
    for(int e=0;e<TE;e++) p[e]*=inv;
    int e0=0;
    #pragma unroll
    for(int e=1;e<TE;e++) if (p[e]>p[e0]) e0=e;
    int e1=-1;
    #pragma unroll
    for(int e=0;e<TE;e++){ if(e==e0) continue; if (e1<0 || p[e]>p[e1]) e1=e; }
    float w0=p[e0], w1=p[e1];
    float tot = w0+w1;
    w0/=tot; w1/=tot;
    int pos = atomicAdd(&g_ecnt[e0],1);
    g_elist[e0*TT+pos]=t; g_ew[e0*TT+pos]=w0;
    pos = atomicAdd(&g_ecnt[e1],1);
    g_elist[e1*TT+pos]=t; g_ew[e1*TT+pos]=w1;
  }
}

// ---------------- launcher ----------------
extern "C" void kernel_launch(void* const* d_in, const int* in_sizes, int n_in,
                              void* d_out, int out_size){
  const float* hidden  = (const float*)d_in[0];
  const float* cosb    = (const float*)d_in[1];
  const float* sinb    = (const float*)d_in[2];
  const float* ln1w    = (const float*)d_in[3];
  const float* ln2w    = (const float*)d_in[4];
  const float* wqkv    = (const float*)d_in[5];
  const float* wout    = (const float*)d_in[6];
  const float* wrouter = (const float*)d_in[7];
  const float* wgate   = (const float*)d_in[8];
  const float* wup     = (const float*)d_in[9];
  const float* wdown   = (const float*)d_in[10];
  float* out = (float*)d_out;

  float *p_h,*p_qkv,*p_scores,*p_attn,*p_res,*p_G,*p_U,*p_ew;
  int *p_elist,*p_ecnt;
  u16 *p_wqkv_h,*p_wqkv_l,*p_wout_h,*p_wout_l;
  u16 *p_wg_h,*p_wg_l,*p_wu_h,*p_wu_l,*p_wd_h,*p_wd_l;
  u16 *p_xh,*p_xl,*p_ah,*p_al,*p_gh,*p_gl;
  cudaGetSymbolAddress((void**)&p_h, g_h);
  cudaGetSymbolAddress((void**)&p_qkv, g_qkv);
  cudaGetSymbolAddress((void**)&p_scores, g_scores);
  cudaGetSymbolAddress((void**)&p_attn, g_attn);
  cudaGetSymbolAddress((void**)&p_res, g_res);
  cudaGetSymbolAddress((void**)&p_G, g_G);
  cudaGetSymbolAddress((void**)&p_U, g_U);
  cudaGetSymbolAddress((void**)&p_ew, g_ew);
  cudaGetSymbolAddress((void**)&p_elist, g_elist);
  cudaGetSymbolAddress((void**)&p_ecnt, g_ecnt);
  cudaGetSymbolAddress((void**)&p_wqkv_h, g_wqkv_h);
  cudaGetSymbolAddress((void**)&p_wqkv_l, g_wqkv_l);
  cudaGetSymbolAddress((void**)&p_wout_h, g_wout_h);
  cudaGetSymbolAddress((void**)&p_wout_l, g_wout_l);
  cudaGetSymbolAddress((void**)&p_wg_h, g_wg_h);
  cudaGetSymbolAddress((void**)&p_wg_l, g_wg_l);
  cudaGetSymbolAddress((void**)&p_wu_h, g_wu_h);
  cudaGetSymbolAddress((void**)&p_wu_l, g_wu_l);
  cudaGetSymbolAddress((void**)&p_wd_h, g_wd_h);
  cudaGetSymbolAddress((void**)&p_wd_l, g_wd_l);
  cudaGetSymbolAddress((void**)&p_xh, g_xh);
  cudaGetSymbolAddress((void**)&p_xl, g_xl);
  cudaGetSymbolAddress((void**)&p_ah, g_ah);
  cudaGetSymbolAddress((void**)&p_al, g_al);
  cudaGetSymbolAddress((void**)&p_gh, g_gh);
  cudaGetSymbolAddress((void**)&p_gl, g_gl);

  cudaFuncSetAttribute(tgemm<0,false>, cudaFuncAttributeMaxDynamicSharedMemorySize, TG_SMEM);
  cudaFuncSetAttribute(tgemm<0,true>,  cudaFuncAttributeMaxDynamicSharedMemorySize, TG_SMEM);
  cudaFuncSetAttribute(tgemm<2,false>, cudaFuncAttributeMaxDynamicSharedMemorySize, TG_SMEM);

  const int n_td = TT*TD;
  float* resid = (out_size >= 2*n_td) ? (out + (size_t)n_td) : p_res;

  // 0. weight conversion / transposition (bf16 hi/lo split)
  convsplit<<<(OQKV*TD/4+255)/256,256>>>(wqkv, p_wqkv_h, p_wqkv_l, OQKV*TD/4);
  convsplit<<<(TD*TD/4+255)/256,256>>>(wout, p_wout_h, p_wout_l, TD*TD/4);
  transsplit<<<dim3(TF/32, TD/32, TE), dim3(32,8)>>>(wgate, p_wg_h, p_wg_l, TD, TF);
  transsplit<<<dim3(TF/32, TD/32, TE), dim3(32,8)>>>(wup,   p_wu_h, p_wu_l, TD, TF);
  transsplit<<<dim3(TD/32, TF/32, TE), dim3(32,8)>>>(wdown, p_wd_h, p_wd_l, TF, TD);

  // 1. LN1 -> fp32 + bf16 hi/lo
  ln_kernel<<<TT,256>>>(hidden, ln1w, p_h, p_xh, p_xl);

  // 2. QKV = x @ wqkv^T
  tgemm<0,false><<<dim3(OQKV/128, TT/128), 256, TG_SMEM>>>(
      TT, OQKV, TD, p_xh, p_xl, TD, p_wqkv_h, p_wqkv_l, TD,
      p_qkv, OQKV, 1.f, nullptr, nullptr, nullptr);

  // 3. RoPE
  {
    int total = TT*(TH+TKV)*(THD/2);
    rope_kernel<<<(total+255)/256,256>>>(p_qkv, cosb, sinb);
  }

  // 4. scores (fp32, causal-skip)
  sgemm<true,1,1><<<dim3(TS_/128, TS_/128, TBATCH*TH),256>>>(
      TS_, TS_, THD, p_qkv, OQKV, p_qkv, OQKV, p_scores, TS_, 1.f/sqrtf((float)THD));

  // 5. softmax
  softmax_kernel<<<TBATCH*TH*TS_,256>>>(p_scores);

  // 6. attn = P @ V (fp32, K-truncated)
  sgemm<false,0,2><<<dim3(THD/128, TS_/128, TBATCH*TH),256>>>(
      TS_, THD, TS_, p_scores, TS_, p_qkv, OQKV, p_attn, TH*THD, 1.f);

  // 6b. attn -> bf16 hi/lo
  convsplit<<<(n_td/4+255)/256,256>>>(p_attn, p_ah, p_al, n_td/4);

  // 7. proj = attn @ wout^T -> reuse g_qkv
  tgemm<0,false><<<dim3(TD/128, TT/128), 256, TG_SMEM>>>(
      TT, TD, TH*THD, p_ah, p_al, TH*THD, p_wout_h, p_wout_l, TH*THD,
      p_qkv, TD, 1.f, nullptr, nullptr, nullptr);

  // 8. residual
  add_kernel<<<(n_td+255)/256,256>>>(p_qkv, hidden, resid, n_td);

  // 9. LN2 -> fp32 x + bf16 hi/lo
  ln_kernel<<<TT,256>>>(resid, ln2w, p_h, p_xh, p_xl);

  // 10. zero + router
  zero_kernel<<<(n_td+255)/256,256>>>(out, n_td);
  zero_cnt_kernel<<<1,32>>>();
  router_kernel<<<TT,128>>>(p_h, wrouter);

  // 11. MoE experts
  for (int e=0; e<TE; e++){
    const int* lst = p_elist + e*TT;
    const float* wts = p_ew + e*TT;
    const int* cnt = p_ecnt + e;
    tgemm<0,true><<<dim3(TF/128, TT/128), 256, TG_SMEM>>>(
        TT, TF, TD, p_xh, p_xl, TD,
        p_wg_h + (size_t)e*TF*TD, p_wg_l + (size_t)e*TF*TD, TD,
        p_G, TF, 1.f, lst, nullptr, cnt);
    tgemm<0,true><<<dim3(TF/128, TT/128), 256, TG_SMEM>>>(
        TT, TF, TD, p_xh, p_xl, TD,
        p_wu_h + (size_t)e*TF*TD, p_wu_l + (size_t)e*TF*TD, TD,
        p_U, TF, 1.f, lst, nullptr, cnt);
    silu_mul_kernel<<<(TT*TF+255)/256,256>>>(cnt, p_gh, p_gl);
    tgemm<2,false><<<dim3(TD/128, TT/128), 256, TG_SMEM>>>(
        TT, TD, TF, p_gh, p_gl, TF,
        p_wd_h + (size_t)e*TD*TF, p_wd_l + (size_t)e*TD*TF, TF,
        out, TD, 1.f, lst, wts, cnt);
  }

  if (resid == p_res && out_size >= 2*n_td){
    add_kernel<<<(n_td+255)/256,256>>>(p_qkv, hidden, out + (size_t)n_td, n_td);
  }
}

// round 5
// speedup vs baseline: 4.6815x; 1.5494x over previous
#include <cuda_runtime.h>
#include <cuda_fp16.h>
#include <math.h>
#include <stdint.h>

// Problem constants
#define TS_ 1024
#define TBATCH 2
#define TD 2048
#define TH 16
#define TKV 4
#define THD 128
#define TE 8
#define TF 2048
#define TT (TBATCH*TS_)            // 2048 tokens
#define OQKV ((TH+2*TKV)*THD)      // 3072
#define REP (TH/TKV)               // 4

typedef unsigned short u16;

// ---------------- scratch (device globals) ----------
__device__ float g_h[(size_t)TT*TD];
__device__ float g_qkv[(size_t)TT*OQKV];
__device__ float g_scores[(size_t)TBATCH*TH*TS_*TS_];
__device__ float g_attn[(size_t)TT*TH*THD];
__device__ float g_res[(size_t)TT*TD];
__device__ float g_GU[(size_t)TT*2*TF];
__device__ int   g_elist[TE*TT];
__device__ float g_ew[TE*TT];
__device__ int   g_ecnt[TE];

// fp16 buffers
__device__ u16 g_wqkv_h[(size_t)OQKV*TD];                 // [OQKV][D]
__device__ u16 g_wout_h[(size_t)TD*TD];                   // [D][H*HD]
__device__ u16 g_wgu_h[(size_t)TE*2*TF*TD];               // [e][2F][D] (gate rows 0..F-1, up F..2F-1)
__device__ u16 g_wd_h[(size_t)TE*TD*TF];                  // [e][D][F]
__device__ u16 g_xh[(size_t)TT*TD],  g_xl[(size_t)TT*TD];
__device__ u16 g_ah[(size_t)TT*TD],  g_al[(size_t)TT*TD];
__device__ u16 g_gh[(size_t)TT*TF],  g_gl[(size_t)TT*TF];
__device__ u16 g_qh[(size_t)TT*OQKV], g_ql[(size_t)TT*OQKV];
__device__ u16 g_ph[(size_t)TBATCH*TH*TS_*TS_], g_pl[(size_t)TBATCH*TH*TS_*TS_];
__device__ u16 g_vt[(size_t)TBATCH*TKV*THD*TS_];          // [b][kv][hd][s]

// ---------------- helpers ----------------
__device__ __forceinline__ u16 h16(float x){
  __half h = __float2half_rn(x);
  return *reinterpret_cast<u16*>(&h);
}
__device__ __forceinline__ float h2f(u16 b){
  __half h = *reinterpret_cast<__half*>(&b);
  return __half2float(h);
}
__device__ __forceinline__ uint32_t smem_u32(const void* p){
  uint32_t a;
  asm("{ .reg .u64 t; cvta.to.shared.u64 t, %1; cvt.u32.u64 %0, t; }" : "=r"(a) : "l"(p));
  return a;
}
__device__ __forceinline__ void ldsm_x4(uint32_t* r, uint32_t addr){
  asm volatile("ldmatrix.sync.aligned.m8n8.x4.shared.b16 {%0,%1,%2,%3}, [%4];"
    : "=r"(r[0]),"=r"(r[1]),"=r"(r[2]),"=r"(r[3]) : "r"(addr));
}
__device__ __forceinline__ void ldsm_x2(uint32_t* r, uint32_t addr){
  asm volatile("ldmatrix.sync.aligned.m8n8.x2.shared.b16 {%0,%1}, [%2];"
    : "=r"(r[0]),"=r"(r[1]) : "r"(addr));
}
__device__ __forceinline__ void mma16816(float* c, const uint32_t* a, const uint32_t* b){
  asm volatile("mma.sync.aligned.m16n8k16.row.col.f32.f16.f16.f32 "
    "{%0,%1,%2,%3}, {%4,%5,%6,%7}, {%8,%9}, {%0,%1,%2,%3};"
    : "+f"(c[0]),"+f"(c[1]),"+f"(c[2]),"+f"(c[3])
    : "r"(a[0]),"r"(a[1]),"r"(a[2]),"r"(a[3]), "r"(b[0]),"r"(b[1]));
}
__device__ __forceinline__ void cp16(uint32_t dst, const void* src, int ssz){
  asm volatile("cp.async.cg.shared.global [%0], [%1], 16, %2;"
    :: "r"(dst), "l"(src), "r"(ssz) : "memory");
}
__device__ __forceinline__ void cp16f(uint32_t dst, const void* src){
  asm volatile("cp.async.cg.shared.global [%0], [%1], 16;"
    :: "r"(dst), "l"(src) : "memory");
}
#define CP_COMMIT() asm volatile("cp.async.commit_group;":::"memory")
#define CP_WAIT(n)  asm volatile("cp.async.wait_group %0;"::"n"(n):"memory")

// ---------------- conversion kernels ----------------
__global__ void convhalf(const float* __restrict__ src, u16* __restrict__ d, int n4){
  int i = blockIdx.x*blockDim.x + threadIdx.x;
  if (i >= n4) return;
  float4 v = reinterpret_cast<const float4*>(src)[i];
  ushort4 hv; hv.x=h16(v.x); hv.y=h16(v.y); hv.z=h16(v.z); hv.w=h16(v.w);
  reinterpret_cast<ushort4*>(d)[i]=hv;
}
__global__ void convsplit(const float* __restrict__ src, u16* __restrict__ h,
                          u16* __restrict__ l, int n4){
  int i = blockIdx.x*blockDim.x + threadIdx.x;
  if (i >= n4) return;
  float4 v = reinterpret_cast<const float4*>(src)[i];
  ushort4 hv, lv;
  hv.x=h16(v.x); hv.y=h16(v.y); hv.z=h16(v.z); hv.w=h16(v.w);
  lv.x=h16(v.x-h2f(hv.x)); lv.y=h16(v.y-h2f(hv.y));
  lv.z=h16(v.z-h2f(hv.z)); lv.w=h16(v.w-h2f(hv.w));
  reinterpret_cast<ushort4*>(h)[i]=hv;
  reinterpret_cast<ushort4*>(l)[i]=lv;
}
// transpose [R,C] -> [C,R] fp16, batched over z
__global__ void transhalf(const float* __restrict__ src, u16* __restrict__ dst,
                          int R, int C, size_t sstr, size_t dstr){
  __shared__ float t[32][33];
  src += (size_t)blockIdx.z * sstr;
  dst += (size_t)blockIdx.z * dstr;
  int c0 = blockIdx.x*32, r0 = blockIdx.y*32;
  int tx = threadIdx.x, ty = threadIdx.y;   // 32 x 8
  #pragma unroll
  for (int j=0;j<4;j++)
    t[ty+j*8][tx] = src[(size_t)(r0+ty+j*8)*C + c0+tx];
  __syncthreads();
  #pragma unroll
  for (int j=0;j<4;j++)
    dst[(size_t)(c0+ty+j*8)*R + r0+tx] = h16(t[tx][ty+j*8]);
}
// V^T: vt[(b*KV+kv)][hd][s] = qkv[b*TS+s][(TH+TKV+kv)*THD+hd]
__global__ void vtrans(const float* __restrict__ qkv, u16* __restrict__ vt){
  __shared__ float t[32][33];
  int z = blockIdx.z; int b = z/TKV, kv = z%TKV;
  int s0 = blockIdx.x*32, h0 = blockIdx.y*32;
  int tx = threadIdx.x, ty = threadIdx.y;
  #pragma unroll
  for (int j=0;j<4;j++){
    int s = s0+ty+j*8;
    t[ty+j*8][tx] = qkv[(size_t)(b*TS_+s)*OQKV + (TH+TKV+kv)*THD + h0+tx];
  }
  __syncthreads();
  #pragma unroll
  for (int j=0;j<4;j++){
    int hd = h0+ty+j*8;
    vt[((size_t)z*THD + hd)*TS_ + s0+tx] = h16(t[tx][ty+j*8]);
  }
}

// ---------------- tensor-core GEMM (fp16 2-term, 3-stage cp.async) ---------
// C[M,N] = alpha * (Ah+Al)[M,K] @ Bh[N,K]^T
// EPI 0: store. EPI 2: C[arow[m]] += aw[m]*v.
// ADDR 0: plain (GATHER optional). ADDR 1: attention scores. ADDR 2: PV.
#define TPAD 80          // bytes per smem row (40 halfs)
#define MATB (128*TPAD)  // 10240 bytes
#define STAGEB (3*MATB)  // Ah, Al, Bh
#define TG_SMEM (3*STAGEB)

template<int EPI, bool GATHER, int ADDR>
__global__ __launch_bounds__(256,2) void tgemm(
    int M, int N, int K,
    const u16* __restrict__ Ah, const u16* __restrict__ Al, int lda,
    const u16* __restrict__ Bh, int ldb,
    float* __restrict__ C, int ldc, float alpha,
    const int* __restrict__ arow, const float* __restrict__ aw,
    const int* __restrict__ cntp)
{
  extern __shared__ __align__(16) char smem[];
  int row0 = blockIdx.y*128, col0 = blockIdx.x*128;
  int Klim = K;

  if (ADDR==1){
    if (col0 > row0 + 127) return;   // fully masked: never read by softmax
    int z = blockIdx.z, b = z/TH, h = z%TH;
    Ah += (size_t)b*TS_*OQKV + h*THD;
    Al += (size_t)b*TS_*OQKV + h*THD;
    lda = OQKV;
    Bh += (size_t)b*TS_*OQKV + (TH + h/REP)*THD;
    ldb = OQKV;
    C  += (size_t)z*TS_*TS_;
    ldc = TS_;
  } else if (ADDR==2){
    int z = blockIdx.z, b = z/TH, h = z%TH;
    Ah += (size_t)z*TS_*TS_;
    Al += (size_t)z*TS_*TS_;
    lda = TS_;
    Bh += ((size_t)(b*TKV + h/REP))*THD*TS_;
    ldb = TS_;
    C  += (size_t)b*TS_*(TH*THD) + h*THD;
    ldc = TH*THD;
    Klim = min(K, row0 + 128);
  }

  int Meff = cntp ? *cntp : M;
  if (row0 >= Meff) return;

  int tid = threadIdx.x, wid = tid>>5, lane = tid&31;
  int wm = wid>>2, wn = wid&3;
  uint32_t sbase = smem_u32(smem);

  uint32_t laneA = (uint32_t)((lane&15)*TPAD) + (uint32_t)((lane>>4)*16);
  uint32_t laneB = (uint32_t)((lane&7)*TPAD)  + (uint32_t)(((lane>>3)&1)*16);

  float acc[4][4][4];
  #pragma unroll
  for(int i=0;i<4;i++)
    #pragma unroll
    for(int j=0;j<4;j++)
      #pragma unroll
      for(int q=0;q<4;q++) acc[i][j][q]=0.f;

  const int NC = Klim/32;

  // precompute per-thread load pointers (row indices invariant across chunks)
  const u16* paH[2]; const u16* paL[2]; const u16* pbH[2];
  int apred[2];
  uint32_t doff[2];
  #pragma unroll
  for (int it=0; it<2; it++){
    int q = tid + it*256;
    int r = q>>2, c16 = q&3;
    doff[it] = (uint32_t)(r*TPAD + c16*16);
    int gm = row0 + r;
    apred[it] = gm < Meff;
    long src = apred[it] ? (GATHER ? (long)arow[gm] : (long)gm) : 0;
    paH[it] = Ah + src*(long)lda + c16*8;
    paL[it] = Al + src*(long)lda + c16*8;
    pbH[it] = Bh + (long)(col0+r)*ldb + c16*8;
  }

  auto issue = [&](int c){
    uint32_t dst0 = sbase + (c%3)*STAGEB;
    int k0 = c*32;
    #pragma unroll
    for (int it=0; it<2; it++){
      int ssz = apred[it] ? 16 : 0;
      cp16(dst0 + doff[it],          paH[it] + k0, ssz);
      cp16(dst0 + MATB + doff[it],   paL[it] + k0, ssz);
      cp16f(dst0 + 2*MATB + doff[it], pbH[it] + k0);
    }
    CP_COMMIT();
  };

  issue(0); issue(1);
  for (int c = 0; c < NC; c++){
    if (c+1 < NC) { CP_WAIT(1); } else { CP_WAIT(0); }
    __syncthreads();
    if (c+2 < NC) issue(c+2);

    uint32_t st = sbase + (c%3)*STAGEB;
    #pragma unroll
    for (int ks = 0; ks < 2; ks++){
      uint32_t rowA = st + (uint32_t)((wm*64)*TPAD + ks*32) + laneA;
      uint32_t rowB = st + 2*MATB + (uint32_t)((wn*32)*TPAD + ks*32) + laneB;
      uint32_t aH[4][4], bH[4][2];
      #pragma unroll
      for (int mf=0; mf<4; mf++) ldsm_x4(aH[mf], rowA + mf*16*TPAD);
      #pragma unroll
      for (int nf=0; nf<4; nf++) ldsm_x2(bH[nf], rowB + nf*8*TPAD);
      #pragma unroll
      for (int mf=0; mf<4; mf++)
        #pragma unroll
        for (int nf=0; nf<4; nf++) mma16816(acc[mf][nf], aH[mf], bH[nf]);
      {
        uint32_t aL[4][4];
        #pragma unroll
        for (int mf=0; mf<4; mf++) ldsm_x4(aL[mf], rowA + MATB + mf*16*TPAD);
        #pragma unroll
        for (int mf=0; mf<4; mf++)
          #pragma unroll
          for (int nf=0; nf<4; nf++) mma16816(acc[mf][nf], aL[mf], bH[nf]);
      }
    }
    __syncthreads();
  }

  // ---- epilogue ----
  int g = lane>>2, tig = lane&3;
  #pragma unroll
  for (int mf=0; mf<4; mf++){
    int ra = row0 + wm*64 + mf*16 + g;
    int rb = ra + 8;
    #pragma unroll
    for (int nf=0; nf<4; nf++){
      int col = col0 + wn*32 + nf*8 + tig*2;
      float* cacc = acc[mf][nf];
      if (EPI == 0){
        if (ra < Meff){
          float* p = C + (size_t)ra*ldc + col;
          p[0] = cacc[0]*alpha; p[1] = cacc[1]*alpha;
        }
        if (rb < Meff){
          float* p = C + (size_t)rb*ldc + col;
          p[0] = cacc[2]*alpha; p[1] = cacc[3]*alpha;
        }
      } else {
        if (ra < Meff){
          float w = aw[ra];
          float* p = C + (size_t)arow[ra]*ldc + col;
          p[0] += w*cacc[0]*alpha; p[1] += w*cacc[1]*alpha;
        }
        if (rb < Meff){
          float w = aw[rb];
          float* p = C + (size_t)arow[rb]*ldc + col;
          p[0] += w*cacc[2]*alpha; p[1] += w*cacc[3]*alpha;
        }
      }
    }
  }
}

// ---------------- reduction helpers ----------------
__device__ __forceinline__ float warp_sum(float v){
  #pragma unroll
  for(int o=16;o;o>>=1) v += __shfl_xor_sync(0xffffffffu, v, o);
  return v;
}
__device__ __forceinline__ float warp_max(float v){
  #pragma unroll
  for(int o=16;o;o>>=1) v = fmaxf(v, __shfl_xor_sync(0xffffffffu, v, o));
  return v;
}

// ---------------- LayerNorm (fp32 + fp16 hi/lo out) ----------------
__global__ void ln_kernel(const float* __restrict__ x, const float* __restrict__ w,
                          float* __restrict__ y, u16* __restrict__ yh, u16* __restrict__ yl){
  int row = blockIdx.x;
  const float* xr = x + (size_t)row*TD;
  float s=0.f, s2=0.f;
  for(int d=threadIdx.x; d<TD; d+=blockDim.x){ float v=xr[d]; s+=v; s2+=v*v; }
  __shared__ float shs[8], shs2[8];
  int lane=threadIdx.x&31, wp=threadIdx.x>>5;
  s = warp_sum(s); s2 = warp_sum(s2);
  if(!lane){ shs[wp]=s; shs2[wp]=s2; }
  __syncthreads();
  if (threadIdx.x < 32){
    float a = (threadIdx.x<8)? shs[threadIdx.x] : 0.f;
    float b = (threadIdx.x<8)? shs2[threadIdx.x] : 0.f;
    a = warp_sum(a); b = warp_sum(b);
    if(!threadIdx.x){ shs[0]=a; shs2[0]=b; }
  }
  __syncthreads();
  float mu = shs[0]*(1.f/TD);
  float var = shs2[0]*(1.f/TD) - mu*mu;
  float rstd = rsqrtf(var + 1e-5f);
  for(int d=threadIdx.x; d<TD; d+=blockDim.x){
    float v = (xr[d]-mu)*rstd*w[d];
    y[(size_t)row*TD + d] = v;
    u16 h = h16(v);
    yh[(size_t)row*TD + d] = h;
    yl[(size_t)row*TD + d] = h16(v - h2f(h));
  }
}

// ---------------- RoPE: rotate q,k and emit fp16 split ----------------
__global__ void rope_kernel(const float* __restrict__ qkv,
                            const float* __restrict__ cosb,
                            const float* __restrict__ sinb,
                            u16* __restrict__ qh, u16* __restrict__ ql){
  int idx = blockIdx.x*blockDim.x + threadIdx.x;
  const int total = TT*(TH+TKV)*(THD/2);
  if (idx >= total) return;
  int i  = idx & 63;
  int rest = idx >> 6;
  int hh = rest % (TH+TKV);
  int t  = rest / (TH+TKV);
  int s  = t % TS_;
  float c  = cosb[s*THD + i];
  float sn = sinb[s*THD + i];
  const float* p = qkv + (size_t)t*OQKV + hh*THD;
  float x1 = p[i], x2 = p[i+64];
  float r1 = x1*c - x2*sn;
  float r2 = x2*c + x1*sn;
  size_t o = (size_t)t*OQKV + hh*THD;
  u16 h1 = h16(r1), h2 = h16(r2);
  qh[o+i] = h1;    ql[o+i]    = h16(r1 - h2f(h1));
  qh[o+i+64] = h2; ql[o+i+64] = h16(r2 - h2f(h2));
}

// ---------------- causal softmax: fp32 scores in, fp16 split P out ---------
__global__ void softmax_kernel(const float* __restrict__ s,
                               u16* __restrict__ ph, u16* __restrict__ pl){
  int row = blockIdx.x;
  int q = row % TS_;
  int L = q + 1;
  int pad = ((q>>7)+1)<<7;   // PV reads up to this K bound
  const float* r = s + (size_t)row*TS_;
  u16* oh = ph + (size_t)row*TS_;
  u16* ol = pl + (size_t)row*TS_;
  int tid = threadIdx.x;
  int lane = tid&31, wp = tid>>5;
  __shared__ float sh[8];

  float mx = -1e30f;
  for(int d=tid; d<L; d+=256) mx = fmaxf(mx, r[d]);
  mx = warp_max(mx);
  if(!lane) sh[wp]=mx;
  __syncthreads();
  if (tid<32){ float v=(tid<8)?sh[tid]:-1e30f; v=warp_max(v); if(!tid) sh[0]=v; }
  __syncthreads();
  mx = sh[0];
  __syncthreads();

  float sum = 0.f;
  for(int d=tid; d<L; d+=256) sum += __expf(r[d]-mx);
  sum = warp_sum(sum);
  if(!lane) sh[wp]=sum;
  __syncthreads();
  if (tid<32){ float v=(tid<8)?sh[tid]:0.f; v=warp_sum(v); if(!tid) sh[0]=v; }
  __syncthreads();
  float inv = 1.f/sh[0];

  for(int d=tid; d<L; d+=256){
    float p = __expf(r[d]-mx)*inv;
    u16 h = h16(p);
    oh[d] = h;
    ol[d] = h16(p - h2f(h));
  }
  for(int d=L+tid; d<pad; d+=256){ oh[d]=0; ol[d]=0; }
}

// ---------------- elementwise ----------------
__global__ void add_kernel(const float* __restrict__ a, const float* __restrict__ b,
                           float* __restrict__ c, int n){
  int i = blockIdx.x*blockDim.x + threadIdx.x;
  if (i<n) c[i]=a[i]+b[i];
}
__global__ void zero_kernel(float* __restrict__ p, int n){
  int i = blockIdx.x*blockDim.x + threadIdx.x;
  if (i<n) p[i]=0.f;
}
__global__ void zero_cnt_kernel(){
  if (threadIdx.x < TE) g_ecnt[threadIdx.x]=0;
}
__global__ void silu_mul_kernel(const int* __restrict__ cntp,
                                u16* __restrict__ gh, u16* __restrict__ gl){
  int n = (*cntp)*TF;
  int i = blockIdx.x*blockDim.x + threadIdx.x;
  if (i>=n) return;
  int m = i/TF, f = i%TF;
  float g = g_GU[(size_t)m*(2*TF) + f];
  float u = g_GU[(size_t)m*(2*TF) + TF + f];
  float y = (g/(1.f+__expf(-g)))*u;
  u16 h = h16(y);
  gh[i] = h;
  gl[i] = h16(y - h2f(h));
}

// ---------------- router ----------------
__global__ void router_kernel(const float* __restrict__ x, const float* __restrict__ wr){
  int t = blockIdx.x;
  int tid = threadIdx.x;
  const float* xr = x + (size_t)t*TD;
  float acc[TE];
  #pragma unroll
  for(int e=0;e<TE;e++) acc[e]=0.f;
  for(int d=tid; d<TD; d+=128){
    float xv = xr[d];
    #pragma unroll
    for(int e=0;e<TE;e++) acc[e] += xv*wr[e*TD+d];
  }
  __shared__ float sh[TE][4];
  int lane=tid&31, wp=tid>>5;
  #pragma unroll
  for(int e=0;e<TE;e++){
    float v = warp_sum(acc[e]);
    if(!lane) sh[e][wp]=v;
  }
  __syncthreads();
  if (tid==0){
    float lg[TE];
    float mx=-1e30f;
    #pragma unroll
    for(int e=0;e<TE;e++){ lg[e]=sh[e][0]+sh[e][1]+sh[e][2]+sh[e][3]; mx=fmaxf(mx,lg[e]); }
    float p[TE]; float s=0.f;
    #pragma unroll
    for(int e=0;e<TE;e++){ p[e]=expf(lg[e]-mx); s+=p[e]; }
    float inv=1.f/s;
    #pragma unroll
    for(int e=0;e<TE;e++) p[e]*=inv;
    int e0=0;
    #pragma unroll
    for(int e=1;e<TE;e++) if (p[e]>p[e0]) e0=e;
    int e1=-1;
    #pragma unroll
    for(int e=0;e<TE;e++){ if(e==e0) continue; if (e1<0 || p[e]>p[e1]) e1=e; }
    float w0=p[e0], w1=p[e1];
    float tot = w0+w1;
    w0/=tot; w1/=tot;
    int pos = atomicAdd(&g_ecnt[e0],1);
    g_elist[e0*TT+pos]=t; g_ew[e0*TT+pos]=w0;
    pos = atomicAdd(&g_ecnt[e1],1);
    g_elist[e1*TT+pos]=t; g_ew[e1*TT+pos]=w1;
  }
}

// ---------------- launcher ----------------
extern "C" void kernel_launch(void* const* d_in, const int* in_sizes, int n_in,
                              void* d_out, int out_size){
  const float* hidden  = (const float*)d_in[0];
  const float* cosb    = (const float*)d_in[1];
  const float* sinb    = (const float*)d_in[2];
  const float* ln1w    = (const float*)d_in[3];
  const float* ln2w    = (const float*)d_in[4];
  const float* wqkv    = (const float*)d_in[5];
  const float* wout    = (const float*)d_in[6];
  const float* wrouter = (const float*)d_in[7];
  const float* wgate   = (const float*)d_in[8];
  const float* wup     = (const float*)d_in[9];
  const float* wdown   = (const float*)d_in[10];
  float* out = (float*)d_out;

  float *p_h,*p_qkv,*p_scores,*p_attn,*p_res,*p_GU,*p_ew;
  int *p_elist,*p_ecnt;
  u16 *p_wqkv,*p_wout,*p_wgu,*p_wd;
  u16 *p_xh,*p_xl,*p_ah,*p_al,*p_gh,*p_gl,*p_qh,*p_ql,*p_ph,*p_pl,*p_vt;
  cudaGetSymbolAddress((void**)&p_h, g_h);
  cudaGetSymbolAddress((void**)&p_qkv, g_qkv);
  cudaGetSymbolAddress((void**)&p_scores, g_scores);
  cudaGetSymbolAddress((void**)&p_attn, g_attn);
  cudaGetSymbolAddress((void**)&p_res, g_res);
  cudaGetSymbolAddress((void**)&p_GU, g_GU);
  cudaGetSymbolAddress((void**)&p_ew, g_ew);
  cudaGetSymbolAddress((void**)&p_elist, g_elist);
  cudaGetSymbolAddress((void**)&p_ecnt, g_ecnt);
  cudaGetSymbolAddress((void**)&p_wqkv, g_wqkv_h);
  cudaGetSymbolAddress((void**)&p_wout, g_wout_h);
  cudaGetSymbolAddress((void**)&p_wgu, g_wgu_h);
  cudaGetSymbolAddress((void**)&p_wd, g_wd_h);
  cudaGetSymbolAddress((void**)&p_xh, g_xh);
  cudaGetSymbolAddress((void**)&p_xl, g_xl);
  cudaGetSymbolAddress((void**)&p_ah, g_ah);
  cudaGetSymbolAddress((void**)&p_al, g_al);
  cudaGetSymbolAddress((void**)&p_gh, g_gh);
  cudaGetSymbolAddress((void**)&p_gl, g_gl);
  cudaGetSymbolAddress((void**)&p_qh, g_qh);
  cudaGetSymbolAddress((void**)&p_ql, g_ql);
  cudaGetSymbolAddress((void**)&p_ph, g_ph);
  cudaGetSymbolAddress((void**)&p_pl, g_pl);
  cudaGetSymbolAddress((void**)&p_vt, g_vt);

  cudaFuncSetAttribute(tgemm<0,false,0>, cudaFuncAttributeMaxDynamicSharedMemorySize, TG_SMEM);
  cudaFuncSetAttribute(tgemm<0,true,0>,  cudaFuncAttributeMaxDynamicSharedMemorySize, TG_SMEM);
  cudaFuncSetAttribute(tgemm<2,false,0>, cudaFuncAttributeMaxDynamicSharedMemorySize, TG_SMEM);
  cudaFuncSetAttribute(tgemm<0,false,1>, cudaFuncAttributeMaxDynamicSharedMemorySize, TG_SMEM);
  cudaFuncSetAttribute(tgemm<0,false,2>, cudaFuncAttributeMaxDynamicSharedMemorySize, TG_SMEM);

  const int n_td = TT*TD;
  float* resid = (out_size >= 2*n_td) ? (out + (size_t)n_td) : p_res;

  // 0. weight conversion (fp16 single)
  convhalf<<<(OQKV*TD/4+255)/256,256>>>(wqkv, p_wqkv, OQKV*TD/4);
  convhalf<<<(TD*TD/4+255)/256,256>>>(wout, p_wout, TD*TD/4);
  transhalf<<<dim3(TF/32, TD/32, TE), dim3(32,8)>>>(wgate, p_wgu, TD, TF,
      (size_t)TD*TF, (size_t)2*TF*TD);
  transhalf<<<dim3(TF/32, TD/32, TE), dim3(32,8)>>>(wup, p_wgu + (size_t)TF*TD, TD, TF,
      (size_t)TD*TF, (size_t)2*TF*TD);
  transhalf<<<dim3(TD/32, TF/32, TE), dim3(32,8)>>>(wdown, p_wd, TF, TD,
      (size_t)TF*TD, (size_t)TD*TF);

  // 1. LN1 -> fp32 + fp16 split
  ln_kernel<<<TT,256>>>(hidden, ln1w, p_h, p_xh, p_xl);

  // 2. QKV = x @ wqkv^T
  tgemm<0,false,0><<<dim3(OQKV/128, TT/128), 256, TG_SMEM>>>(
      TT, OQKV, TD, p_xh, p_xl, TD, p_wqkv, TD,
      p_qkv, OQKV, 1.f, nullptr, nullptr, nullptr);

  // 3. RoPE -> qh/ql (fp16 split of rotated q,k)
  {
    int total = TT*(TH+TKV)*(THD/2);
    rope_kernel<<<(total+255)/256,256>>>(p_qkv, cosb, sinb, p_qh, p_ql);
  }
  // 3b. V^T fp16
  vtrans<<<dim3(TS_/32, THD/32, TBATCH*TKV), dim3(32,8)>>>(p_qkv, p_vt);

  // 4. scores = Q K^T / sqrt(HD) (tensor, causal tile-skip, no mask writes)
  tgemm<0,false,1><<<dim3(TS_/128, TS_/128, TBATCH*TH), 256, TG_SMEM>>>(
      TS_, TS_, THD, p_qh, p_ql, 0, p_qh, 0,
      p_scores, 0, 1.f/sqrtf((float)THD), nullptr, nullptr, nullptr);

  // 5. causal softmax -> P fp16 split (zero-padded to 128-boundary)
  softmax_kernel<<<TBATCH*TH*TS_,256>>>(p_scores, p_ph, p_pl);

  // 6. attn = P @ V (tensor, K-truncated)
  tgemm<0,false,2><<<dim3(1, TS_/128, TBATCH*TH), 256, TG_SMEM>>>(
      TS_, THD, TS_, p_ph, p_pl, 0, p_vt, 0,
      p_attn, 0, 1.f, nullptr, nullptr, nullptr);

  // 6b. attn -> fp16 split
  convsplit<<<(n_td/4+255)/256,256>>>(p_attn, p_ah, p_al, n_td/4);

  // 7. proj = attn @ wout^T -> reuse g_qkv
  tgemm<0,false,0><<<dim3(TD/128, TT/128), 256, TG_SMEM>>>(
      TT, TD, TH*THD, p_ah, p_al, TH*THD, p_wout, TH*THD,
      p_qkv, TD, 1.f, nullptr, nullptr, nullptr);

  // 8. residual
  add_kernel<<<(n_td+255)/256,256>>>(p_qkv, hidden, resid, n_td);

  // 9. LN2
  ln_kernel<<<TT,256>>>(resid, ln2w, p_h, p_xh, p_xl);

  // 10. zero + router
  zero_kernel<<<(n_td+255)/256,256>>>(out, n_td);
  zero_cnt_kernel<<<1,32>>>();
  router_kernel<<<TT,128>>>(p_h, wrouter);

  // 11. MoE experts: fused gate|up GEMM, silu, down (scatter)
  for (int e=0; e<TE; e++){
    const int* lst = p_elist + e*TT;
    const float* wts = p_ew + e*TT;
    const int* cnt = p_ecnt + e;
    tgemm<0,true,0><<<dim3(2*TF/128, TT/128), 256, TG_SMEM>>>(
        TT, 2*TF, TD, p_xh, p_xl, TD,
        p_wgu + (size_t)e*2*TF*TD, TD,
        p_GU, 2*TF, 1.f, lst, nullptr, cnt);
    silu_mul_kernel<<<(TT*TF+255)/256,256>>>(cnt, p_gh, p_gl);
    tgemm<2,false,0><<<dim3(TD/128, TT/128), 256, TG_SMEM>>>(
        TT, TD, TF, p_gh, p_gl, TF,
        p_wd + (size_t)e*TD*TF, TF,
        out, TD, 1.f, lst, wts, cnt);
  }

  if (resid == p_res && out_size >= 2*n_td){
    add_kernel<<<(n_td+255)/256,256>>>(p_qkv, hidden, out + (size_t)n_td, n_td);
  }
}

// round 6
// speedup vs baseline: 8.5448x; 1.8253x over previous
#include <cuda_runtime.h>
#include <cuda_fp16.h>
#include <math.h>
#include <stdint.h>

// Problem constants
#define TS_ 1024
#define TBATCH 2
#define TD 2048
#define TH 16
#define TKV 4
#define THD 128
#define TE 8
#define TF 2048
#define TT (TBATCH*TS_)            // 2048 tokens
#define OQKV ((TH+2*TKV)*THD)      // 3072
#define REP (TH/TKV)               // 4

typedef unsigned short u16;

// ---------------- scratch (device globals) ----------
__device__ float g_h[(size_t)TT*TD];
__device__ float g_qkv[(size_t)TT*OQKV];
__device__ float g_scores[(size_t)TBATCH*TH*TS_*TS_];
__device__ float g_attn[(size_t)TT*TH*THD];
__device__ float g_res[(size_t)TT*TD];
__device__ float g_GU[(size_t)TE*TT*2*TF];     // per-expert compact [e][m][2F]
__device__ int   g_elist[TE*TT];
__device__ float g_ew[TE*TT];
__device__ int   g_ecnt[TE];

// fp16 buffers
__device__ u16 g_wqkv_h[(size_t)OQKV*TD];
__device__ u16 g_wout_h[(size_t)TD*TD];
__device__ u16 g_wgu_h[(size_t)TE*2*TF*TD];    // [e][2F][D]
__device__ u16 g_wd_h[(size_t)TE*TD*TF];       // [e][D][F]
__device__ u16 g_xh[(size_t)TT*TD],  g_xl[(size_t)TT*TD];
__device__ u16 g_ah[(size_t)TT*TD],  g_al[(size_t)TT*TD];
__device__ u16 g_gh[(size_t)TE*TT*TF], g_gl[(size_t)TE*TT*TF];
__device__ u16 g_qh[(size_t)TT*OQKV], g_ql[(size_t)TT*OQKV];
__device__ u16 g_ph[(size_t)TBATCH*TH*TS_*TS_], g_pl[(size_t)TBATCH*TH*TS_*TS_];
__device__ u16 g_vt[(size_t)TBATCH*TKV*THD*TS_];

// ---------------- helpers ----------------
__device__ __forceinline__ u16 h16(float x){
  __half h = __float2half_rn(x);
  return *reinterpret_cast<u16*>(&h);
}
__device__ __forceinline__ float h2f(u16 b){
  __half h = *reinterpret_cast<__half*>(&b);
  return __half2float(h);
}
__device__ __forceinline__ uint32_t smem_u32(const void* p){
  uint32_t a;
  asm("{ .reg .u64 t; cvta.to.shared.u64 t, %1; cvt.u32.u64 %0, t; }" : "=r"(a) : "l"(p));
  return a;
}
__device__ __forceinline__ void ldsm_x4(uint32_t* r, uint32_t addr){
  asm volatile("ldmatrix.sync.aligned.m8n8.x4.shared.b16 {%0,%1,%2,%3}, [%4];"
    : "=r"(r[0]),"=r"(r[1]),"=r"(r[2]),"=r"(r[3]) : "r"(addr));
}
__device__ __forceinline__ void mma16816(float* c, const uint32_t* a, const uint32_t* b){
  asm volatile("mma.sync.aligned.m16n8k16.row.col.f32.f16.f16.f32 "
    "{%0,%1,%2,%3}, {%4,%5,%6,%7}, {%8,%9}, {%0,%1,%2,%3};"
    : "+f"(c[0]),"+f"(c[1]),"+f"(c[2]),"+f"(c[3])
    : "r"(a[0]),"r"(a[1]),"r"(a[2]),"r"(a[3]), "r"(b[0]),"r"(b[1]));
}
__device__ __forceinline__ void cp16(uint32_t dst, const void* src, int ssz){
  asm volatile("cp.async.cg.shared.global [%0], [%1], 16, %2;"
    :: "r"(dst), "l"(src), "r"(ssz) : "memory");
}
__device__ __forceinline__ void cp16f(uint32_t dst, const void* src){
  asm volatile("cp.async.cg.shared.global [%0], [%1], 16;"
    :: "r"(dst), "l"(src) : "memory");
}
#define CP_COMMIT() asm volatile("cp.async.commit_group;":::"memory")
#define CP_WAIT(n)  asm volatile("cp.async.wait_group %0;"::"n"(n):"memory")

// ---------------- conversion kernels ----------------
__global__ void convhalf(const float* __restrict__ src, u16* __restrict__ d, int n4){
  int i = blockIdx.x*blockDim.x + threadIdx.x;
  if (i >= n4) return;
  float4 v = reinterpret_cast<const float4*>(src)[i];
  ushort4 hv; hv.x=h16(v.x); hv.y=h16(v.y); hv.z=h16(v.z); hv.w=h16(v.w);
  reinterpret_cast<ushort4*>(d)[i]=hv;
}
__global__ void convsplit(const float* __restrict__ src, u16* __restrict__ h,
                          u16* __restrict__ l, int n4){
  int i = blockIdx.x*blockDim.x + threadIdx.x;
  if (i >= n4) return;
  float4 v = reinterpret_cast<const float4*>(src)[i];
  ushort4 hv, lv;
  hv.x=h16(v.x); hv.y=h16(v.y); hv.z=h16(v.z); hv.w=h16(v.w);
  lv.x=h16(v.x-h2f(hv.x)); lv.y=h16(v.y-h2f(hv.y));
  lv.z=h16(v.z-h2f(hv.z)); lv.w=h16(v.w-h2f(hv.w));
  reinterpret_cast<ushort4*>(h)[i]=hv;
  reinterpret_cast<ushort4*>(l)[i]=lv;
}
__global__ void transhalf(const float* __restrict__ src, u16* __restrict__ dst,
                          int R, int C, size_t sstr, size_t dstr){
  __shared__ float t[32][33];
  src += (size_t)blockIdx.z * sstr;
  dst += (size_t)blockIdx.z * dstr;
  int c0 = blockIdx.x*32, r0 = blockIdx.y*32;
  int tx = threadIdx.x, ty = threadIdx.y;
  #pragma unroll
  for (int j=0;j<4;j++)
    t[ty+j*8][tx] = src[(size_t)(r0+ty+j*8)*C + c0+tx];
  __syncthreads();
  #pragma unroll
  for (int j=0;j<4;j++)
    dst[(size_t)(c0+ty+j*8)*R + r0+tx] = h16(t[tx][ty+j*8]);
}
__global__ void vtrans(const float* __restrict__ qkv, u16* __restrict__ vt){
  __shared__ float t[32][33];
  int z = blockIdx.z; int b = z/TKV, kv = z%TKV;
  int s0 = blockIdx.x*32, h0 = blockIdx.y*32;
  int tx = threadIdx.x, ty = threadIdx.y;
  #pragma unroll
  for (int j=0;j<4;j++){
    int s = s0+ty+j*8;
    t[ty+j*8][tx] = qkv[(size_t)(b*TS_+s)*OQKV + (TH+TKV+kv)*THD + h0+tx];
  }
  __syncthreads();
  #pragma unroll
  for (int j=0;j<4;j++){
    int hd = h0+ty+j*8;
    vt[((size_t)z*THD + hd)*TS_ + s0+tx] = h16(t[tx][ty+j*8]);
  }
}

// ---------------- tensor-core GEMM (fp16 2-term, BK=64, 2-stage) -----------
// C[M,N] = alpha * (Ah+Al)[M,K] @ Bh[N,K]^T
// EPI 0: store. EPI 3: atomicAdd C[arow[m]] += aw[m]*v.
// ADDR 0: plain. 1: attn scores. 2: PV. 3: expert-batched gather-store.
// 4: expert-batched (A per-expert) atomic scatter.
#define TPAD 144          // bytes per smem row (72 halfs; conflict-free 4i pattern)
#define MATB (128*TPAD)   // 18432
#define STAGEB (3*MATB)   // Ah, Al, Bh
#define TG_SMEM (2*STAGEB)

template<int EPI, bool GATHER, int ADDR>
__global__ __launch_bounds__(256,2) void tgemm(
    int M, int N, int K,
    const u16* __restrict__ Ah, const u16* __restrict__ Al, int lda,
    const u16* __restrict__ Bh, int ldb,
    float* __restrict__ C, int ldc, float alpha,
    const int* __restrict__ arow, const float* __restrict__ aw,
    const int* __restrict__ cntp,
    size_t astride, size_t bstride, size_t cstride)
{
  extern __shared__ __align__(16) char smem[];
  int row0 = blockIdx.y*128, col0 = blockIdx.x*128;
  int Klim = K;

  if (ADDR==1){
    if (col0 > row0 + 127) return;
    int z = blockIdx.z, b = z/TH, h = z%TH;
    Ah += (size_t)b*TS_*OQKV + h*THD;
    Al += (size_t)b*TS_*OQKV + h*THD;
    lda = OQKV;
    Bh += (size_t)b*TS_*OQKV + (TH + h/REP)*THD;
    ldb = OQKV;
    C  += (size_t)z*TS_*TS_;
    ldc = TS_;
  } else if (ADDR==2){
    int z = blockIdx.z, b = z/TH, h = z%TH;
    Ah += (size_t)z*TS_*TS_;
    Al += (size_t)z*TS_*TS_;
    lda = TS_;
    Bh += ((size_t)(b*TKV + h/REP))*THD*TS_;
    ldb = TS_;
    C  += (size_t)b*TS_*(TH*THD) + h*THD;
    ldc = TH*THD;
    Klim = min(K, row0 + 128);
  } else if (ADDR==3 || ADDR==4){
    int z = blockIdx.z;
    arow += z*TT;
    if (ADDR==4){ aw += z*TT; Ah += (size_t)z*astride; Al += (size_t)z*astride; }
    cntp += z;
    Bh += (size_t)z*bstride;
    C  += (size_t)z*cstride;
  }

  int Meff = cntp ? *cntp : M;
  if (row0 >= Meff) return;

  int tid = threadIdx.x, wid = tid>>5, lane = tid&31;
  int wm = wid>>2, wn = wid&3;
  uint32_t sbase = smem_u32(smem);

  uint32_t laneA  = (uint32_t)((lane&15)*TPAD) + (uint32_t)((lane>>4)*16);
  uint32_t laneB4 = (uint32_t)((lane&7)*TPAD) + (uint32_t)(((lane>>3)&1)*16)
                  + (uint32_t)((lane>>4)*(8*TPAD));

  float acc[4][4][4];
  #pragma unroll
  for(int i=0;i<4;i++)
    #pragma unroll
    for(int j=0;j<4;j++)
      #pragma unroll
      for(int q=0;q<4;q++) acc[i][j][q]=0.f;

  const int NC = Klim/64;

  // per-thread load geometry (BK=64: 128 rows x 128B per matrix, 4 its)
  int c16 = tid&7, rt = tid>>3;     // rt 0..31
  uint32_t doff0 = (uint32_t)(rt*TPAD + c16*16);
  long aoff[4]; int apred[4];
  #pragma unroll
  for (int it=0; it<4; it++){
    int gm = row0 + rt + it*32;
    apred[it] = gm < Meff;
    long src = apred[it] ? ((GATHER||ADDR==3) ? (long)arow[gm] : (long)gm) : 0;
    aoff[it] = src*(long)lda + c16*8;
  }
  const u16* pb0 = Bh + (long)(col0 + rt)*ldb + c16*8;

  auto issue = [&](int c){
    uint32_t dst0 = sbase + (c&1)*STAGEB;
    int k0 = c*64;
    #pragma unroll
    for (int it=0; it<4; it++){
      uint32_t d = dst0 + doff0 + it*32*TPAD;
      int ssz = apred[it] ? 16 : 0;
      cp16(d,          Ah + aoff[it] + k0, ssz);
      cp16(d + MATB,   Al + aoff[it] + k0, ssz);
      cp16f(d + 2*MATB, pb0 + (long)it*32*ldb + k0);
    }
    CP_COMMIT();
  };

  issue(0);
  for (int c = 0; c < NC; c++){
    if (c+1 < NC){ issue(c+1); CP_WAIT(1); }
    else         { CP_WAIT(0); }
    __syncthreads();

    uint32_t st = sbase + (c&1)*STAGEB;
    #pragma unroll
    for (int ks = 0; ks < 4; ks++){
      uint32_t rowA = st + (uint32_t)((wm*64)*TPAD + ks*32) + laneA;
      uint32_t rowB = st + 2*MATB + (uint32_t)((wn*32)*TPAD + ks*32) + laneB4;
      uint32_t aH[4][4], bH[4][2];
      #pragma unroll
      for (int mf=0; mf<4; mf++) ldsm_x4(aH[mf], rowA + mf*16*TPAD);
      #pragma unroll
      for (int np=0; np<2; np++){
        uint32_t t4[4];
        ldsm_x4(t4, rowB + np*16*TPAD);
        bH[2*np][0]=t4[0]; bH[2*np][1]=t4[1];
        bH[2*np+1][0]=t4[2]; bH[2*np+1][1]=t4[3];
      }
      #pragma unroll
      for (int mf=0; mf<4; mf++)
        #pragma unroll
        for (int nf=0; nf<4; nf++) mma16816(acc[mf][nf], aH[mf], bH[nf]);
      {
        uint32_t aL[4][4];
        #pragma unroll
        for (int mf=0; mf<4; mf++) ldsm_x4(aL[mf], rowA + MATB + mf*16*TPAD);
        #pragma unroll
        for (int mf=0; mf<4; mf++)
          #pragma unroll
          for (int nf=0; nf<4; nf++) mma16816(acc[mf][nf], aL[mf], bH[nf]);
      }
    }
    __syncthreads();
  }

  // ---- epilogue ----
  int g = lane>>2, tig = lane&3;
  #pragma unroll
  for (int mf=0; mf<4; mf++){
    int ra = row0 + wm*64 + mf*16 + g;
    int rb = ra + 8;
    #pragma unroll
    for (int nf=0; nf<4; nf++){
      int col = col0 + wn*32 + nf*8 + tig*2;
      float* cacc = acc[mf][nf];
      if (EPI == 0){
        if (ra < Meff){
          float* p = C + (size_t)ra*ldc + col;
          p[0] = cacc[0]*alpha; p[1] = cacc[1]*alpha;
        }
        if (rb < Meff){
          float* p = C + (size_t)rb*ldc + col;
          p[0] = cacc[2]*alpha; p[1] = cacc[3]*alpha;
        }
      } else {
        if (ra < Meff){
          float w = aw[ra];
          float* p = C + (size_t)arow[ra]*ldc + col;
          atomicAdd(p,   w*cacc[0]*alpha);
          atomicAdd(p+1, w*cacc[1]*alpha);
        }
        if (rb < Meff){
          float w = aw[rb];
          float* p = C + (size_t)arow[rb]*ldc + col;
          atomicAdd(p,   w*cacc[2]*alpha);
          atomicAdd(p+1, w*cacc[3]*alpha);
        }
      }
    }
  }
}

// ---------------- reduction helpers ----------------
__device__ __forceinline__ float warp_sum(float v){
  #pragma unroll
  for(int o=16;o;o>>=1) v += __shfl_xor_sync(0xffffffffu, v, o);
  return v;
}
__device__ __forceinline__ float warp_max(float v){
  #pragma unroll
  for(int o=16;o;o>>=1) v = fmaxf(v, __shfl_xor_sync(0xffffffffu, v, o));
  return v;
}

// ---------------- LayerNorm ----------------
__global__ void ln_kernel(const float* __restrict__ x, const float* __restrict__ w,
                          float* __restrict__ y, u16* __restrict__ yh, u16* __restrict__ yl){
  int row = blockIdx.x;
  const float* xr = x + (size_t)row*TD;
  float s=0.f, s2=0.f;
  for(int d=threadIdx.x; d<TD; d+=blockDim.x){ float v=xr[d]; s+=v; s2+=v*v; }
  __shared__ float shs[8], shs2[8];
  int lane=threadIdx.x&31, wp=threadIdx.x>>5;
  s = warp_sum(s); s2 = warp_sum(s2);
  if(!lane){ shs[wp]=s; shs2[wp]=s2; }
  __syncthreads();
  if (threadIdx.x < 32){
    float a = (threadIdx.x<8)? shs[threadIdx.x] : 0.f;
    float b = (threadIdx.x<8)? shs2[threadIdx.x] : 0.f;
    a = warp_sum(a); b = warp_sum(b);
    if(!threadIdx.x){ shs[0]=a; shs2[0]=b; }
  }
  __syncthreads();
  float mu = shs[0]*(1.f/TD);
  float var = shs2[0]*(1.f/TD) - mu*mu;
  float rstd = rsqrtf(var + 1e-5f);
  for(int d=threadIdx.x; d<TD; d+=blockDim.x){
    float v = (xr[d]-mu)*rstd*w[d];
    y[(size_t)row*TD + d] = v;
    u16 h = h16(v);
    yh[(size_t)row*TD + d] = h;
    yl[(size_t)row*TD + d] = h16(v - h2f(h));
  }
}

// ---------------- RoPE ----------------
__global__ void rope_kernel(const float* __restrict__ qkv,
                            const float* __restrict__ cosb,
                            const float* __restrict__ sinb,
                            u16* __restrict__ qh, u16* __restrict__ ql){
  int idx = blockIdx.x*blockDim.x + threadIdx.x;
  const int total = TT*(TH+TKV)*(THD/2);
  if (idx >= total) return;
  int i  = idx & 63;
  int rest = idx >> 6;
  int hh = rest % (TH+TKV);
  int t  = rest / (TH+TKV);
  int s  = t % TS_;
  float c  = cosb[s*THD + i];
  float sn = sinb[s*THD + i];
  const float* p = qkv + (size_t)t*OQKV + hh*THD;
  float x1 = p[i], x2 = p[i+64];
  float r1 = x1*c - x2*sn;
  float r2 = x2*c + x1*sn;
  size_t o = (size_t)t*OQKV + hh*THD;
  u16 h1 = h16(r1), h2 = h16(r2);
  qh[o+i] = h1;    ql[o+i]    = h16(r1 - h2f(h1));
  qh[o+i+64] = h2; ql[o+i+64] = h16(r2 - h2f(h2));
}

// ---------------- causal softmax -> fp16 split P ----------------
__global__ void softmax_kernel(const float* __restrict__ s,
                               u16* __restrict__ ph, u16* __restrict__ pl){
  int row = blockIdx.x;
  int q = row % TS_;
  int L = q + 1;
  int pad = ((q>>7)+1)<<7;
  const float* r = s + (size_t)row*TS_;
  u16* oh = ph + (size_t)row*TS_;
  u16* ol = pl + (size_t)row*TS_;
  int tid = threadIdx.x;
  int lane = tid&31, wp = tid>>5;
  __shared__ float sh[8];

  float mx = -1e30f;
  for(int d=tid; d<L; d+=256) mx = fmaxf(mx, r[d]);
  mx = warp_max(mx);
  if(!lane) sh[wp]=mx;
  __syncthreads();
  if (tid<32){ float v=(tid<8)?sh[tid]:-1e30f; v=warp_max(v); if(!tid) sh[0]=v; }
  __syncthreads();
  mx = sh[0];
  __syncthreads();

  float sum = 0.f;
  for(int d=tid; d<L; d+=256) sum += __expf(r[d]-mx);
  sum = warp_sum(sum);
  if(!lane) sh[wp]=sum;
  __syncthreads();
  if (tid<32){ float v=(tid<8)?sh[tid]:0.f; v=warp_sum(v); if(!tid) sh[0]=v; }
  __syncthreads();
  float inv = 1.f/sh[0];

  for(int d=tid; d<L; d+=256){
    float p = __expf(r[d]-mx)*inv;
    u16 h = h16(p);
    oh[d] = h;
    ol[d] = h16(p - h2f(h));
  }
  for(int d=L+tid; d<pad; d+=256){ oh[d]=0; ol[d]=0; }
}

// ---------------- elementwise ----------------
__global__ void add_kernel(const float* __restrict__ a, const float* __restrict__ b,
                           float* __restrict__ c, int n){
  int i = blockIdx.x*blockDim.x + threadIdx.x;
  if (i<n) c[i]=a[i]+b[i];
}
__global__ void zero_kernel(float* __restrict__ p, int n){
  int i = blockIdx.x*blockDim.x + threadIdx.x;
  if (i<n) p[i]=0.f;
}
__global__ void zero_cnt_kernel(){
  if (threadIdx.x < TE) g_ecnt[threadIdx.x]=0;
}
// expert-batched silu*up -> fp16 split
__global__ void silu_mul_kernel(u16* __restrict__ gh, u16* __restrict__ gl){
  int z = blockIdx.z;
  int n = g_ecnt[z]*TF;
  int i = blockIdx.x*blockDim.x + threadIdx.x;
  if (i>=n) return;
  int m = i/TF, f = i%TF;
  const float* gu = g_GU + (size_t)z*TT*2*TF + (size_t)m*(2*TF);
  float g = gu[f], u = gu[TF+f];
  float y = (g/(1.f+__expf(-g)))*u;
  size_t o = (size_t)z*TT*TF + i;
  u16 h = h16(y);
  gh[o] = h;
  gl[o] = h16(y - h2f(h));
}

// ---------------- router ----------------
__global__ void router_kernel(const float* __restrict__ x, const float* __restrict__ wr){
  int t = blockIdx.x;
  int tid = threadIdx.x;
  const float* xr = x + (size_t)t*TD;
  float acc[TE];
  #pragma unroll
  for(int e=0;e<TE;e++) acc[e]=0.f;
  for(int d=tid; d<TD; d+=128){
    float xv = xr[d];
    #pragma unroll
    for(int e=0;e<TE;e++) acc[e] += xv*wr[e*TD+d];
  }
  __shared__ float sh[TE][4];
  int lane=tid&31, wp=tid>>5;
  #pragma unroll
  for(int e=0;e<TE;e++){
    float v = warp_sum(acc[e]);
    if(!lane) sh[e][wp]=v;
  }
  __syncthreads();
  if (tid==0){
    float lg[TE];
    float mx=-1e30f;
    #pragma unroll
    for(int e=0;e<TE;e++){ lg[e]=sh[e][0]+sh[e][1]+sh[e][2]+sh[e][3]; mx=fmaxf(mx,lg[e]); }
    float p[TE]; float s=0.f;
    #pragma unroll
    for(int e=0;e<TE;e++){ p[e]=expf(lg[e]-mx); s+=p[e]; }
    float inv=1.f/s;
    #pragma unroll
    for(int e=0;e<TE;e++) p[e]*=inv;
    int e0=0;
    #pragma unroll
    for(int e=1;e<TE;e++) if (p[e]>p[e0]) e0=e;
    int e1=-1;
    #pragma unroll
    for(int e=0;e<TE;e++){ if(e==e0) continue; if (e1<0 || p[e]>p[e1]) e1=e; }
    float w0=p[e0], w1=p[e1];
    float tot = w0+w1;
    w0/=tot; w1/=tot;
    int pos = atomicAdd(&g_ecnt[e0],1);
    g_elist[e0*TT+pos]=t; g_ew[e0*TT+pos]=w0;
    pos = atomicAdd(&g_ecnt[e1],1);
    g_elist[e1*TT+pos]=t; g_ew[e1*TT+pos]=w1;
  }
}

// ---------------- launcher ----------------
extern "C" void kernel_launch(void* const* d_in, const int* in_sizes, int n_in,
                              void* d_out, int out_size){
  const float* hidden  = (const float*)d_in[0];
  const float* cosb    = (const float*)d_in[1];
  const float* sinb    = (const float*)d_in[2];
  const float* ln1w    = (const float*)d_in[3];
  const float* ln2w    = (const float*)d_in[4];
  const float* wqkv    = (const float*)d_in[5];
  const float* wout    = (const float*)d_in[6];
  const float* wrouter = (const float*)d_in[7];
  const float* wgate   = (const float*)d_in[8];
  const float* wup     = (const float*)d_in[9];
  const float* wdown   = (const float*)d_in[10];
  float* out = (float*)d_out;

  float *p_h,*p_qkv,*p_scores,*p_attn,*p_res,*p_GU,*p_ew;
  int *p_elist,*p_ecnt;
  u16 *p_wqkv,*p_wout,*p_wgu,*p_wd;
  u16 *p_xh,*p_xl,*p_ah,*p_al,*p_gh,*p_gl,*p_qh,*p_ql,*p_ph,*p_pl,*p_vt;
  cudaGetSymbolAddress((void**)&p_h, g_h);
  cudaGetSymbolAddress((void**)&p_qkv, g_qkv);
  cudaGetSymbolAddress((void**)&p_scores, g_scores);
  cudaGetSymbolAddress((void**)&p_attn, g_attn);
  cudaGetSymbolAddress((void**)&p_res, g_res);
  cudaGetSymbolAddress((void**)&p_GU, g_GU);
  cudaGetSymbolAddress((void**)&p_ew, g_ew);
  cudaGetSymbolAddress((void**)&p_elist, g_elist);
  cudaGetSymbolAddress((void**)&p_ecnt, g_ecnt);
  cudaGetSymbolAddress((void**)&p_wqkv, g_wqkv_h);
  cudaGetSymbolAddress((void**)&p_wout, g_wout_h);
  cudaGetSymbolAddress((void**)&p_wgu, g_wgu_h);
  cudaGetSymbolAddress((void**)&p_wd, g_wd_h);
  cudaGetSymbolAddress((void**)&p_xh, g_xh);
  cudaGetSymbolAddress((void**)&p_xl, g_xl);
  cudaGetSymbolAddress((void**)&p_ah, g_ah);
  cudaGetSymbolAddress((void**)&p_al, g_al);
  cudaGetSymbolAddress((void**)&p_gh, g_gh);
  cudaGetSymbolAddress((void**)&p_gl, g_gl);
  cudaGetSymbolAddress((void**)&p_qh, g_qh);
  cudaGetSymbolAddress((void**)&p_ql, g_ql);
  cudaGetSymbolAddress((void**)&p_ph, g_ph);
  cudaGetSymbolAddress((void**)&p_pl, g_pl);
  cudaGetSymbolAddress((void**)&p_vt, g_vt);

  cudaFuncSetAttribute(tgemm<0,false,0>, cudaFuncAttributeMaxDynamicSharedMemorySize, TG_SMEM);
  cudaFuncSetAttribute(tgemm<0,false,1>, cudaFuncAttributeMaxDynamicSharedMemorySize, TG_SMEM);
  cudaFuncSetAttribute(tgemm<0,false,2>, cudaFuncAttributeMaxDynamicSharedMemorySize, TG_SMEM);
  cudaFuncSetAttribute(tgemm<0,true,3>,  cudaFuncAttributeMaxDynamicSharedMemorySize, TG_SMEM);
  cudaFuncSetAttribute(tgemm<3,false,4>, cudaFuncAttributeMaxDynamicSharedMemorySize, TG_SMEM);

  const int n_td = TT*TD;
  float* resid = (out_size >= 2*n_td) ? (out + (size_t)n_td) : p_res;

  // 0. weight conversion
  convhalf<<<(OQKV*TD/4+255)/256,256>>>(wqkv, p_wqkv, OQKV*TD/4);
  convhalf<<<(TD*TD/4+255)/256,256>>>(wout, p_wout, TD*TD/4);
  transhalf<<<dim3(TF/32, TD/32, TE), dim3(32,8)>>>(wgate, p_wgu, TD, TF,
      (size_t)TD*TF, (size_t)2*TF*TD);
  transhalf<<<dim3(TF/32, TD/32, TE), dim3(32,8)>>>(wup, p_wgu + (size_t)TF*TD, TD, TF,
      (size_t)TD*TF, (size_t)2*TF*TD);
  transhalf<<<dim3(TD/32, TF/32, TE), dim3(32,8)>>>(wdown, p_wd, TF, TD,
      (size_t)TF*TD, (size_t)TD*TF);

  // 1. LN1
  ln_kernel<<<TT,256>>>(hidden, ln1w, p_h, p_xh, p_xl);

  // 2. QKV
  tgemm<0,false,0><<<dim3(OQKV/128, TT/128), 256, TG_SMEM>>>(
      TT, OQKV, TD, p_xh, p_xl, TD, p_wqkv, TD,
      p_qkv, OQKV, 1.f, nullptr, nullptr, nullptr, 0,0,0);

  // 3. RoPE + V^T
  {
    int total = TT*(TH+TKV)*(THD/2);
    rope_kernel<<<(total+255)/256,256>>>(p_qkv, cosb, sinb, p_qh, p_ql);
  }
  vtrans<<<dim3(TS_/32, THD/32, TBATCH*TKV), dim3(32,8)>>>(p_qkv, p_vt);

  // 4. scores (tensor, causal tile-skip)
  tgemm<0,false,1><<<dim3(TS_/128, TS_/128, TBATCH*TH), 256, TG_SMEM>>>(
      TS_, TS_, THD, p_qh, p_ql, 0, p_qh, 0,
      p_scores, 0, 1.f/sqrtf((float)THD), nullptr, nullptr, nullptr, 0,0,0);

  // 5. softmax -> P fp16 split
  softmax_kernel<<<TBATCH*TH*TS_,256>>>(p_scores, p_ph, p_pl);

  // 6. PV (tensor, K-truncated)
  tgemm<0,false,2><<<dim3(1, TS_/128, TBATCH*TH), 256, TG_SMEM>>>(
      TS_, THD, TS_, p_ph, p_pl, 0, p_vt, 0,
      p_attn, 0, 1.f, nullptr, nullptr, nullptr, 0,0,0);

  // 6b. attn split
  convsplit<<<(n_td/4+255)/256,256>>>(p_attn, p_ah, p_al, n_td/4);

  // 7. out-proj -> g_qkv
  tgemm<0,false,0><<<dim3(TD/128, TT/128), 256, TG_SMEM>>>(
      TT, TD, TH*THD, p_ah, p_al, TH*THD, p_wout, TH*THD,
      p_qkv, TD, 1.f, nullptr, nullptr, nullptr, 0,0,0);

  // 8. residual
  add_kernel<<<(n_td+255)/256,256>>>(p_qkv, hidden, resid, n_td);

  // 9. LN2
  ln_kernel<<<TT,256>>>(resid, ln2w, p_h, p_xh, p_xl);

  // 10. zero + router
  zero_kernel<<<(n_td+255)/256,256>>>(out, n_td);
  zero_cnt_kernel<<<1,32>>>();
  router_kernel<<<TT,128>>>(p_h, wrouter);

  // 11. MoE: expert-batched GU GEMM, silu, down (atomic scatter)
  tgemm<0,true,3><<<dim3(2*TF/128, TT/128, TE), 256, TG_SMEM>>>(
      TT, 2*TF, TD, p_xh, p_xl, TD, p_wgu, TD,
      p_GU, 2*TF, 1.f, p_elist, nullptr, p_ecnt,
      0, (size_t)2*TF*TD, (size_t)TT*2*TF);
  silu_mul_kernel<<<dim3((TT*TF+255)/256, 1, TE), 256>>>(p_gh, p_gl);
  tgemm<3,false,4><<<dim3(TD/128, TT/128, TE), 256, TG_SMEM>>>(
      TT, TD, TF, p_gh, p_gl, TF, p_wd, TF,
      out, TD, 1.f, p_elist, p_ew, p_ecnt,
      (size_t)TT*TF, (size_t)TD*TF, 0);

  if (resid == p_res && out_size >= 2*n_td){
    add_kernel<<<(n_td+255)/256,256>>>(p_qkv, hidden, out + (size_t)n_td, n_td);
  }
}

// round 8
// speedup vs baseline: 10.5701x; 1.2370x over previous
#include <cuda_runtime.h>
#include <cuda_fp16.h>
#include <math.h>
#include <stdint.h>

// Problem constants
#define TS_ 1024
#define TBATCH 2
#define TD 2048
#define TH 16
#define TKV 4
#define THD 128
#define TE 8
#define TF 2048
#define TT (TBATCH*TS_)            // 2048 tokens
#define OQKV ((TH+2*TKV)*THD)      // 3072
#define REP (TH/TKV)               // 4

typedef unsigned short u16;

// ---------------- scratch (device globals) ----------
__device__ float g_h[(size_t)TT*TD];
__device__ float g_qkv[(size_t)TT*OQKV];
__device__ float g_scores[(size_t)TBATCH*TH*TS_*TS_];
__device__ float g_attn[(size_t)TT*TH*THD];
__device__ float g_res[(size_t)TT*TD];
__device__ float g_GU[(size_t)TE*TT*2*TF];
__device__ int   g_elist[TE*TT];
__device__ float g_ew[TE*TT];
__device__ int   g_ecnt[TE];

// fp16 buffers
__device__ u16 g_wqkv_h[(size_t)OQKV*TD];
__device__ u16 g_wout_h[(size_t)TD*TD];
__device__ u16 g_wgu_h[(size_t)TE*2*TF*TD];    // [e][2F][D]
__device__ u16 g_wd_h[(size_t)TE*TD*TF];       // [e][D][F]
__device__ u16 g_xh[(size_t)TT*TD],  g_xl[(size_t)TT*TD];
__device__ u16 g_ah[(size_t)TT*TD],  g_al[(size_t)TT*TD];
__device__ u16 g_gh[(size_t)TE*TT*TF];
__device__ u16 g_qh[(size_t)TT*OQKV], g_ql[(size_t)TT*OQKV];
__device__ u16 g_ph[(size_t)TBATCH*TH*TS_*TS_], g_pl[(size_t)TBATCH*TH*TS_*TS_];
__device__ u16 g_vt[(size_t)TBATCH*TKV*THD*TS_];

// ---------------- helpers ----------------
__device__ __forceinline__ u16 h16(float x){
  __half h = __float2half_rn(x);
  return *reinterpret_cast<u16*>(&h);
}
__device__ __forceinline__ float h2f(u16 b){
  __half h = *reinterpret_cast<__half*>(&b);
  return __half2float(h);
}
__device__ __forceinline__ uint32_t smem_u32(const void* p){
  uint32_t a;
  asm("{ .reg .u64 t; cvta.to.shared.u64 t, %1; cvt.u32.u64 %0, t; }" : "=r"(a) : "l"(p));
  return a;
}
__device__ __forceinline__ void ldsm_x4(uint32_t* r, uint32_t addr){
  asm volatile("ldmatrix.sync.aligned.m8n8.x4.shared.b16 {%0,%1,%2,%3}, [%4];"
    : "=r"(r[0]),"=r"(r[1]),"=r"(r[2]),"=r"(r[3]) : "r"(addr));
}
__device__ __forceinline__ void mma16816(float* c, const uint32_t* a, const uint32_t* b){
  asm volatile("mma.sync.aligned.m16n8k16.row.col.f32.f16.f16.f32 "
    "{%0,%1,%2,%3}, {%4,%5,%6,%7}, {%8,%9}, {%0,%1,%2,%3};"
    : "+f"(c[0]),"+f"(c[1]),"+f"(c[2]),"+f"(c[3])
    : "r"(a[0]),"r"(a[1]),"r"(a[2]),"r"(a[3]), "r"(b[0]),"r"(b[1]));
}
__device__ __forceinline__ void cp16(uint32_t dst, const void* src, int ssz){
  asm volatile("cp.async.cg.shared.global [%0], [%1], 16, %2;"
    :: "r"(dst), "l"(src), "r"(ssz) : "memory");
}
__device__ __forceinline__ void cp16f(uint32_t dst, const void* src){
  asm volatile("cp.async.cg.shared.global [%0], [%1], 16;"
    :: "r"(dst), "l"(src) : "memory");
}
#define CP_COMMIT() asm volatile("cp.async.commit_group;":::"memory")
#define CP_WAIT(n)  asm volatile("cp.async.wait_group %0;"::"n"(n):"memory")

// ---------------- conversion kernels ----------------
__global__ void convhalf(const float* __restrict__ src, u16* __restrict__ d, int n4){
  int i = blockIdx.x*blockDim.x + threadIdx.x;
  if (i >= n4) return;
  float4 v = reinterpret_cast<const float4*>(src)[i];
  ushort4 hv; hv.x=h16(v.x); hv.y=h16(v.y); hv.z=h16(v.z); hv.w=h16(v.w);
  reinterpret_cast<ushort4*>(d)[i]=hv;
}
__global__ void convsplit(const float* __restrict__ src, u16* __restrict__ h,
                          u16* __restrict__ l, int n4){
  int i = blockIdx.x*blockDim.x + threadIdx.x;
  if (i >= n4) return;
  float4 v = reinterpret_cast<const float4*>(src)[i];
  ushort4 hv, lv;
  hv.x=h16(v.x); hv.y=h16(v.y); hv.z=h16(v.z); hv.w=h16(v.w);
  lv.x=h16(v.x-h2f(hv.x)); lv.y=h16(v.y-h2f(hv.y));
  lv.z=h16(v.z-h2f(hv.z)); lv.w=h16(v.w-h2f(hv.w));
  reinterpret_cast<ushort4*>(h)[i]=hv;
  reinterpret_cast<ushort4*>(l)[i]=lv;
}
__global__ void transhalf(const float* __restrict__ src, u16* __restrict__ dst,
                          int R, int C, size_t sstr, size_t dstr){
  __shared__ float t[32][33];
  src += (size_t)blockIdx.z * sstr;
  dst += (size_t)blockIdx.z * dstr;
  int c0 = blockIdx.x*32, r0 = blockIdx.y*32;
  int tx = threadIdx.x, ty = threadIdx.y;
  #pragma unroll
  for (int j=0;j<4;j++)
    t[ty+j*8][tx] = src[(size_t)(r0+ty+j*8)*C + c0+tx];
  __syncthreads();
  #pragma unroll
  for (int j=0;j<4;j++)
    dst[(size_t)(c0+ty+j*8)*R + r0+tx] = h16(t[tx][ty+j*8]);
}
__global__ void vtrans(const float* __restrict__ qkv, u16* __restrict__ vt){
  __shared__ float t[32][33];
  int z = blockIdx.z; int b = z/TKV, kv = z%TKV;
  int s0 = blockIdx.x*32, h0 = blockIdx.y*32;
  int tx = threadIdx.x, ty = threadIdx.y;
  #pragma unroll
  for (int j=0;j<4;j++){
    int s = s0+ty+j*8;
    t[ty+j*8][tx] = qkv[(size_t)(b*TS_+s)*OQKV + (TH+TKV+kv)*THD + h0+tx];
  }
  __syncthreads();
  #pragma unroll
  for (int j=0;j<4;j++){
    int hd = h0+ty+j*8;
    vt[((size_t)z*THD + hd)*TS_ + s0+tx] = h16(t[tx][ty+j*8]);
  }
}

// ---------------- tensor-core GEMM (fp16, optional A hi/lo split) ----------
// C[M,N] = alpha * (Ah[+Al])[M,K] @ Bh[N,K]^T     BK=64, 2-stage cp.async
// EPI 0: store. EPI 3: atomicAdd C[arow[m]] += aw[m]*v.
// ADDR 0: plain. 1: attn scores. 2: PV. 3: expert-batched gather-store.
// 4: expert-batched (A per-expert) atomic scatter.
#define TPAD 144
#define MATB (128*TPAD)   // 18432

template<int EPI, bool GATHER, int ADDR, bool ASPLIT>
__global__ __launch_bounds__(256,2) void tgemm(
    int M, int N, int K,
    const u16* __restrict__ Ah, const u16* __restrict__ Al, int lda,
    const u16* __restrict__ Bh, int ldb,
    float* __restrict__ C, int ldc, float alpha,
    const int* __restrict__ arow, const float* __restrict__ aw,
    const int* __restrict__ cntp,
    size_t astride, size_t bstride, size_t cstride)
{
  constexpr int NMAT = ASPLIT ? 3 : 2;
  constexpr int STB  = NMAT*MATB;
  constexpr int BOFF = (ASPLIT ? 2 : 1)*MATB;
  extern __shared__ __align__(16) char smem[];
  int row0 = blockIdx.y*128, col0 = blockIdx.x*128;
  int Klim = K;

  if (ADDR==1){
    if (col0 > row0 + 127) return;
    int z = blockIdx.z, b = z/TH, h = z%TH;
    size_t off = (size_t)b*TS_*OQKV + h*THD;
    Ah += off; if (ASPLIT) Al += off;
    lda = OQKV;
    Bh += (size_t)b*TS_*OQKV + (TH + h/REP)*THD;
    ldb = OQKV;
    C  += (size_t)z*TS_*TS_;
    ldc = TS_;
  } else if (ADDR==2){
    int z = blockIdx.z, b = z/TH, h = z%TH;
    size_t off = (size_t)z*TS_*TS_;
    Ah += off; if (ASPLIT) Al += off;
    lda = TS_;
    Bh += ((size_t)(b*TKV + h/REP))*THD*TS_;
    ldb = TS_;
    C  += (size_t)b*TS_*(TH*THD) + h*THD;
    ldc = TH*THD;
    Klim = min(K, row0 + 128);
  } else if (ADDR==3 || ADDR==4){
    int z = blockIdx.z;
    arow += z*TT;
    if (ADDR==4){ aw += z*TT; Ah += (size_t)z*astride; }
    cntp += z;
    Bh += (size_t)z*bstride;
    C  += (size_t)z*cstride;
  }

  int Meff = cntp ? *cntp : M;
  if (row0 >= Meff) return;

  int tid = threadIdx.x, wid = tid>>5, lane = tid&31;
  int wm = wid>>2, wn = wid&3;
  uint32_t sbase = smem_u32(smem);

  uint32_t laneA  = (uint32_t)((lane&15)*TPAD) + (uint32_t)((lane>>4)*16);
  uint32_t laneB4 = (uint32_t)((lane&7)*TPAD) + (uint32_t)(((lane>>3)&1)*16)
                  + (uint32_t)((lane>>4)*(8*TPAD));

  float acc[4][4][4];
  #pragma unroll
  for(int i=0;i<4;i++)
    #pragma unroll
    for(int j=0;j<4;j++)
      #pragma unroll
      for(int q=0;q<4;q++) acc[i][j][q]=0.f;

  const int NC = Klim/64;

  int c16 = tid&7, rt = tid>>3;     // rt 0..31
  uint32_t doff0 = (uint32_t)(rt*TPAD + c16*16);
  long aoff[4]; int apred[4];
  #pragma unroll
  for (int it=0; it<4; it++){
    int gm = row0 + rt + it*32;
    apred[it] = gm < Meff;
    long src = apred[it] ? ((GATHER||ADDR==3) ? (long)arow[gm] : (long)gm) : 0;
    aoff[it] = src*(long)lda + c16*8;
  }
  const u16* pb0 = Bh + (long)(col0 + rt)*ldb + c16*8;

  auto issue = [&](int c){
    uint32_t dst0 = sbase + (c&1)*STB;
    int k0 = c*64;
    #pragma unroll
    for (int it=0; it<4; it++){
      uint32_t d = dst0 + doff0 + it*32*TPAD;
      int ssz = apred[it] ? 16 : 0;
      cp16(d, Ah + aoff[it] + k0, ssz);
      if (ASPLIT) cp16(d + MATB, Al + aoff[it] + k0, ssz);
      cp16f(d + BOFF, pb0 + (long)it*32*ldb + k0);
    }
    CP_COMMIT();
  };

  issue(0);
  for (int c = 0; c < NC; c++){
    if (c+1 < NC){ issue(c+1); CP_WAIT(1); }
    else         { CP_WAIT(0); }
    __syncthreads();

    uint32_t st = sbase + (c&1)*STB;
    #pragma unroll
    for (int ks = 0; ks < 4; ks++){
      uint32_t rowA = st + (uint32_t)((wm*64)*TPAD + ks*32) + laneA;
      uint32_t rowB = st + BOFF + (uint32_t)((wn*32)*TPAD + ks*32) + laneB4;
      uint32_t aH[4][4], bH[4][2];
      #pragma unroll
      for (int mf=0; mf<4; mf++) ldsm_x4(aH[mf], rowA + mf*16*TPAD);
      #pragma unroll
      for (int np=0; np<2; np++){
        uint32_t t4[4];
        ldsm_x4(t4, rowB + np*16*TPAD);
        bH[2*np][0]=t4[0]; bH[2*np][1]=t4[1];
        bH[2*np+1][0]=t4[2]; bH[2*np+1][1]=t4[3];
      }
      #pragma unroll
      for (int mf=0; mf<4; mf++)
        #pragma unroll
        for (int nf=0; nf<4; nf++) mma16816(acc[mf][nf], aH[mf], bH[nf]);
      if (ASPLIT){
        uint32_t aL[4][4];
        #pragma unroll
        for (int mf=0; mf<4; mf++) ldsm_x4(aL[mf], rowA + MATB + mf*16*TPAD);
        #pragma unroll
        for (int mf=0; mf<4; mf++)
          #pragma unroll
          for (int nf=0; nf<4; nf++) mma16816(acc[mf][nf], aL[mf], bH[nf]);
      }
    }
    __syncthreads();
  }

  // ---- epilogue ----
  int g = lane>>2, tig = lane&3;
  #pragma unroll
  for (int mf=0; mf<4; mf++){
    int ra = row0 + wm*64 + mf*16 + g;
    int rb = ra + 8;
    #pragma unroll
    for (int nf=0; nf<4; nf++){
      int col = col0 + wn*32 + nf*8 + tig*2;
      float* cacc = acc[mf][nf];
      if (EPI == 0){
        if (ra < Meff){
          float* p = C + (size_t)ra*ldc + col;
          p[0] = cacc[0]*alpha; p[1] = cacc[1]*alpha;
        }
        if (rb < Meff){
          float* p = C + (size_t)rb*ldc + col;
          p[0] = cacc[2]*alpha; p[1] = cacc[3]*alpha;
        }
      } else {
        if (ra < Meff){
          float w = aw[ra];
          float* p = C + (size_t)arow[ra]*ldc + col;
          atomicAdd(p,   w*cacc[0]*alpha);
          atomicAdd(p+1, w*cacc[1]*alpha);
        }
        if (rb < Meff){
          float w = aw[rb];
          float* p = C + (size_t)arow[rb]*ldc + col;
          atomicAdd(p,   w*cacc[2]*alpha);
          atomicAdd(p+1, w*cacc[3]*alpha);
        }
      }
    }
  }
}

// ---------------- reduction helpers ----------------
__device__ __forceinline__ float warp_sum(float v){
  #pragma unroll
  for(int o=16;o;o>>=1) v += __shfl_xor_sync(0xffffffffu, v, o);
  return v;
}
__device__ __forceinline__ float warp_max(float v){
  #pragma unroll
  for(int o=16;o;o>>=1) v = fmaxf(v, __shfl_xor_sync(0xffffffffu, v, o));
  return v;
}

// ---------------- LayerNorm (fp32 + fp16 hi/lo) ----------------
__global__ void ln_kernel(const float* __restrict__ x, const float* __restrict__ w,
                          float* __restrict__ y, u16* __restrict__ yh, u16* __restrict__ yl){
  int row = blockIdx.x;
  const float* xr = x + (size_t)row*TD;
  float s=0.f, s2=0.f;
  for(int d=threadIdx.x; d<TD; d+=blockDim.x){ float v=xr[d]; s+=v; s2+=v*v; }
  __shared__ float shs[8], shs2[8];
  int lane=threadIdx.x&31, wp=threadIdx.x>>5;
  s = warp_sum(s); s2 = warp_sum(s2);
  if(!lane){ shs[wp]=s; shs2[wp]=s2; }
  __syncthreads();
  if (threadIdx.x < 32){
    float a = (threadIdx.x<8)? shs[threadIdx.x] : 0.f;
    float b = (threadIdx.x<8)? shs2[threadIdx.x] : 0.f;
    a = warp_sum(a); b = warp_sum(b);
    if(!threadIdx.x){ shs[0]=a; shs2[0]=b; }
  }
  __syncthreads();
  float mu = shs[0]*(1.f/TD);
  float var = shs2[0]*(1.f/TD) - mu*mu;
  float rstd = rsqrtf(var + 1e-5f);
  for(int d=threadIdx.x; d<TD; d+=blockDim.x){
    float v = (xr[d]-mu)*rstd*w[d];
    y[(size_t)row*TD + d] = v;
    u16 h = h16(v);
    yh[(size_t)row*TD + d] = h;
    yl[(size_t)row*TD + d] = h16(v - h2f(h));
  }
}

// ---------------- RoPE -> fp16 split ----------------
__global__ void rope_kernel(const float* __restrict__ qkv,
                            const float* __restrict__ cosb,
                            const float* __restrict__ sinb,
                            u16* __restrict__ qh, u16* __restrict__ ql){
  int idx = blockIdx.x*blockDim.x + threadIdx.x;
  const int total = TT*(TH+TKV)*(THD/2);
  if (idx >= total) return;
  int i  = idx & 63;
  int rest = idx >> 6;
  int hh = rest % (TH+TKV);
  int t  = rest / (TH+TKV);
  int s  = t % TS_;
  float c  = cosb[s*THD + i];
  float sn = sinb[s*THD + i];
  const float* p = qkv + (size_t)t*OQKV + hh*THD;
  float x1 = p[i], x2 = p[i+64];
  float r1 = x1*c - x2*sn;
  float r2 = x2*c + x1*sn;
  size_t o = (size_t)t*OQKV + hh*THD;
  u16 h1 = h16(r1), h2 = h16(r2);
  qh[o+i] = h1;    ql[o+i]    = h16(r1 - h2f(h1));
  qh[o+i+64] = h2; ql[o+i+64] = h16(r2 - h2f(h2));
}

// ---------------- causal softmax -> fp16 split P ----------------
__global__ void softmax_kernel(const float* __restrict__ s,
                               u16* __restrict__ ph, u16* __restrict__ pl){
  int row = blockIdx.x;
  int q = row % TS_;
  int L = q + 1;
  int pad = ((q>>7)+1)<<7;
  const float* r = s + (size_t)row*TS_;
  u16* oh = ph + (size_t)row*TS_;
  u16* ol = pl + (size_t)row*TS_;
  int tid = threadIdx.x;
  int lane = tid&31, wp = tid>>5;
  __shared__ float sh[8];

  float mx = -1e30f;
  for(int d=tid; d<L; d+=256) mx = fmaxf(mx, r[d]);
  mx = warp_max(mx);
  if(!lane) sh[wp]=mx;
  __syncthreads();
  if (tid<32){ float v=(tid<8)?sh[tid]:-1e30f; v=warp_max(v); if(!tid) sh[0]=v; }
  __syncthreads();
  mx = sh[0];
  __syncthreads();

  float sum = 0.f;
  for(int d=tid; d<L; d+=256) sum += __expf(r[d]-mx);
  sum = warp_sum(sum);
  if(!lane) sh[wp]=sum;
  __syncthreads();
  if (tid<32){ float v=(tid<8)?sh[tid]:0.f; v=warp_sum(v); if(!tid) sh[0]=v; }
  __syncthreads();
  float inv = 1.f/sh[0];

  for(int d=tid; d<L; d+=256){
    float p = __expf(r[d]-mx)*inv;
    u16 h = h16(p);
    oh[d] = h;
    ol[d] = h16(p - h2f(h));
  }
  for(int d=L+tid; d<pad; d+=256){ oh[d]=0; ol[d]=0; }
}

// ---------------- elementwise ----------------
__global__ void add_kernel(const float* __restrict__ a, const float* __restrict__ b,
                           float* __restrict__ c, int n){
  int i = blockIdx.x*blockDim.x + threadIdx.x;
  if (i<n) c[i]=a[i]+b[i];
}
__global__ void zero_kernel(float* __restrict__ p, int n){
  int i = blockIdx.x*blockDim.x + threadIdx.x;
  if (i<n) p[i]=0.f;
}
__global__ void zero_cnt_kernel(){
  if (threadIdx.x < TE) g_ecnt[threadIdx.x]=0;
}
// expert-batched silu*up -> fp16 (single)
__global__ void silu_mul_kernel(u16* __restrict__ gh){
  int z = blockIdx.z;
  int n = g_ecnt[z]*TF;
  int i = blockIdx.x*blockDim.x + threadIdx.x;
  if (i>=n) return;
  int m = i/TF, f = i%TF;
  const float* gu = g_GU + (size_t)z*TT*2*TF + (size_t)m*(2*TF);
  float g = gu[f], u = gu[TF+f];
  float y = (g/(1.f+__expf(-g)))*u;
  gh[(size_t)z*TT*TF + i] = h16(y);
}

// ---------------- router ----------------
__global__ void router_kernel(const float* __restrict__ x, const float* __restrict__ wr){
  int t = blockIdx.x;
  int tid = threadIdx.x;
  const float* xr = x + (size_t)t*TD;
  float acc[TE];
  #pragma unroll
  for(int e=0;e<TE;e++) acc[e]=0.f;
  for(int d=tid; d<TD; d+=128){
    float xv = xr[d];
    #pragma unroll
    for(int e=0;e<TE;e++) acc[e] += xv*wr[e*TD+d];
  }
  __shared__ float sh[TE][4];
  int lane=tid&31, wp=tid>>5;
  #pragma unroll
  for(int e=0;e<TE;e++){
    float v = warp_sum(acc[e]);
    if(!lane) sh[e][wp]=v;
  }
  __syncthreads();
  if (tid==0){
    float lg[TE];
    float mx=-1e30f;
    #pragma unroll
    for(int e=0;e<TE;e++){ lg[e]=sh[e][0]+sh[e][1]+sh[e][2]+sh[e][3]; mx=fmaxf(mx,lg[e]); }
    float p[TE]; float s=0.f;
    #pragma unroll
    for(int e=0;e<TE;e++){ p[e]=expf(lg[e]-mx); s+=p[e]; }
    float inv=1.f/s;
    #pragma unroll
    for(int e=0;e<TE;e++) p[e]*=inv;
    int e0=0;
    #pragma unroll
    for(int e=1;e<TE;e++) if (p[e]>p[e0]) e0=e;
    int e1=-1;
    #pragma unroll
    for(int e=0;e<TE;e++){ if(e==e0) continue; if (e1<0 || p[e]>p[e1]) e1=e; }
    float w0=p[e0], w1=p[e1];
    float tot = w0+w1;
    w0/=tot; w1/=tot;
    int pos = atomicAdd(&g_ecnt[e0],1);
    g_elist[e0*TT+pos]=t; g_ew[e0*TT+pos]=w0;
    pos = atomicAdd(&g_ecnt[e1],1);
    g_elist[e1*TT+pos]=t; g_ew[e1*TT+pos]=w1;
  }
}

// ---------------- launcher ----------------
extern "C" void kernel_launch(void* const* d_in, const int* in_sizes, int n_in,
                              void* d_out, int out_size){
  const float* hidden  = (const float*)d_in[0];
  const float* cosb    = (const float*)d_in[1];
  const float* sinb    = (const float*)d_in[2];
  const float* ln1w    = (const float*)d_in[3];
  const float* ln2w    = (const float*)d_in[4];
  const float* wqkv    = (const float*)d_in[5];
  const float* wout    = (const float*)d_in[6];
  const float* wrouter = (const float*)d_in[7];
  const float* wgate   = (const float*)d_in[8];
  const float* wup     = (const float*)d_in[9];
  const float* wdown   = (const float*)d_in[10];
  float* out = (float*)d_out;

  float *p_h,*p_qkv,*p_scores,*p_attn,*p_res,*p_GU,*p_ew;
  int *p_elist,*p_ecnt;
  u16 *p_wqkv,*p_wout,*p_wgu,*p_wd;
  u16 *p_xh,*p_xl,*p_ah,*p_al,*p_gh,*p_qh,*p_ql,*p_ph,*p_pl,*p_vt;
  cudaGetSymbolAddress((void**)&p_h, g_h);
  cudaGetSymbolAddress((void**)&p_qkv, g_qkv);
  cudaGetSymbolAddress((void**)&p_scores, g_scores);
  cudaGetSymbolAddress((void**)&p_attn, g_attn);
  cudaGetSymbolAddress((void**)&p_res, g_res);
  cudaGetSymbolAddress((void**)&p_GU, g_GU);
  cudaGetSymbolAddress((void**)&p_ew, g_ew);
  cudaGetSymbolAddress((void**)&p_elist, g_elist);
  cudaGetSymbolAddress((void**)&p_ecnt, g_ecnt);
  cudaGetSymbolAddress((void**)&p_wqkv, g_wqkv_h);
  cudaGetSymbolAddress((void**)&p_wout, g_wout_h);
  cudaGetSymbolAddress((void**)&p_wgu, g_wgu_h);
  cudaGetSymbolAddress((void**)&p_wd, g_wd_h);
  cudaGetSymbolAddress((void**)&p_xh, g_xh);
  cudaGetSymbolAddress((void**)&p_xl, g_xl);
  cudaGetSymbolAddress((void**)&p_ah, g_ah);
  cudaGetSymbolAddress((void**)&p_al, g_al);
  cudaGetSymbolAddress((void**)&p_gh, g_gh);
  cudaGetSymbolAddress((void**)&p_qh, g_qh);
  cudaGetSymbolAddress((void**)&p_ql, g_ql);
  cudaGetSymbolAddress((void**)&p_ph, g_ph);
  cudaGetSymbolAddress((void**)&p_pl, g_pl);
  cudaGetSymbolAddress((void**)&p_vt, g_vt);

  const int SMEM_S = 2*3*MATB;   // split stages
  const int SMEM_N = 2*2*MATB;   // non-split
  cudaFuncSetAttribute(tgemm<0,false,0,true>,  cudaFuncAttributeMaxDynamicSharedMemorySize, SMEM_S);
  cudaFuncSetAttribute(tgemm<0,false,1,true>,  cudaFuncAttributeMaxDynamicSharedMemorySize, SMEM_S);
  cudaFuncSetAttribute(tgemm<0,false,2,true>,  cudaFuncAttributeMaxDynamicSharedMemorySize, SMEM_S);
  cudaFuncSetAttribute(tgemm<0,true,3,false>,  cudaFuncAttributeMaxDynamicSharedMemorySize, SMEM_N);
  cudaFuncSetAttribute(tgemm<3,false,4,false>, cudaFuncAttributeMaxDynamicSharedMemorySize, SMEM_N);

  const int n_td = TT*TD;
  float* resid = (out_size >= 2*n_td) ? (out + (size_t)n_td) : p_res;

  // 0. weight conversion
  convhalf<<<(OQKV*TD/4+255)/256,256>>>(wqkv, p_wqkv, OQKV*TD/4);
  convhalf<<<(TD*TD/4+255)/256,256>>>(wout, p_wout, TD*TD/4);
  transhalf<<<dim3(TF/32, TD/32, TE), dim3(32,8)>>>(wgate, p_wgu, TD, TF,
      (size_t)TD*TF, (size_t)2*TF*TD);
  transhalf<<<dim3(TF/32, TD/32, TE), dim3(32,8)>>>(wup, p_wgu + (size_t)TF*TD, TD, TF,
      (size_t)TD*TF, (size_t)2*TF*TD);
  transhalf<<<dim3(TD/32, TF/32, TE), dim3(32,8)>>>(wdown, p_wd, TF, TD,
      (size_t)TF*TD, (size_t)TD*TF);

  // 1. LN1 (split — feeds residual-critical QKV)
  ln_kernel<<<TT,256>>>(hidden, ln1w, p_h, p_xh, p_xl);

  // 2. QKV (split A)
  tgemm<0,false,0,true><<<dim3(OQKV/128, TT/128), 256, SMEM_S>>>(
      TT, OQKV, TD, p_xh, p_xl, TD, p_wqkv, TD,
      p_qkv, OQKV, 1.f, nullptr, nullptr, nullptr, 0,0,0);

  // 3. RoPE (split) + V^T
  {
    int total = TT*(TH+TKV)*(THD/2);
    rope_kernel<<<(total+255)/256,256>>>(p_qkv, cosb, sinb, p_qh, p_ql);
  }
  vtrans<<<dim3(TS_/32, THD/32, TBATCH*TKV), dim3(32,8)>>>(p_qkv, p_vt);

  // 4. scores (split Q)
  tgemm<0,false,1,true><<<dim3(TS_/128, TS_/128, TBATCH*TH), 256, SMEM_S>>>(
      TS_, TS_, THD, p_qh, p_ql, 0, p_qh, 0,
      p_scores, 0, 1.f/sqrtf((float)THD), nullptr, nullptr, nullptr, 0,0,0);

  // 5. softmax -> P split
  softmax_kernel<<<TBATCH*TH*TS_,256>>>(p_scores, p_ph, p_pl);

  // 6. PV (split P)
  tgemm<0,false,2,true><<<dim3(1, TS_/128, TBATCH*TH), 256, SMEM_S>>>(
      TS_, THD, TS_, p_ph, p_pl, 0, p_vt, 0,
      p_attn, 0, 1.f, nullptr, nullptr, nullptr, 0,0,0);

  // 6b. attn -> fp16 split
  convsplit<<<(n_td/4+255)/256,256>>>(p_attn, p_ah, p_al, n_td/4);

  // 7. out-proj (split A) -> g_qkv
  tgemm<0,false,0,true><<<dim3(TD/128, TT/128), 256, SMEM_S>>>(
      TT, TD, TH*THD, p_ah, p_al, TH*THD, p_wout, TH*THD,
      p_qkv, TD, 1.f, nullptr, nullptr, nullptr, 0,0,0);

  // 8. residual
  add_kernel<<<(n_td+255)/256,256>>>(p_qkv, hidden, resid, n_td);

  // 9. LN2 (xl written but unused by MoE — harmless)
  ln_kernel<<<TT,256>>>(resid, ln2w, p_h, p_xh, p_xl);

  // 10. zero + router (fp32 h)
  zero_kernel<<<(n_td+255)/256,256>>>(out, n_td);
  zero_cnt_kernel<<<1,32>>>();
  router_kernel<<<TT,128>>>(p_h, wrouter);

  // 11. MoE (single-fp16 A — downstream of routing, linear in output)
  tgemm<0,true,3,false><<<dim3(2*TF/128, TT/128, TE), 256, SMEM_N>>>(
      TT, 2*TF, TD, p_xh, nullptr, TD, p_wgu, TD,
      p_GU, 2*TF, 1.f, p_elist, nullptr, p_ecnt,
      0, (size_t)2*TF*TD, (size_t)TT*2*TF);
  silu_mul_kernel<<<dim3((TT*TF+255)/256, 1, TE), 256>>>(p_gh);
  tgemm<3,false,4,false><<<dim3(TD/128, TT/128, TE), 256, SMEM_N>>>(
      TT, TD, TF, p_gh, nullptr, TF, p_wd, TF,
      out, TD, 1.f, p_elist, p_ew, p_ecnt,
      (size_t)TT*TF, (size_t)TD*TF, 0);

  if (resid == p_res && out_size >= 2*n_td){
    add_kernel<<<(n_td+255)/256,256>>>(p_qkv, hidden, out + (size_t)n_td, n_td);
  }
}

// round 9
// speedup vs baseline: 11.4706x; 1.0852x over previous
#include <cuda_runtime.h>
#include <cuda_fp16.h>
#include <math.h>
#include <stdint.h>

// Problem constants
#define TS_ 1024
#define TBATCH 2
#define TD 2048
#define TH 16
#define TKV 4
#define THD 128
#define TE 8
#define TF 2048
#define TT (TBATCH*TS_)            // 2048 tokens
#define OQKV ((TH+2*TKV)*THD)      // 3072
#define REP (TH/TKV)               // 4

typedef unsigned short u16;

// ---------------- scratch (device globals) ----------
__device__ float g_h[(size_t)TT*TD];
__device__ float g_qkv[(size_t)TT*OQKV];
__device__ float g_scores[(size_t)TBATCH*TH*TS_*TS_];
__device__ float g_attn[(size_t)TT*TH*THD];
__device__ float g_res[(size_t)TT*TD];
__device__ int   g_elist[TE*TT];
__device__ float g_ew[TE*TT];
__device__ int   g_ecnt[TE];

// fp16 buffers
__device__ u16 g_wqkv_h[(size_t)OQKV*TD];
__device__ u16 g_wout_h[(size_t)TD*TD];
__device__ u16 g_wgu_h[(size_t)TE*2*TF*TD];    // [e][2F][D], rows interleaved gate/up
__device__ u16 g_wd_h[(size_t)TE*TD*TF];       // [e][D][F]
__device__ u16 g_xh[(size_t)TT*TD],  g_xl[(size_t)TT*TD];
__device__ u16 g_ah[(size_t)TT*TD],  g_al[(size_t)TT*TD];
__device__ u16 g_gh[(size_t)TE*TT*TF];
__device__ u16 g_qh[(size_t)TT*OQKV], g_ql[(size_t)TT*OQKV];
__device__ u16 g_ph[(size_t)TBATCH*TH*TS_*TS_], g_pl[(size_t)TBATCH*TH*TS_*TS_];
__device__ u16 g_vt[(size_t)TBATCH*TKV*THD*TS_];

// ---------------- helpers ----------------
__device__ __forceinline__ u16 h16(float x){
  __half h = __float2half_rn(x);
  return *reinterpret_cast<u16*>(&h);
}
__device__ __forceinline__ float h2f(u16 b){
  __half h = *reinterpret_cast<__half*>(&b);
  return __half2float(h);
}
__device__ __forceinline__ uint32_t smem_u32(const void* p){
  uint32_t a;
  asm("{ .reg .u64 t; cvta.to.shared.u64 t, %1; cvt.u32.u64 %0, t; }" : "=r"(a) : "l"(p));
  return a;
}
__device__ __forceinline__ void ldsm_x4(uint32_t* r, uint32_t addr){
  asm volatile("ldmatrix.sync.aligned.m8n8.x4.shared.b16 {%0,%1,%2,%3}, [%4];"
    : "=r"(r[0]),"=r"(r[1]),"=r"(r[2]),"=r"(r[3]) : "r"(addr));
}
__device__ __forceinline__ void mma16816(float* c, const uint32_t* a, const uint32_t* b){
  asm volatile("mma.sync.aligned.m16n8k16.row.col.f32.f16.f16.f32 "
    "{%0,%1,%2,%3}, {%4,%5,%6,%7}, {%8,%9}, {%0,%1,%2,%3};"
    : "+f"(c[0]),"+f"(c[1]),"+f"(c[2]),"+f"(c[3])
    : "r"(a[0]),"r"(a[1]),"r"(a[2]),"r"(a[3]), "r"(b[0]),"r"(b[1]));
}
__device__ __forceinline__ void cp16(uint32_t dst, const void* src, int ssz){
  asm volatile("cp.async.cg.shared.global [%0], [%1], 16, %2;"
    :: "r"(dst), "l"(src), "r"(ssz) : "memory");
}
__device__ __forceinline__ void cp16f(uint32_t dst, const void* src){
  asm volatile("cp.async.cg.shared.global [%0], [%1], 16;"
    :: "r"(dst), "l"(src) : "memory");
}
#define CP_COMMIT() asm volatile("cp.async.commit_group;":::"memory")
#define CP_WAIT(n)  asm volatile("cp.async.wait_group %0;"::"n"(n):"memory")

// ---------------- conversion kernels ----------------
__global__ void convhalf(const float* __restrict__ src, u16* __restrict__ d, int n4){
  int i = blockIdx.x*blockDim.x + threadIdx.x;
  if (i >= n4) return;
  float4 v = reinterpret_cast<const float4*>(src)[i];
  ushort4 hv; hv.x=h16(v.x); hv.y=h16(v.y); hv.z=h16(v.z); hv.w=h16(v.w);
  reinterpret_cast<ushort4*>(d)[i]=hv;
}
__global__ void convsplit(const float* __restrict__ src, u16* __restrict__ h,
                          u16* __restrict__ l, int n4){
  int i = blockIdx.x*blockDim.x + threadIdx.x;
  if (i >= n4) return;
  float4 v = reinterpret_cast<const float4*>(src)[i];
  ushort4 hv, lv;
  hv.x=h16(v.x); hv.y=h16(v.y); hv.z=h16(v.z); hv.w=h16(v.w);
  lv.x=h16(v.x-h2f(hv.x)); lv.y=h16(v.y-h2f(hv.y));
  lv.z=h16(v.z-h2f(hv.z)); lv.w=h16(v.w-h2f(hv.w));
  reinterpret_cast<ushort4*>(h)[i]=hv;
  reinterpret_cast<ushort4*>(l)[i]=lv;
}
// transpose [R,C] -> [C,R] fp16; dst row = rmul*c + roff (for gate/up interleave)
__global__ void transhalf(const float* __restrict__ src, u16* __restrict__ dst,
                          int R, int C, size_t sstr, size_t dstr, int rmul, int roff){
  __shared__ float t[32][33];
  src += (size_t)blockIdx.z * sstr;
  dst += (size_t)blockIdx.z * dstr;
  int c0 = blockIdx.x*32, r0 = blockIdx.y*32;
  int tx = threadIdx.x, ty = threadIdx.y;
  #pragma unroll
  for (int j=0;j<4;j++)
    t[ty+j*8][tx] = src[(size_t)(r0+ty+j*8)*C + c0+tx];
  __syncthreads();
  #pragma unroll
  for (int j=0;j<4;j++)
    dst[(size_t)(rmul*(c0+ty+j*8)+roff)*R + r0+tx] = h16(t[tx][ty+j*8]);
}
__global__ void vtrans(const float* __restrict__ qkv, u16* __restrict__ vt){
  __shared__ float t[32][33];
  int z = blockIdx.z; int b = z/TKV, kv = z%TKV;
  int s0 = blockIdx.x*32, h0 = blockIdx.y*32;
  int tx = threadIdx.x, ty = threadIdx.y;
  #pragma unroll
  for (int j=0;j<4;j++){
    int s = s0+ty+j*8;
    t[ty+j*8][tx] = qkv[(size_t)(b*TS_+s)*OQKV + (TH+TKV+kv)*THD + h0+tx];
  }
  __syncthreads();
  #pragma unroll
  for (int j=0;j<4;j++){
    int hd = h0+ty+j*8;
    vt[((size_t)z*THD + hd)*TS_ + s0+tx] = h16(t[tx][ty+j*8]);
  }
}

// ---------------- tensor-core GEMM (fp16, optional A hi/lo split) ----------
// C[M,N] = alpha * (Ah[+Al])[M,K] @ Bh[N,K]^T     BK=64, 2-stage cp.async
// EPI 0: store. EPI 1: fused silu(gate)*up -> fp16 (interleaved cols).
// EPI 2: store + hres add. EPI 3: atomicAdd C[arow[m]] += aw[m]*v.
// ADDR 0: plain. 1: attn scores. 2: PV. 3: expert-batched gather.
// 4: expert-batched (A per-expert) atomic scatter.
#define TPAD 144
#define MATB (128*TPAD)   // 18432

template<int EPI, bool GATHER, int ADDR, bool ASPLIT>
__global__ __launch_bounds__(256,2) void tgemm(
    int M, int N, int K,
    const u16* __restrict__ Ah, const u16* __restrict__ Al, int lda,
    const u16* __restrict__ Bh, int ldb,
    float* __restrict__ C, int ldc, float alpha,
    const int* __restrict__ arow, const float* __restrict__ aw,
    const int* __restrict__ cntp,
    size_t astride, size_t bstride, size_t cstride)
{
  constexpr int NMAT = ASPLIT ? 3 : 2;
  constexpr int STB  = NMAT*MATB;
  constexpr int BOFF = (ASPLIT ? 2 : 1)*MATB;
  extern __shared__ __align__(16) char smem[];
  int row0 = blockIdx.y*128, col0 = blockIdx.x*128;
  int Klim = K;

  if (ADDR==1){
    if (col0 > row0 + 127) return;
    int z = blockIdx.z, b = z/TH, h = z%TH;
    size_t off = (size_t)b*TS_*OQKV + h*THD;
    Ah += off; if (ASPLIT) Al += off;
    lda = OQKV;
    Bh += (size_t)b*TS_*OQKV + (TH + h/REP)*THD;
    ldb = OQKV;
    C  += (size_t)z*TS_*TS_;
    ldc = TS_;
  } else if (ADDR==2){
    int z = blockIdx.z, b = z/TH, h = z%TH;
    size_t off = (size_t)z*TS_*TS_;
    Ah += off; if (ASPLIT) Al += off;
    lda = TS_;
    Bh += ((size_t)(b*TKV + h/REP))*THD*TS_;
    ldb = TS_;
    C  += (size_t)b*TS_*(TH*THD) + h*THD;
    ldc = TH*THD;
    Klim = min(K, row0 + 128);
  } else if (ADDR==3 || ADDR==4){
    int z = blockIdx.z;
    arow += z*TT;
    if (ADDR==4){ aw += z*TT; Ah += (size_t)z*astride; }
    cntp += z;
    Bh += (size_t)z*bstride;
    if (EPI != 1) C += (size_t)z*cstride;
  }

  int Meff = cntp ? *cntp : M;
  if (row0 >= Meff) return;

  int tid = threadIdx.x, wid = tid>>5, lane = tid&31;
  int wm = wid>>2, wn = wid&3;
  uint32_t sbase = smem_u32(smem);

  uint32_t laneA  = (uint32_t)((lane&15)*TPAD) + (uint32_t)((lane>>4)*16);
  uint32_t laneB4 = (uint32_t)((lane&7)*TPAD) + (uint32_t)(((lane>>3)&1)*16)
                  + (uint32_t)((lane>>4)*(8*TPAD));

  float acc[4][4][4];
  #pragma unroll
  for(int i=0;i<4;i++)
    #pragma unroll
    for(int j=0;j<4;j++)
      #pragma unroll
      for(int q=0;q<4;q++) acc[i][j][q]=0.f;

  const int NC = Klim/64;

  int c16 = tid&7, rt = tid>>3;     // rt 0..31
  uint32_t doff0 = (uint32_t)(rt*TPAD + c16*16);
  long aoff[4]; int apred[4];
  #pragma unroll
  for (int it=0; it<4; it++){
    int gm = row0 + rt + it*32;
    apred[it] = gm < Meff;
    long src = apred[it] ? ((GATHER||ADDR==3) ? (long)arow[gm] : (long)gm) : 0;
    aoff[it] = src*(long)lda + c16*8;
  }
  const u16* pb0 = Bh + (long)(col0 + rt)*ldb + c16*8;

  auto issue = [&](int c){
    uint32_t dst0 = sbase + (c&1)*STB;
    int k0 = c*64;
    #pragma unroll
    for (int it=0; it<4; it++){
      uint32_t d = dst0 + doff0 + it*32*TPAD;
      int ssz = apred[it] ? 16 : 0;
      cp16(d, Ah + aoff[it] + k0, ssz);
      if (ASPLIT) cp16(d + MATB, Al + aoff[it] + k0, ssz);
      cp16f(d + BOFF, pb0 + (long)it*32*ldb + k0);
    }
    CP_COMMIT();
  };

  issue(0);
  for (int c = 0; c < NC; c++){
    if (c+1 < NC){ issue(c+1); CP_WAIT(1); }
    else         { CP_WAIT(0); }
    __syncthreads();

    uint32_t st = sbase + (c&1)*STB;
    #pragma unroll
    for (int ks = 0; ks < 4; ks++){
      uint32_t rowA = st + (uint32_t)((wm*64)*TPAD + ks*32) + laneA;
      uint32_t rowB = st + BOFF + (uint32_t)((wn*32)*TPAD + ks*32) + laneB4;
      uint32_t aH[4][4], bH[4][2];
      #pragma unroll
      for (int mf=0; mf<4; mf++) ldsm_x4(aH[mf], rowA + mf*16*TPAD);
      #pragma unroll
      for (int np=0; np<2; np++){
        uint32_t t4[4];
        ldsm_x4(t4, rowB + np*16*TPAD);
        bH[2*np][0]=t4[0]; bH[2*np][1]=t4[1];
        bH[2*np+1][0]=t4[2]; bH[2*np+1][1]=t4[3];
      }
      #pragma unroll
      for (int mf=0; mf<4; mf++)
        #pragma unroll
        for (int nf=0; nf<4; nf++) mma16816(acc[mf][nf], aH[mf], bH[nf]);
      if (ASPLIT){
        uint32_t aL[4][4];
        #pragma unroll
        for (int mf=0; mf<4; mf++) ldsm_x4(aL[mf], rowA + MATB + mf*16*TPAD);
        #pragma unroll
        for (int mf=0; mf<4; mf++)
          #pragma unroll
          for (int nf=0; nf<4; nf++) mma16816(acc[mf][nf], aL[mf], bH[nf]);
      }
    }
    __syncthreads();
  }

  // ---- epilogue ----
  int g = lane>>2, tig = lane&3;
  u16* G = nullptr;
  if (EPI == 1) G = reinterpret_cast<u16*>(C) + (size_t)blockIdx.z*cstride;
  #pragma unroll
  for (int mf=0; mf<4; mf++){
    int ra = row0 + wm*64 + mf*16 + g;
    int rb = ra + 8;
    #pragma unroll
    for (int nf=0; nf<4; nf++){
      int col = col0 + wn*32 + nf*8 + tig*2;
      float* cacc = acc[mf][nf];
      if (EPI == 0){
        if (ra < Meff){
          float* p = C + (size_t)ra*ldc + col;
          p[0] = cacc[0]*alpha; p[1] = cacc[1]*alpha;
        }
        if (rb < Meff){
          float* p = C + (size_t)rb*ldc + col;
          p[0] = cacc[2]*alpha; p[1] = cacc[3]*alpha;
        }
      } else if (EPI == 1){
        // interleaved: col even = gate_f, col+1 = up_f; f = col/2
        int f = col >> 1;
        if (ra < Meff){
          float gg = cacc[0];
          G[(size_t)ra*(ldc>>1) + f] = h16((gg/(1.f+__expf(-gg)))*cacc[1]);
        }
        if (rb < Meff){
          float gg = cacc[2];
          G[(size_t)rb*(ldc>>1) + f] = h16((gg/(1.f+__expf(-gg)))*cacc[3]);
        }
      } else if (EPI == 2){
        if (ra < Meff){
          float* p = C + (size_t)ra*ldc + col;
          const float* hr = aw + (size_t)ra*ldc + col;
          p[0] = cacc[0]*alpha + hr[0]; p[1] = cacc[1]*alpha + hr[1];
        }
        if (rb < Meff){
          float* p = C + (size_t)rb*ldc + col;
          const float* hr = aw + (size_t)rb*ldc + col;
          p[0] = cacc[2]*alpha + hr[0]; p[1] = cacc[3]*alpha + hr[1];
        }
      } else {
        if (ra < Meff){
          float w = aw[ra];
          float* p = C + (size_t)arow[ra]*ldc + col;
          atomicAdd(p,   w*cacc[0]*alpha);
          atomicAdd(p+1, w*cacc[1]*alpha);
        }
        if (rb < Meff){
          float w = aw[rb];
          float* p = C + (size_t)arow[rb]*ldc + col;
          atomicAdd(p,   w*cacc[2]*alpha);
          atomicAdd(p+1, w*cacc[3]*alpha);
        }
      }
    }
  }
}

// ---------------- reduction helpers ----------------
__device__ __forceinline__ float warp_sum(float v){
  #pragma unroll
  for(int o=16;o;o>>=1) v += __shfl_xor_sync(0xffffffffu, v, o);
  return v;
}
__device__ __forceinline__ float warp_max(float v){
  #pragma unroll
  for(int o=16;o;o>>=1) v = fmaxf(v, __shfl_xor_sync(0xffffffffu, v, o));
  return v;
}

// ---------------- LayerNorm (fp32 + fp16 hi[/lo]) ----------------
__global__ void ln_kernel(const float* __restrict__ x, const float* __restrict__ w,
                          float* __restrict__ y, u16* __restrict__ yh, u16* __restrict__ yl){
  int row = blockIdx.x;
  const float* xr = x + (size_t)row*TD;
  float s=0.f, s2=0.f;
  for(int d=threadIdx.x; d<TD; d+=blockDim.x){ float v=xr[d]; s+=v; s2+=v*v; }
  __shared__ float shs[8], shs2[8];
  int lane=threadIdx.x&31, wp=threadIdx.x>>5;
  s = warp_sum(s); s2 = warp_sum(s2);
  if(!lane){ shs[wp]=s; shs2[wp]=s2; }
  __syncthreads();
  if (threadIdx.x < 32){
    float a = (threadIdx.x<8)? shs[threadIdx.x] : 0.f;
    float b = (threadIdx.x<8)? shs2[threadIdx.x] : 0.f;
    a = warp_sum(a); b = warp_sum(b);
    if(!threadIdx.x){ shs[0]=a; shs2[0]=b; }
  }
  __syncthreads();
  float mu = shs[0]*(1.f/TD);
  float var = shs2[0]*(1.f/TD) - mu*mu;
  float rstd = rsqrtf(var + 1e-5f);
  for(int d=threadIdx.x; d<TD; d+=blockDim.x){
    float v = (xr[d]-mu)*rstd*w[d];
    y[(size_t)row*TD + d] = v;
    u16 h = h16(v);
    yh[(size_t)row*TD + d] = h;
    if (yl) yl[(size_t)row*TD + d] = h16(v - h2f(h));
  }
}

// ---------------- RoPE -> fp16 split ----------------
__global__ void rope_kernel(const float* __restrict__ qkv,
                            const float* __restrict__ cosb,
                            const float* __restrict__ sinb,
                            u16* __restrict__ qh, u16* __restrict__ ql){
  int idx = blockIdx.x*blockDim.x + threadIdx.x;
  const int total = TT*(TH+TKV)*(THD/2);
  if (idx >= total) return;
  int i  = idx & 63;
  int rest = idx >> 6;
  int hh = rest % (TH+TKV);
  int t  = rest / (TH+TKV);
  int s  = t % TS_;
  float c  = cosb[s*THD + i];
  float sn = sinb[s*THD + i];
  const float* p = qkv + (size_t)t*OQKV + hh*THD;
  float x1 = p[i], x2 = p[i+64];
  float r1 = x1*c - x2*sn;
  float r2 = x2*c + x1*sn;
  size_t o = (size_t)t*OQKV + hh*THD;
  u16 h1 = h16(r1), h2 = h16(r2);
  qh[o+i] = h1;    ql[o+i]    = h16(r1 - h2f(h1));
  qh[o+i+64] = h2; ql[o+i+64] = h16(r2 - h2f(h2));
}

// ---------------- causal softmax -> fp16 split P ----------------
__global__ void softmax_kernel(const float* __restrict__ s,
                               u16* __restrict__ ph, u16* __restrict__ pl){
  int row = blockIdx.x;
  int q = row % TS_;
  int L = q + 1;
  int pad = ((q>>7)+1)<<7;
  const float* r = s + (size_t)row*TS_;
  u16* oh = ph + (size_t)row*TS_;
  u16* ol = pl + (size_t)row*TS_;
  int tid = threadIdx.x;
  int lane = tid&31, wp = tid>>5;
  __shared__ float sh[8];

  float mx = -1e30f;
  for(int d=tid; d<L; d+=256) mx = fmaxf(mx, r[d]);
  mx = warp_max(mx);
  if(!lane) sh[wp]=mx;
  __syncthreads();
  if (tid<32){ float v=(tid<8)?sh[tid]:-1e30f; v=warp_max(v); if(!tid) sh[0]=v; }
  __syncthreads();
  mx = sh[0];
  __syncthreads();

  float sum = 0.f;
  for(int d=tid; d<L; d+=256) sum += __expf(r[d]-mx);
  sum = warp_sum(sum);
  if(!lane) sh[wp]=sum;
  __syncthreads();
  if (tid<32){ float v=(tid<8)?sh[tid]:0.f; v=warp_sum(v); if(!tid) sh[0]=v; }
  __syncthreads();
  float inv = 1.f/sh[0];

  for(int d=tid; d<L; d+=256){
    float p = __expf(r[d]-mx)*inv;
    u16 h = h16(p);
    oh[d] = h;
    ol[d] = h16(p - h2f(h));
  }
  for(int d=L+tid; d<pad; d+=256){ oh[d]=0; ol[d]=0; }
}

// ---------------- elementwise ----------------
__global__ void zero_kernel(float* __restrict__ p, int n){
  int i = blockIdx.x*blockDim.x + threadIdx.x;
  if (i<n) p[i]=0.f;
}
__global__ void zero_cnt_kernel(){
  if (threadIdx.x < TE) g_ecnt[threadIdx.x]=0;
}

// ---------------- router ----------------
__global__ void router_kernel(const float* __restrict__ x, const float* __restrict__ wr){
  int t = blockIdx.x;
  int tid = threadIdx.x;
  const float* xr = x + (size_t)t*TD;
  float acc[TE];
  #pragma unroll
  for(int e=0;e<TE;e++) acc[e]=0.f;
  for(int d=tid; d<TD; d+=128){
    float xv = xr[d];
    #pragma unroll
    for(int e=0;e<TE;e++) acc[e] += xv*wr[e*TD+d];
  }
  __shared__ float sh[TE][4];
  int lane=tid&31, wp=tid>>5;
  #pragma unroll
  for(int e=0;e<TE;e++){
    float v = warp_sum(acc[e]);
    if(!lane) sh[e][wp]=v;
  }
  __syncthreads();
  if (tid==0){
    float lg[TE];
    float mx=-1e30f;
    #pragma unroll
    for(int e=0;e<TE;e++){ lg[e]=sh[e][0]+sh[e][1]+sh[e][2]+sh[e][3]; mx=fmaxf(mx,lg[e]); }
    float p[TE]; float s=0.f;
    #pragma unroll
    for(int e=0;e<TE;e++){ p[e]=expf(lg[e]-mx); s+=p[e]; }
    float inv=1.f/s;
    #pragma unroll
    for(int e=0;e<TE;e++) p[e]*=inv;
    int e0=0;
    #pragma unroll
    for(int e=1;e<TE;e++) if (p[e]>p[e0]) e0=e;
    int e1=-1;
    #pragma unroll
    for(int e=0;e<TE;e++){ if(e==e0) continue; if (e1<0 || p[e]>p[e1]) e1=e; }
    float w0=p[e0], w1=p[e1];
    float tot = w0+w1;
    w0/=tot; w1/=tot;
    int pos = atomicAdd(&g_ecnt[e0],1);
    g_elist[e0*TT+pos]=t; g_ew[e0*TT+pos]=w0;
    pos = atomicAdd(&g_ecnt[e1],1);
    g_elist[e1*TT+pos]=t; g_ew[e1*TT+pos]=w1;
  }
}

// ---------------- launcher ----------------
extern "C" void kernel_launch(void* const* d_in, const int* in_sizes, int n_in,
                              void* d_out, int out_size){
  const float* hidden  = (const float*)d_in[0];
  const float* cosb    = (const float*)d_in[1];
  const float* sinb    = (const float*)d_in[2];
  const float* ln1w    = (const float*)d_in[3];
  const float* ln2w    = (const float*)d_in[4];
  const float* wqkv    = (const float*)d_in[5];
  const float* wout    = (const float*)d_in[6];
  const float* wrouter = (const float*)d_in[7];
  const float* wgate   = (const float*)d_in[8];
  const float* wup     = (const float*)d_in[9];
  const float* wdown   = (const float*)d_in[10];
  float* out = (float*)d_out;

  float *p_h,*p_qkv,*p_scores,*p_attn,*p_res,*p_ew;
  int *p_elist,*p_ecnt;
  u16 *p_wqkv,*p_wout,*p_wgu,*p_wd;
  u16 *p_xh,*p_xl,*p_ah,*p_al,*p_gh,*p_qh,*p_ql,*p_ph,*p_pl,*p_vt;
  cudaGetSymbolAddress((void**)&p_h, g_h);
  cudaGetSymbolAddress((void**)&p_qkv, g_qkv);
  cudaGetSymbolAddress((void**)&p_scores, g_scores);
  cudaGetSymbolAddress((void**)&p_attn, g_attn);
  cudaGetSymbolAddress((void**)&p_res, g_res);
  cudaGetSymbolAddress((void**)&p_ew, g_ew);
  cudaGetSymbolAddress((void**)&p_elist, g_elist);
  cudaGetSymbolAddress((void**)&p_ecnt, g_ecnt);
  cudaGetSymbolAddress((void**)&p_wqkv, g_wqkv_h);
  cudaGetSymbolAddress((void**)&p_wout, g_wout_h);
  cudaGetSymbolAddress((void**)&p_wgu, g_wgu_h);
  cudaGetSymbolAddress((void**)&p_wd, g_wd_h);
  cudaGetSymbolAddress((void**)&p_xh, g_xh);
  cudaGetSymbolAddress((void**)&p_xl, g_xl);
  cudaGetSymbolAddress((void**)&p_ah, g_ah);
  cudaGetSymbolAddress((void**)&p_al, g_al);
  cudaGetSymbolAddress((void**)&p_gh, g_gh);
  cudaGetSymbolAddress((void**)&p_qh, g_qh);
  cudaGetSymbolAddress((void**)&p_ql, g_ql);
  cudaGetSymbolAddress((void**)&p_ph, g_ph);
  cudaGetSymbolAddress((void**)&p_pl, g_pl);
  cudaGetSymbolAddress((void**)&p_vt, g_vt);

  const int SMEM_S = 2*3*MATB;   // split stages
  const int SMEM_N = 2*2*MATB;   // non-split
  cudaFuncSetAttribute(tgemm<0,false,0,true>,  cudaFuncAttributeMaxDynamicSharedMemorySize, SMEM_S);
  cudaFuncSetAttribute(tgemm<0,false,1,true>,  cudaFuncAttributeMaxDynamicSharedMemorySize, SMEM_S);
  cudaFuncSetAttribute(tgemm<0,false,2,true>,  cudaFuncAttributeMaxDynamicSharedMemorySize, SMEM_S);
  cudaFuncSetAttribute(tgemm<2,false,0,true>,  cudaFuncAttributeMaxDynamicSharedMemorySize, SMEM_S);
  cudaFuncSetAttribute(tgemm<1,true,3,false>,  cudaFuncAttributeMaxDynamicSharedMemorySize, SMEM_N);
  cudaFuncSetAttribute(tgemm<3,false,4,false>, cudaFuncAttributeMaxDynamicSharedMemorySize, SMEM_N);

  const int n_td = TT*TD;
  float* resid = (out_size >= 2*n_td) ? (out + (size_t)n_td) : p_res;

  // --- launch order arranged so an early tgemm lands in the ncu -s 5 window ---
  // 0: convhalf(wqkv)  1: ln1  2: QKV tgemm  3: rope  4: vtrans  5: scores tgemm
  convhalf<<<(OQKV*TD/4+255)/256,256>>>(wqkv, p_wqkv, OQKV*TD/4);
  ln_kernel<<<TT,256>>>(hidden, ln1w, p_h, p_xh, p_xl);
  tgemm<0,false,0,true><<<dim3(OQKV/128, TT/128), 256, SMEM_S>>>(
      TT, OQKV, TD, p_xh, p_xl, TD, p_wqkv, TD,
      p_qkv, OQKV, 1.f, nullptr, nullptr, nullptr, 0,0,0);
  {
    int total = TT*(TH+TKV)*(THD/2);
    rope_kernel<<<(total+255)/256,256>>>(p_qkv, cosb, sinb, p_qh, p_ql);
  }
  vtrans<<<dim3(TS_/32, THD/32, TBATCH*TKV), dim3(32,8)>>>(p_qkv, p_vt);
  tgemm<0,false,1,true><<<dim3(TS_/128, TS_/128, TBATCH*TH), 256, SMEM_S>>>(
      TS_, TS_, THD, p_qh, p_ql, 0, p_qh, 0,
      p_scores, 0, 1.f/sqrtf((float)THD), nullptr, nullptr, nullptr, 0,0,0);

  // remaining weight conversions (independent of attention chain)
  convhalf<<<(TD*TD/4+255)/256,256>>>(wout, p_wout, TD*TD/4);
  transhalf<<<dim3(TF/32, TD/32, TE), dim3(32,8)>>>(wgate, p_wgu, TD, TF,
      (size_t)TD*TF, (size_t)2*TF*TD, 2, 0);
  transhalf<<<dim3(TF/32, TD/32, TE), dim3(32,8)>>>(wup, p_wgu, TD, TF,
      (size_t)TD*TF, (size_t)2*TF*TD, 2, 1);
  transhalf<<<dim3(TD/32, TF/32, TE), dim3(32,8)>>>(wdown, p_wd, TF, TD,
      (size_t)TF*TD, (size_t)TD*TF, 1, 0);

  // softmax -> P split
  softmax_kernel<<<TBATCH*TH*TS_,256>>>(p_scores, p_ph, p_pl);

  // PV (split P)
  tgemm<0,false,2,true><<<dim3(1, TS_/128, TBATCH*TH), 256, SMEM_S>>>(
      TS_, THD, TS_, p_ph, p_pl, 0, p_vt, 0,
      p_attn, 0, 1.f, nullptr, nullptr, nullptr, 0,0,0);

  // attn -> fp16 split
  convsplit<<<(n_td/4+255)/256,256>>>(p_attn, p_ah, p_al, n_td/4);

  // out-proj (split A) with fused residual add -> resid
  tgemm<2,false,0,true><<<dim3(TD/128, TT/128), 256, SMEM_S>>>(
      TT, TD, TH*THD, p_ah, p_al, TH*THD, p_wout, TH*THD,
      resid, TD, 1.f, nullptr, hidden, nullptr, 0,0,0);

  // LN2 (hi only — MoE uses single A)
  ln_kernel<<<TT,256>>>(resid, ln2w, p_h, p_xh, nullptr);

  // zero + router
  zero_kernel<<<(n_td+255)/256,256>>>(out, n_td);
  zero_cnt_kernel<<<1,32>>>();
  router_kernel<<<TT,128>>>(p_h, wrouter);

  // MoE: GU GEMM with fused silu -> gh (fp16), then down (atomic scatter)
  tgemm<1,true,3,false><<<dim3(2*TF/128, TT/128, TE), 256, SMEM_N>>>(
      TT, 2*TF, TD, p_xh, nullptr, TD, p_wgu, TD,
      (float*)p_gh, 2*TF, 1.f, p_elist, nullptr, p_ecnt,
      0, (size_t)2*TF*TD, (size_t)TT*TF);
  tgemm<3,false,4,false><<<dim3(TD/128, TT/128, TE), 256, SMEM_N>>>(
      TT, TD, TF, p_gh, nullptr, TF, p_wd, TF,
      out, TD, 1.f, p_elist, p_ew, p_ecnt,
      (size_t)TT*TF, (size_t)TD*TF, 0);
}

// round 10
// speedup vs baseline: 11.8514x; 1.0332x over previous
#include <cuda_runtime.h>
#include <cuda_fp16.h>
#include <math.h>
#include <stdint.h>

// Problem constants
#define TS_ 1024
#define TBATCH 2
#define TD 2048
#define TH 16
#define TKV 4
#define THD 128
#define TE 8
#define TF 2048
#define TT (TBATCH*TS_)            // 2048 tokens
#define OQKV ((TH+2*TKV)*THD)      // 3072
#define REP (TH/TKV)               // 4

typedef unsigned short u16;

// ---------------- scratch (device globals) ----------
__device__ float g_h[(size_t)TT*TD];
__device__ float g_qkv[(size_t)TT*OQKV];
__device__ float g_scores[(size_t)TBATCH*TH*TS_*TS_];
__device__ float g_res[(size_t)TT*TD];
__device__ int   g_elist[TE*TT];
__device__ float g_ew[TE*TT];
__device__ int   g_ecnt[TE];

// fp16 buffers
__device__ u16 g_wqkv_h[(size_t)OQKV*TD];
__device__ u16 g_wout_h[(size_t)TD*TD];
__device__ u16 g_wgu_h[(size_t)TE*2*TF*TD];    // [e][2F][D], rows interleaved gate/up
__device__ u16 g_wd_h[(size_t)TE*TD*TF];       // [e][D][F]
__device__ u16 g_xh[(size_t)TT*TD],  g_xl[(size_t)TT*TD];
__device__ u16 g_ah[(size_t)TT*TD],  g_al[(size_t)TT*TD];
__device__ u16 g_gh[(size_t)TE*TT*TF];
__device__ u16 g_qh[(size_t)TT*OQKV], g_ql[(size_t)TT*OQKV];
__device__ u16 g_ph[(size_t)TBATCH*TH*TS_*TS_], g_pl[(size_t)TBATCH*TH*TS_*TS_];
__device__ u16 g_vt[(size_t)TBATCH*TKV*THD*TS_];

// ---------------- helpers ----------------
__device__ __forceinline__ u16 h16(float x){
  __half h = __float2half_rn(x);
  return *reinterpret_cast<u16*>(&h);
}
__device__ __forceinline__ float h2f(u16 b){
  __half h = *reinterpret_cast<__half*>(&b);
  return __half2float(h);
}
__device__ __forceinline__ uint32_t smem_u32(const void* p){
  uint32_t a;
  asm("{ .reg .u64 t; cvta.to.shared.u64 t, %1; cvt.u32.u64 %0, t; }" : "=r"(a) : "l"(p));
  return a;
}
__device__ __forceinline__ void ldsm_x4(uint32_t* r, uint32_t addr){
  asm volatile("ldmatrix.sync.aligned.m8n8.x4.shared.b16 {%0,%1,%2,%3}, [%4];"
    : "=r"(r[0]),"=r"(r[1]),"=r"(r[2]),"=r"(r[3]) : "r"(addr));
}
__device__ __forceinline__ void mma16816(float* c, const uint32_t* a, const uint32_t* b){
  asm volatile("mma.sync.aligned.m16n8k16.row.col.f32.f16.f16.f32 "
    "{%0,%1,%2,%3}, {%4,%5,%6,%7}, {%8,%9}, {%0,%1,%2,%3};"
    : "+f"(c[0]),"+f"(c[1]),"+f"(c[2]),"+f"(c[3])
    : "r"(a[0]),"r"(a[1]),"r"(a[2]),"r"(a[3]), "r"(b[0]),"r"(b[1]));
}
__device__ __forceinline__ void cp16(uint32_t dst, const void* src, int ssz){
  asm volatile("cp.async.cg.shared.global [%0], [%1], 16, %2;"
    :: "r"(dst), "l"(src), "r"(ssz) : "memory");
}
__device__ __forceinline__ void cp16f(uint32_t dst, const void* src){
  asm volatile("cp.async.cg.shared.global [%0], [%1], 16;"
    :: "r"(dst), "l"(src) : "memory");
}
#define CP_COMMIT() asm volatile("cp.async.commit_group;":::"memory")
#define CP_WAIT(n)  asm volatile("cp.async.wait_group %0;"::"n"(n):"memory")

// ---------------- conversion kernels ----------------
__global__ void convhalf(const float* __restrict__ src, u16* __restrict__ d, int n4){
  int i = blockIdx.x*blockDim.x + threadIdx.x;
  if (i >= n4) return;
  float4 v = reinterpret_cast<const float4*>(src)[i];
  ushort4 hv; hv.x=h16(v.x); hv.y=h16(v.y); hv.z=h16(v.z); hv.w=h16(v.w);
  reinterpret_cast<ushort4*>(d)[i]=hv;
}
// transpose [R,C] -> [C,R] fp16; dst row = rmul*c + roff (for gate/up interleave)
__global__ void transhalf(const float* __restrict__ src, u16* __restrict__ dst,
                          int R, int C, size_t sstr, size_t dstr, int rmul, int roff){
  __shared__ float t[32][33];
  src += (size_t)blockIdx.z * sstr;
  dst += (size_t)blockIdx.z * dstr;
  int c0 = blockIdx.x*32, r0 = blockIdx.y*32;
  int tx = threadIdx.x, ty = threadIdx.y;
  #pragma unroll
  for (int j=0;j<4;j++)
    t[ty+j*8][tx] = src[(size_t)(r0+ty+j*8)*C + c0+tx];
  __syncthreads();
  #pragma unroll
  for (int j=0;j<4;j++)
    dst[(size_t)(rmul*(c0+ty+j*8)+roff)*R + r0+tx] = h16(t[tx][ty+j*8]);
}
__global__ void vtrans(const float* __restrict__ qkv, u16* __restrict__ vt){
  __shared__ float t[32][33];
  int z = blockIdx.z; int b = z/TKV, kv = z%TKV;
  int s0 = blockIdx.x*32, h0 = blockIdx.y*32;
  int tx = threadIdx.x, ty = threadIdx.y;
  #pragma unroll
  for (int j=0;j<4;j++){
    int s = s0+ty+j*8;
    t[ty+j*8][tx] = qkv[(size_t)(b*TS_+s)*OQKV + (TH+TKV+kv)*THD + h0+tx];
  }
  __syncthreads();
  #pragma unroll
  for (int j=0;j<4;j++){
    int hd = h0+ty+j*8;
    vt[((size_t)z*THD + hd)*TS_ + s0+tx] = h16(t[tx][ty+j*8]);
  }
}

// ---------------- tensor-core GEMM (fp16, optional A hi/lo split) ----------
// C[M,N] = alpha * (Ah[+Al])[M,K] @ Bh[N,K]^T     BK=64, 2-stage cp.async
// EPI 0: store fp32. EPI 1: fused silu(gate)*up -> fp16 (interleaved cols).
// EPI 2: store + hres add. EPI 3: atomicAdd C[arow[m]] += aw[m]*v.
// EPI 4: fp16 hi/lo split store (C=hi base, aw=lo base).
// ADDR 0: plain. 1: attn scores. 2: PV. 3: expert-batched gather.
// 4: expert-batched (A per-expert) atomic scatter.
#define TPAD 144
#define MATB (128*TPAD)   // 18432

template<int EPI, bool GATHER, int ADDR, bool ASPLIT>
__global__ __launch_bounds__(256,2) void tgemm(
    int M, int N, int K,
    const u16* __restrict__ Ah, const u16* __restrict__ Al, int lda,
    const u16* __restrict__ Bh, int ldb,
    float* __restrict__ C, int ldc, float alpha,
    const int* __restrict__ arow, const float* __restrict__ aw,
    const int* __restrict__ cntp,
    size_t astride, size_t bstride, size_t cstride)
{
  constexpr int NMAT = ASPLIT ? 3 : 2;
  constexpr int STB  = NMAT*MATB;
  constexpr int BOFF = (ASPLIT ? 2 : 1)*MATB;
  extern __shared__ __align__(16) char smem[];
  int row0 = blockIdx.y*128, col0 = blockIdx.x*128;
  int Klim = K;
  size_t cbase = 0;

  if (ADDR==1){
    if (col0 > row0 + 127) return;
    int z = blockIdx.z, b = z/TH, h = z%TH;
    size_t off = (size_t)b*TS_*OQKV + h*THD;
    Ah += off; if (ASPLIT) Al += off;
    lda = OQKV;
    Bh += (size_t)b*TS_*OQKV + (TH + h/REP)*THD;
    ldb = OQKV;
    C  += (size_t)z*TS_*TS_;
    ldc = TS_;
  } else if (ADDR==2){
    int z = blockIdx.z, b = z/TH, h = z%TH;
    size_t off = (size_t)z*TS_*TS_;
    Ah += off; if (ASPLIT) Al += off;
    lda = TS_;
    Bh += ((size_t)(b*TKV + h/REP))*THD*TS_;
    ldb = TS_;
    cbase = (size_t)b*TS_*(TH*THD) + h*THD;
    if (EPI != 4) C += cbase;
    ldc = TH*THD;
    Klim = min(K, row0 + 128);
  } else if (ADDR==3 || ADDR==4){
    int z = blockIdx.z;
    arow += z*TT;
    if (ADDR==4){ aw += z*TT; Ah += (size_t)z*astride; }
    cntp += z;
    Bh += (size_t)z*bstride;
    if (EPI != 1) C += (size_t)z*cstride;
  }

  int Meff = cntp ? *cntp : M;
  if (row0 >= Meff) return;

  int tid = threadIdx.x, wid = tid>>5, lane = tid&31;
  int wm = wid>>2, wn = wid&3;
  uint32_t sbase = smem_u32(smem);

  uint32_t laneA  = (uint32_t)((lane&15)*TPAD) + (uint32_t)((lane>>4)*16);
  uint32_t laneB4 = (uint32_t)((lane&7)*TPAD) + (uint32_t)(((lane>>3)&1)*16)
                  + (uint32_t)((lane>>4)*(8*TPAD));

  float acc[4][4][4];
  #pragma unroll
  for(int i=0;i<4;i++)
    #pragma unroll
    for(int j=0;j<4;j++)
      #pragma unroll
      for(int q=0;q<4;q++) acc[i][j][q]=0.f;

  const int NC = Klim/64;

  int c16 = tid&7, rt = tid>>3;     // rt 0..31
  uint32_t doff0 = (uint32_t)(rt*TPAD + c16*16);
  long aoff[4]; int apred[4];
  #pragma unroll
  for (int it=0; it<4; it++){
    int gm = row0 + rt + it*32;
    apred[it] = gm < Meff;
    long src = apred[it] ? ((GATHER||ADDR==3) ? (long)arow[gm] : (long)gm) : 0;
    aoff[it] = src*(long)lda + c16*8;
  }
  const u16* pb0 = Bh + (long)(col0 + rt)*ldb + c16*8;

  auto issue = [&](int c){
    uint32_t dst0 = sbase + (c&1)*STB;
    int k0 = c*64;
    #pragma unroll
    for (int it=0; it<4; it++){
      uint32_t d = dst0 + doff0 + it*32*TPAD;
      int ssz = apred[it] ? 16 : 0;
      cp16(d, Ah + aoff[it] + k0, ssz);
      if (ASPLIT) cp16(d + MATB, Al + aoff[it] + k0, ssz);
      cp16f(d + BOFF, pb0 + (long)it*32*ldb + k0);
    }
    CP_COMMIT();
  };

  issue(0);
  for (int c = 0; c < NC; c++){
    if (c+1 < NC){ issue(c+1); CP_WAIT(1); }
    else         { CP_WAIT(0); }
    __syncthreads();

    uint32_t st = sbase + (c&1)*STB;
    #pragma unroll
    for (int ks = 0; ks < 4; ks++){
      uint32_t rowA = st + (uint32_t)((wm*64)*TPAD + ks*32) + laneA;
      uint32_t rowB = st + BOFF + (uint32_t)((wn*32)*TPAD + ks*32) + laneB4;
      uint32_t aH[4][4], bH[4][2];
      #pragma unroll
      for (int mf=0; mf<4; mf++) ldsm_x4(aH[mf], rowA + mf*16*TPAD);
      #pragma unroll
      for (int np=0; np<2; np++){
        uint32_t t4[4];
        ldsm_x4(t4, rowB + np*16*TPAD);
        bH[2*np][0]=t4[0]; bH[2*np][1]=t4[1];
        bH[2*np+1][0]=t4[2]; bH[2*np+1][1]=t4[3];
      }
      #pragma unroll
      for (int mf=0; mf<4; mf++)
        #pragma unroll
        for (int nf=0; nf<4; nf++) mma16816(acc[mf][nf], aH[mf], bH[nf]);
      if (ASPLIT){
        uint32_t aL[4][4];
        #pragma unroll
        for (int mf=0; mf<4; mf++) ldsm_x4(aL[mf], rowA + MATB + mf*16*TPAD);
        #pragma unroll
        for (int mf=0; mf<4; mf++)
          #pragma unroll
          for (int nf=0; nf<4; nf++) mma16816(acc[mf][nf], aL[mf], bH[nf]);
      }
    }
    __syncthreads();
  }

  // ---- epilogue ----
  int g = lane>>2, tig = lane&3;
  u16* G = nullptr;
  if (EPI == 1) G = reinterpret_cast<u16*>(C) + (size_t)blockIdx.z*cstride;
  u16* Oh = nullptr; u16* Ol = nullptr;
  if (EPI == 4){
    Oh = reinterpret_cast<u16*>(C) + cbase;
    Ol = const_cast<u16*>(reinterpret_cast<const u16*>(aw)) + cbase;
  }
  #pragma unroll
  for (int mf=0; mf<4; mf++){
    int ra = row0 + wm*64 + mf*16 + g;
    int rb = ra + 8;
    #pragma unroll
    for (int nf=0; nf<4; nf++){
      int col = col0 + wn*32 + nf*8 + tig*2;
      float* cacc = acc[mf][nf];
      if (EPI == 0){
        if (ra < Meff){
          float* p = C + (size_t)ra*ldc + col;
          p[0] = cacc[0]*alpha; p[1] = cacc[1]*alpha;
        }
        if (rb < Meff){
          float* p = C + (size_t)rb*ldc + col;
          p[0] = cacc[2]*alpha; p[1] = cacc[3]*alpha;
        }
      } else if (EPI == 1){
        int f = col >> 1;
        if (ra < Meff){
          float gg = cacc[0];
          G[(size_t)ra*(ldc>>1) + f] = h16((gg/(1.f+__expf(-gg)))*cacc[1]);
        }
        if (rb < Meff){
          float gg = cacc[2];
          G[(size_t)rb*(ldc>>1) + f] = h16((gg/(1.f+__expf(-gg)))*cacc[3]);
        }
      } else if (EPI == 2){
        if (ra < Meff){
          float* p = C + (size_t)ra*ldc + col;
          const float* hr = aw + (size_t)ra*ldc + col;
          p[0] = cacc[0]*alpha + hr[0]; p[1] = cacc[1]*alpha + hr[1];
        }
        if (rb < Meff){
          float* p = C + (size_t)rb*ldc + col;
          const float* hr = aw + (size_t)rb*ldc + col;
          p[0] = cacc[2]*alpha + hr[0]; p[1] = cacc[3]*alpha + hr[1];
        }
      } else if (EPI == 4){
        if (ra < Meff){
          size_t o = (size_t)ra*ldc + col;
          float v0 = cacc[0]*alpha, v1 = cacc[1]*alpha;
          u16 h0 = h16(v0), h1 = h16(v1);
          Oh[o] = h0;   Oh[o+1] = h1;
          Ol[o] = h16(v0 - h2f(h0)); Ol[o+1] = h16(v1 - h2f(h1));
        }
        if (rb < Meff){
          size_t o = (size_t)rb*ldc + col;
          float v0 = cacc[2]*alpha, v1 = cacc[3]*alpha;
          u16 h0 = h16(v0), h1 = h16(v1);
          Oh[o] = h0;   Oh[o+1] = h1;
          Ol[o] = h16(v0 - h2f(h0)); Ol[o+1] = h16(v1 - h2f(h1));
        }
      } else {
        if (ra < Meff){
          float w = aw[ra];
          float* p = C + (size_t)arow[ra]*ldc + col;
          atomicAdd(p,   w*cacc[0]*alpha);
          atomicAdd(p+1, w*cacc[1]*alpha);
        }
        if (rb < Meff){
          float w = aw[rb];
          float* p = C + (size_t)arow[rb]*ldc + col;
          atomicAdd(p,   w*cacc[2]*alpha);
          atomicAdd(p+1, w*cacc[3]*alpha);
        }
      }
    }
  }
}

// ---------------- reduction helpers ----------------
__device__ __forceinline__ float warp_sum(float v){
  #pragma unroll
  for(int o=16;o;o>>=1) v += __shfl_xor_sync(0xffffffffu, v, o);
  return v;
}
__device__ __forceinline__ float warp_max(float v){
  #pragma unroll
  for(int o=16;o;o>>=1) v = fmaxf(v, __shfl_xor_sync(0xffffffffu, v, o));
  return v;
}

// ---------------- LayerNorm (fp32 + fp16 hi[/lo]) ----------------
__global__ void ln_kernel(const float* __restrict__ x, const float* __restrict__ w,
                          float* __restrict__ y, u16* __restrict__ yh, u16* __restrict__ yl){
  int row = blockIdx.x;
  const float* xr = x + (size_t)row*TD;
  float s=0.f, s2=0.f;
  for(int d=threadIdx.x; d<TD; d+=blockDim.x){ float v=xr[d]; s+=v; s2+=v*v; }
  __shared__ float shs[8], shs2[8];
  int lane=threadIdx.x&31, wp=threadIdx.x>>5;
  s = warp_sum(s); s2 = warp_sum(s2);
  if(!lane){ shs[wp]=s; shs2[wp]=s2; }
  __syncthreads();
  if (threadIdx.x < 32){
    float a = (threadIdx.x<8)? shs[threadIdx.x] : 0.f;
    float b = (threadIdx.x<8)? shs2[threadIdx.x] : 0.f;
    a = warp_sum(a); b = warp_sum(b);
    if(!threadIdx.x){ shs[0]=a; shs2[0]=b; }
  }
  __syncthreads();
  float mu = shs[0]*(1.f/TD);
  float var = shs2[0]*(1.f/TD) - mu*mu;
  float rstd = rsqrtf(var + 1e-5f);
  for(int d=threadIdx.x; d<TD; d+=blockDim.x){
    float v = (xr[d]-mu)*rstd*w[d];
    y[(size_t)row*TD + d] = v;
    u16 h = h16(v);
    yh[(size_t)row*TD + d] = h;
    if (yl) yl[(size_t)row*TD + d] = h16(v - h2f(h));
  }
}

// ---------------- RoPE -> fp16 split ----------------
__global__ void rope_kernel(const float* __restrict__ qkv,
                            const float* __restrict__ cosb,
                            const float* __restrict__ sinb,
                            u16* __restrict__ qh, u16* __restrict__ ql){
  int idx = blockIdx.x*blockDim.x + threadIdx.x;
  const int total = TT*(TH+TKV)*(THD/2);
  if (idx >= total) return;
  int i  = idx & 63;
  int rest = idx >> 6;
  int hh = rest % (TH+TKV);
  int t  = rest / (TH+TKV);
  int s  = t % TS_;
  float c  = cosb[s*THD + i];
  float sn = sinb[s*THD + i];
  const float* p = qkv + (size_t)t*OQKV + hh*THD;
  float x1 = p[i], x2 = p[i+64];
  float r1 = x1*c - x2*sn;
  float r2 = x2*c + x1*sn;
  size_t o = (size_t)t*OQKV + hh*THD;
  u16 h1 = h16(r1), h2 = h16(r2);
  qh[o+i] = h1;    ql[o+i]    = h16(r1 - h2f(h1));
  qh[o+i+64] = h2; ql[o+i+64] = h16(r2 - h2f(h2));
}

// ---------------- causal softmax -> fp16 split P ----------------
__global__ void softmax_kernel(const float* __restrict__ s,
                               u16* __restrict__ ph, u16* __restrict__ pl){
  int row = blockIdx.x;
  int q = row % TS_;
  int L = q + 1;
  int pad = ((q>>7)+1)<<7;
  const float* r = s + (size_t)row*TS_;
  u16* oh = ph + (size_t)row*TS_;
  u16* ol = pl + (size_t)row*TS_;
  int tid = threadIdx.x;
  int lane = tid&31, wp = tid>>5;
  __shared__ float sh[8];

  float mx = -1e30f;
  for(int d=tid; d<L; d+=256) mx = fmaxf(mx, r[d]);
  mx = warp_max(mx);
  if(!lane) sh[wp]=mx;
  __syncthreads();
  if (tid<32){ float v=(tid<8)?sh[tid]:-1e30f; v=warp_max(v); if(!tid) sh[0]=v; }
  __syncthreads();
  mx = sh[0];
  __syncthreads();

  float sum = 0.f;
  for(int d=tid; d<L; d+=256) sum += __expf(r[d]-mx);
  sum = warp_sum(sum);
  if(!lane) sh[wp]=sum;
  __syncthreads();
  if (tid<32){ float v=(tid<8)?sh[tid]:0.f; v=warp_sum(v); if(!tid) sh[0]=v; }
  __syncthreads();
  float inv = 1.f/sh[0];

  for(int d=tid; d<L; d+=256){
    float p = __expf(r[d]-mx)*inv;
    u16 h = h16(p);
    oh[d] = h;
    ol[d] = h16(p - h2f(h));
  }
  for(int d=L+tid; d<pad; d+=256){ oh[d]=0; ol[d]=0; }
}

// ---------------- elementwise ----------------
__global__ void zero_kernel(float* __restrict__ p, int n){
  int i = blockIdx.x*blockDim.x + threadIdx.x;
  if (i<n) p[i]=0.f;
}
__global__ void zero_cnt_kernel(){
  if (threadIdx.x < TE) g_ecnt[threadIdx.x]=0;
}

// ---------------- router ----------------
__global__ void router_kernel(const float* __restrict__ x, const float* __restrict__ wr){
  int t = blockIdx.x;
  int tid = threadIdx.x;
  const float* xr = x + (size_t)t*TD;
  float acc[TE];
  #pragma unroll
  for(int e=0;e<TE;e++) acc[e]=0.f;
  for(int d=tid; d<TD; d+=128){
    float xv = xr[d];
    #pragma unroll
    for(int e=0;e<TE;e++) acc[e] += xv*wr[e*TD+d];
  }
  __shared__ float sh[TE][4];
  int lane=tid&31, wp=tid>>5;
  #pragma unroll
  for(int e=0;e<TE;e++){
    float v = warp_sum(acc[e]);
    if(!lane) sh[e][wp]=v;
  }
  __syncthreads();
  if (tid==0){
    float lg[TE];
    float mx=-1e30f;
    #pragma unroll
    for(int e=0;e<TE;e++){ lg[e]=sh[e][0]+sh[e][1]+sh[e][2]+sh[e][3]; mx=fmaxf(mx,lg[e]); }
    float p[TE]; float s=0.f;
    #pragma unroll
    for(int e=0;e<TE;e++){ p[e]=expf(lg[e]-mx); s+=p[e]; }
    float inv=1.f/s;
    #pragma unroll
    for(int e=0;e<TE;e++) p[e]*=inv;
    int e0=0;
    #pragma unroll
    for(int e=1;e<TE;e++) if (p[e]>p[e0]) e0=e;
    int e1=-1;
    #pragma unroll
    for(int e=0;e<TE;e++){ if(e==e0) continue; if (e1<0 || p[e]>p[e1]) e1=e; }
    float w0=p[e0], w1=p[e1];
    float tot = w0+w1;
    w0/=tot; w1/=tot;
    int pos = atomicAdd(&g_ecnt[e0],1);
    g_elist[e0*TT+pos]=t; g_ew[e0*TT+pos]=w0;
    pos = atomicAdd(&g_ecnt[e1],1);
    g_elist[e1*TT+pos]=t; g_ew[e1*TT+pos]=w1;
  }
}

// ---------------- launcher ----------------
extern "C" void kernel_launch(void* const* d_in, const int* in_sizes, int n_in,
                              void* d_out, int out_size){
  const float* hidden  = (const float*)d_in[0];
  const float* cosb    = (const float*)d_in[1];
  const float* sinb    = (const float*)d_in[2];
  const float* ln1w    = (const float*)d_in[3];
  const float* ln2w    = (const float*)d_in[4];
  const float* wqkv    = (const float*)d_in[5];
  const float* wout    = (const float*)d_in[6];
  const float* wrouter = (const float*)d_in[7];
  const float* wgate   = (const float*)d_in[8];
  const float* wup     = (const float*)d_in[9];
  const float* wdown   = (const float*)d_in[10];
  float* out = (float*)d_out;

  float *p_h,*p_qkv,*p_scores,*p_res,*p_ew;
  int *p_elist,*p_ecnt;
  u16 *p_wqkv,*p_wout,*p_wgu,*p_wd;
  u16 *p_xh,*p_xl,*p_ah,*p_al,*p_gh,*p_qh,*p_ql,*p_ph,*p_pl,*p_vt;
  cudaGetSymbolAddress((void**)&p_h, g_h);
  cudaGetSymbolAddress((void**)&p_qkv, g_qkv);
  cudaGetSymbolAddress((void**)&p_scores, g_scores);
  cudaGetSymbolAddress((void**)&p_res, g_res);
  cudaGetSymbolAddress((void**)&p_ew, g_ew);
  cudaGetSymbolAddress((void**)&p_elist, g_elist);
  cudaGetSymbolAddress((void**)&p_ecnt, g_ecnt);
  cudaGetSymbolAddress((void**)&p_wqkv, g_wqkv_h);
  cudaGetSymbolAddress((void**)&p_wout, g_wout_h);
  cudaGetSymbolAddress((void**)&p_wgu, g_wgu_h);
  cudaGetSymbolAddress((void**)&p_wd, g_wd_h);
  cudaGetSymbolAddress((void**)&p_xh, g_xh);
  cudaGetSymbolAddress((void**)&p_xl, g_xl);
  cudaGetSymbolAddress((void**)&p_ah, g_ah);
  cudaGetSymbolAddress((void**)&p_al, g_al);
  cudaGetSymbolAddress((void**)&p_gh, g_gh);
  cudaGetSymbolAddress((void**)&p_qh, g_qh);
  cudaGetSymbolAddress((void**)&p_ql, g_ql);
  cudaGetSymbolAddress((void**)&p_ph, g_ph);
  cudaGetSymbolAddress((void**)&p_pl, g_pl);
  cudaGetSymbolAddress((void**)&p_vt, g_vt);

  const int SMEM_S = 2*3*MATB;   // split stages
  const int SMEM_N = 2*2*MATB;   // non-split
  cudaFuncSetAttribute(tgemm<0,false,0,true>,  cudaFuncAttributeMaxDynamicSharedMemorySize, SMEM_S);
  cudaFuncSetAttribute(tgemm<0,false,1,true>,  cudaFuncAttributeMaxDynamicSharedMemorySize, SMEM_S);
  cudaFuncSetAttribute(tgemm<4,false,2,true>,  cudaFuncAttributeMaxDynamicSharedMemorySize, SMEM_S);
  cudaFuncSetAttribute(tgemm<2,false,0,true>,  cudaFuncAttributeMaxDynamicSharedMemorySize, SMEM_S);
  cudaFuncSetAttribute(tgemm<1,true,3,false>,  cudaFuncAttributeMaxDynamicSharedMemorySize, SMEM_N);
  cudaFuncSetAttribute(tgemm<3,false,4,false>, cudaFuncAttributeMaxDynamicSharedMemorySize, SMEM_N);

  const int n_td = TT*TD;
  float* resid = (out_size >= 2*n_td) ? (out + (size_t)n_td) : p_res;

  // ---- fork side stream for independent weight conversions + output zero ----
  cudaStream_t s2;
  cudaStreamCreate(&s2);
  cudaEvent_t evFork, evJoin;
  cudaEventCreateWithFlags(&evFork, cudaEventDisableTiming);
  cudaEventCreateWithFlags(&evJoin, cudaEventDisableTiming);
  cudaEventRecord(evFork, 0);
  cudaStreamWaitEvent(s2, evFork, 0);

  // side stream: wout, wgate/wup/wdown conversions + out zeroing (no deps on attention)
  convhalf<<<(TD*TD/4+255)/256,256,0,s2>>>(wout, p_wout, TD*TD/4);
  transhalf<<<dim3(TF/32, TD/32, TE), dim3(32,8),0,s2>>>(wgate, p_wgu, TD, TF,
      (size_t)TD*TF, (size_t)2*TF*TD, 2, 0);
  transhalf<<<dim3(TF/32, TD/32, TE), dim3(32,8),0,s2>>>(wup, p_wgu, TD, TF,
      (size_t)TD*TF, (size_t)2*TF*TD, 2, 1);
  transhalf<<<dim3(TD/32, TF/32, TE), dim3(32,8),0,s2>>>(wdown, p_wd, TF, TD,
      (size_t)TF*TD, (size_t)TD*TF, 1, 0);
  zero_kernel<<<(n_td+255)/256,256,0,s2>>>(out, n_td);
  cudaEventRecord(evJoin, s2);

  // main stream: attention chain
  convhalf<<<(OQKV*TD/4+255)/256,256>>>(wqkv, p_wqkv, OQKV*TD/4);
  ln_kernel<<<TT,256>>>(hidden, ln1w, p_h, p_xh, p_xl);
  tgemm<0,false,0,true><<<dim3(OQKV/128, TT/128), 256, SMEM_S>>>(
      TT, OQKV, TD, p_xh, p_xl, TD, p_wqkv, TD,
      p_qkv, OQKV, 1.f, nullptr, nullptr, nullptr, 0,0,0);
  {
    int total = TT*(TH+TKV)*(THD/2);
    rope_kernel<<<(total+255)/256,256>>>(p_qkv, cosb, sinb, p_qh, p_ql);
  }
  vtrans<<<dim3(TS_/32, THD/32, TBATCH*TKV), dim3(32,8)>>>(p_qkv, p_vt);
  tgemm<0,false,1,true><<<dim3(TS_/128, TS_/128, TBATCH*TH), 256, SMEM_S>>>(
      TS_, TS_, THD, p_qh, p_ql, 0, p_qh, 0,
      p_scores, 0, 1.f/sqrtf((float)THD), nullptr, nullptr, nullptr, 0,0,0);
  softmax_kernel<<<TBATCH*TH*TS_,256>>>(p_scores, p_ph, p_pl);

  // PV with fused fp16 hi/lo split store -> ah/al
  tgemm<4,false,2,true><<<dim3(1, TS_/128, TBATCH*TH), 256, SMEM_S>>>(
      TS_, THD, TS_, p_ph, p_pl, 0, p_vt, 0,
      (float*)p_ah, 0, 1.f, nullptr, (const float*)p_al, nullptr, 0,0,0);

  // join side stream before out-proj (needs wout; also orders out zeroing)
  cudaStreamWaitEvent(0, evJoin, 0);

  // out-proj (split A) with fused residual add -> resid
  tgemm<2,false,0,true><<<dim3(TD/128, TT/128), 256, SMEM_S>>>(
      TT, TD, TH*THD, p_ah, p_al, TH*THD, p_wout, TH*THD,
      resid, TD, 1.f, nullptr, hidden, nullptr, 0,0,0);

  // LN2 (hi only — MoE uses single A)
  ln_kernel<<<TT,256>>>(resid, ln2w, p_h, p_xh, nullptr);

  // router
  zero_cnt_kernel<<<1,32>>>();
  router_kernel<<<TT,128>>>(p_h, wrouter);

  // MoE: GU GEMM with fused silu -> gh (fp16), then down (atomic scatter)
  tgemm<1,true,3,false><<<dim3(2*TF/128, TT/128, TE), 256, SMEM_N>>>(
      TT, 2*TF, TD, p_xh, nullptr, TD, p_wgu, TD,
      (float*)p_gh, 2*TF, 1.f, p_elist, nullptr, p_ecnt,
      0, (size_t)2*TF*TD, (size_t)TT*TF);
  tgemm<3,false,4,false><<<dim3(TD/128, TT/128, TE), 256, SMEM_N>>>(
      TT, TD, TF, p_gh, nullptr, TF, p_wd, TF,
      out, TD, 1.f, p_elist, p_ew, p_ecnt,
      (size_t)TT*TF, (size_t)TD*TF, 0);

  cudaStreamDestroy(s2);
  cudaEventDestroy(evFork);
  cudaEventDestroy(evJoin);
}

// round 11
// speedup vs baseline: 11.9870x; 1.0114x over previous
#include <cuda_runtime.h>
#include <cuda_fp16.h>
#include <math.h>
#include <stdint.h>

// Problem constants
#define TS_ 1024
#define TBATCH 2
#define TD 2048
#define TH 16
#define TKV 4
#define THD 128
#define TE 8
#define TF 2048
#define TT (TBATCH*TS_)            // 2048 tokens
#define OQKV ((TH+2*TKV)*THD)      // 3072
#define REP (TH/TKV)               // 4

typedef unsigned short u16;

// ---------------- scratch (device globals) ----------
__device__ float g_h[(size_t)TT*TD];
__device__ float g_qkv[(size_t)TT*OQKV];
__device__ float g_scores[(size_t)TBATCH*TH*TS_*TS_];
__device__ float g_res[(size_t)TT*TD];
__device__ int   g_elist[TE*TT];
__device__ float g_ew[TE*TT];
__device__ int   g_ecnt[TE];

// fp16 buffers
__device__ u16 g_wqkv_h[(size_t)OQKV*TD];
__device__ u16 g_wout_h[(size_t)TD*TD];
__device__ u16 g_wgu_h[(size_t)TE*2*TF*TD];    // [e][2F][D], rows interleaved gate/up
__device__ u16 g_wd_h[(size_t)TE*TD*TF];       // [e][D][F]
__device__ u16 g_xh[(size_t)TT*TD],  g_xl[(size_t)TT*TD];
__device__ u16 g_ah[(size_t)TT*TD],  g_al[(size_t)TT*TD];
__device__ u16 g_gh[(size_t)TE*TT*TF];
__device__ u16 g_qh[(size_t)TT*OQKV], g_ql[(size_t)TT*OQKV];
__device__ u16 g_ph[(size_t)TBATCH*TH*TS_*TS_], g_pl[(size_t)TBATCH*TH*TS_*TS_];
__device__ u16 g_vt[(size_t)TBATCH*TKV*THD*TS_];

// ---------------- helpers ----------------
__device__ __forceinline__ u16 h16(float x){
  __half h = __float2half_rn(x);
  return *reinterpret_cast<u16*>(&h);
}
__device__ __forceinline__ float h2f(u16 b){
  __half h = *reinterpret_cast<__half*>(&b);
  return __half2float(h);
}
__device__ __forceinline__ uint32_t smem_u32(const void* p){
  uint32_t a;
  asm("{ .reg .u64 t; cvta.to.shared.u64 t, %1; cvt.u32.u64 %0, t; }" : "=r"(a) : "l"(p));
  return a;
}
__device__ __forceinline__ void ldsm_x4(uint32_t* r, uint32_t addr){
  asm volatile("ldmatrix.sync.aligned.m8n8.x4.shared.b16 {%0,%1,%2,%3}, [%4];"
    : "=r"(r[0]),"=r"(r[1]),"=r"(r[2]),"=r"(r[3]) : "r"(addr));
}
__device__ __forceinline__ void mma16816(float* c, const uint32_t* a, const uint32_t* b){
  asm volatile("mma.sync.aligned.m16n8k16.row.col.f32.f16.f16.f32 "
    "{%0,%1,%2,%3}, {%4,%5,%6,%7}, {%8,%9}, {%0,%1,%2,%3};"
    : "+f"(c[0]),"+f"(c[1]),"+f"(c[2]),"+f"(c[3])
    : "r"(a[0]),"r"(a[1]),"r"(a[2]),"r"(a[3]), "r"(b[0]),"r"(b[1]));
}
__device__ __forceinline__ void cp16(uint32_t dst, const void* src, int ssz){
  asm volatile("cp.async.cg.shared.global [%0], [%1], 16, %2;"
    :: "r"(dst), "l"(src), "r"(ssz) : "memory");
}
__device__ __forceinline__ void cp16f(uint32_t dst, const void* src){
  asm volatile("cp.async.cg.shared.global [%0], [%1], 16;"
    :: "r"(dst), "l"(src) : "memory");
}
#define CP_COMMIT() asm volatile("cp.async.commit_group;":::"memory")
#define CP_WAIT(n)  asm volatile("cp.async.wait_group %0;"::"n"(n):"memory")

// ---------------- conversion kernels ----------------
__global__ void convhalf(const float* __restrict__ src, u16* __restrict__ d, int n4){
  int i = blockIdx.x*blockDim.x + threadIdx.x;
  if (i >= n4) return;
  float4 v = reinterpret_cast<const float4*>(src)[i];
  ushort4 hv; hv.x=h16(v.x); hv.y=h16(v.y); hv.z=h16(v.z); hv.w=h16(v.w);
  reinterpret_cast<ushort4*>(d)[i]=hv;
}
// transpose [R,C] -> [C,R] fp16; dst row = rmul*c + roff (for gate/up interleave)
__global__ void transhalf(const float* __restrict__ src, u16* __restrict__ dst,
                          int R, int C, size_t sstr, size_t dstr, int rmul, int roff){
  __shared__ float t[32][33];
  src += (size_t)blockIdx.z * sstr;
  dst += (size_t)blockIdx.z * dstr;
  int c0 = blockIdx.x*32, r0 = blockIdx.y*32;
  int tx = threadIdx.x, ty = threadIdx.y;
  #pragma unroll
  for (int j=0;j<4;j++)
    t[ty+j*8][tx] = src[(size_t)(r0+ty+j*8)*C + c0+tx];
  __syncthreads();
  #pragma unroll
  for (int j=0;j<4;j++)
    dst[(size_t)(rmul*(c0+ty+j*8)+roff)*R + r0+tx] = h16(t[tx][ty+j*8]);
}
__global__ void vtrans(const float* __restrict__ qkv, u16* __restrict__ vt){
  __shared__ float t[32][33];
  int z = blockIdx.z; int b = z/TKV, kv = z%TKV;
  int s0 = blockIdx.x*32, h0 = blockIdx.y*32;
  int tx = threadIdx.x, ty = threadIdx.y;
  #pragma unroll
  for (int j=0;j<4;j++){
    int s = s0+ty+j*8;
    t[ty+j*8][tx] = qkv[(size_t)(b*TS_+s)*OQKV + (TH+TKV+kv)*THD + h0+tx];
  }
  __syncthreads();
  #pragma unroll
  for (int j=0;j<4;j++){
    int hd = h0+ty+j*8;
    vt[((size_t)z*THD + hd)*TS_ + s0+tx] = h16(t[tx][ty+j*8]);
  }
}

// ---------------- tensor-core GEMM (fp16, optional A hi/lo split) ----------
// C[M,N] = alpha * (Ah[+Al])[M,K] @ Bh[N,K]^T     BK=64 cp.async pipeline
// Pipeline depth: split=2 stages, non-split=3 stages (fits 2 CTA/SM both ways)
// EPI 0: store fp32. EPI 1: fused silu(gate)*up -> fp16 (interleaved cols).
// EPI 2: store + hres add. EPI 3: atomicAdd C[arow[m]] += aw[m]*v.
// EPI 4: fp16 hi/lo split store (C=hi base, aw=lo base).
// ADDR 0: plain. 1: attn scores. 2: PV. 3: expert-batched gather.
// 4: expert-batched (A per-expert) atomic scatter.
#define TPAD 144
#define MATB (128*TPAD)   // 18432

template<int EPI, bool GATHER, int ADDR, bool ASPLIT>
__global__ __launch_bounds__(256,2) void tgemm(
    int M, int N, int K,
    const u16* __restrict__ Ah, const u16* __restrict__ Al, int lda,
    const u16* __restrict__ Bh, int ldb,
    float* __restrict__ C, int ldc, float alpha,
    const int* __restrict__ arow, const float* __restrict__ aw,
    const int* __restrict__ cntp,
    size_t astride, size_t bstride, size_t cstride)
{
  constexpr int NMAT = ASPLIT ? 3 : 2;
  constexpr int NST  = ASPLIT ? 2 : 3;     // pipeline stages
  constexpr int STB  = NMAT*MATB;
  constexpr int BOFF = (ASPLIT ? 2 : 1)*MATB;
  extern __shared__ __align__(16) char smem[];
  int row0 = blockIdx.y*128, col0 = blockIdx.x*128;
  int Klim = K;
  size_t cbase = 0;

  if (ADDR==1){
    if (col0 > row0 + 127) return;
    int z = blockIdx.z, b = z/TH, h = z%TH;
    size_t off = (size_t)b*TS_*OQKV + h*THD;
    Ah += off; if (ASPLIT) Al += off;
    lda = OQKV;
    Bh += (size_t)b*TS_*OQKV + (TH + h/REP)*THD;
    ldb = OQKV;
    C  += (size_t)z*TS_*TS_;
    ldc = TS_;
  } else if (ADDR==2){
    int z = blockIdx.z, b = z/TH, h = z%TH;
    size_t off = (size_t)z*TS_*TS_;
    Ah += off; if (ASPLIT) Al += off;
    lda = TS_;
    Bh += ((size_t)(b*TKV + h/REP))*THD*TS_;
    ldb = TS_;
    cbase = (size_t)b*TS_*(TH*THD) + h*THD;
    if (EPI != 4) C += cbase;
    ldc = TH*THD;
    Klim = min(K, row0 + 128);
  } else if (ADDR==3 || ADDR==4){
    int z = blockIdx.z;
    arow += z*TT;
    if (ADDR==4){ aw += z*TT; Ah += (size_t)z*astride; }
    cntp += z;
    Bh += (size_t)z*bstride;
    if (EPI != 1) C += (size_t)z*cstride;
  }

  int Meff = cntp ? *cntp : M;
  if (row0 >= Meff) return;

  int tid = threadIdx.x, wid = tid>>5, lane = tid&31;
  int wm = wid>>2, wn = wid&3;
  uint32_t sbase = smem_u32(smem);

  uint32_t laneA  = (uint32_t)((lane&15)*TPAD) + (uint32_t)((lane>>4)*16);
  uint32_t laneB4 = (uint32_t)((lane&7)*TPAD) + (uint32_t)(((lane>>3)&1)*16)
                  + (uint32_t)((lane>>4)*(8*TPAD));

  float acc[4][4][4];
  #pragma unroll
  for(int i=0;i<4;i++)
    #pragma unroll
    for(int j=0;j<4;j++)
      #pragma unroll
      for(int q=0;q<4;q++) acc[i][j][q]=0.f;

  const int NC = Klim/64;

  int c16 = tid&7, rt = tid>>3;     // rt 0..31
  uint32_t doff0 = (uint32_t)(rt*TPAD + c16*16);
  long aoff[4]; int apred[4];
  #pragma unroll
  for (int it=0; it<4; it++){
    int gm = row0 + rt + it*32;
    apred[it] = gm < Meff;
    long src = apred[it] ? ((GATHER||ADDR==3) ? (long)arow[gm] : (long)gm) : 0;
    aoff[it] = src*(long)lda + c16*8;
  }
  const u16* pb0 = Bh + (long)(col0 + rt)*ldb + c16*8;

  auto issue = [&](int c){
    uint32_t dst0 = sbase + (c%NST)*STB;
    int k0 = c*64;
    #pragma unroll
    for (int it=0; it<4; it++){
      uint32_t d = dst0 + doff0 + it*32*TPAD;
      int ssz = apred[it] ? 16 : 0;
      cp16(d, Ah + aoff[it] + k0, ssz);
      if (ASPLIT) cp16(d + MATB, Al + aoff[it] + k0, ssz);
      cp16f(d + BOFF, pb0 + (long)it*32*ldb + k0);
    }
    CP_COMMIT();
  };

  issue(0);
  if (NST >= 3 && NC > 1) issue(1);
  for (int c = 0; c < NC; c++){
    if (NST == 2){
      if (c+1 < NC){ issue(c+1); CP_WAIT(1); }
      else         { CP_WAIT(0); }
    } else {
      if (c+2 < NC){ issue(c+2); CP_WAIT(2); }
      else if (c+2 == NC){ CP_WAIT(1); }
      else { CP_WAIT(0); }
    }
    __syncthreads();

    uint32_t st = sbase + (c%NST)*STB;
    #pragma unroll
    for (int ks = 0; ks < 4; ks++){
      uint32_t rowA = st + (uint32_t)((wm*64)*TPAD + ks*32) + laneA;
      uint32_t rowB = st + BOFF + (uint32_t)((wn*32)*TPAD + ks*32) + laneB4;
      uint32_t aH[4][4], bH[4][2];
      #pragma unroll
      for (int mf=0; mf<4; mf++) ldsm_x4(aH[mf], rowA + mf*16*TPAD);
      #pragma unroll
      for (int np=0; np<2; np++){
        uint32_t t4[4];
        ldsm_x4(t4, rowB + np*16*TPAD);
        bH[2*np][0]=t4[0]; bH[2*np][1]=t4[1];
        bH[2*np+1][0]=t4[2]; bH[2*np+1][1]=t4[3];
      }
      #pragma unroll
      for (int mf=0; mf<4; mf++)
        #pragma unroll
        for (int nf=0; nf<4; nf++) mma16816(acc[mf][nf], aH[mf], bH[nf]);
      if (ASPLIT){
        uint32_t aL[4][4];
        #pragma unroll
        for (int mf=0; mf<4; mf++) ldsm_x4(aL[mf], rowA + MATB + mf*16*TPAD);
        #pragma unroll
        for (int mf=0; mf<4; mf++)
          #pragma unroll
          for (int nf=0; nf<4; nf++) mma16816(acc[mf][nf], aL[mf], bH[nf]);
      }
    }
    __syncthreads();
  }

  // ---- epilogue ----
  int g = lane>>2, tig = lane&3;
  u16* G = nullptr;
  if (EPI == 1) G = reinterpret_cast<u16*>(C) + (size_t)blockIdx.z*cstride;
  u16* Oh = nullptr; u16* Ol = nullptr;
  if (EPI == 4){
    Oh = reinterpret_cast<u16*>(C) + cbase;
    Ol = const_cast<u16*>(reinterpret_cast<const u16*>(aw)) + cbase;
  }
  #pragma unroll
  for (int mf=0; mf<4; mf++){
    int ra = row0 + wm*64 + mf*16 + g;
    int rb = ra + 8;
    #pragma unroll
    for (int nf=0; nf<4; nf++){
      int col = col0 + wn*32 + nf*8 + tig*2;
      float* cacc = acc[mf][nf];
      if (EPI == 0){
        if (ra < Meff){
          float* p = C + (size_t)ra*ldc + col;
          p[0] = cacc[0]*alpha; p[1] = cacc[1]*alpha;
        }
        if (rb < Meff){
          float* p = C + (size_t)rb*ldc + col;
          p[0] = cacc[2]*alpha; p[1] = cacc[3]*alpha;
        }
      } else if (EPI == 1){
        int f = col >> 1;
        if (ra < Meff){
          float gg = cacc[0];
          G[(size_t)ra*(ldc>>1) + f] = h16((gg/(1.f+__expf(-gg)))*cacc[1]);
        }
        if (rb < Meff){
          float gg = cacc[2];
          G[(size_t)rb*(ldc>>1) + f] = h16((gg/(1.f+__expf(-gg)))*cacc[3]);
        }
      } else if (EPI == 2){
        if (ra < Meff){
          float* p = C + (size_t)ra*ldc + col;
          const float* hr = aw + (size_t)ra*ldc + col;
          p[0] = cacc[0]*alpha + hr[0]; p[1] = cacc[1]*alpha + hr[1];
        }
        if (rb < Meff){
          float* p = C + (size_t)rb*ldc + col;
          const float* hr = aw + (size_t)rb*ldc + col;
          p[0] = cacc[2]*alpha + hr[0]; p[1] = cacc[3]*alpha + hr[1];
        }
      } else if (EPI == 4){
        if (ra < Meff){
          size_t o = (size_t)ra*ldc + col;
          float v0 = cacc[0]*alpha, v1 = cacc[1]*alpha;
          u16 h0 = h16(v0), h1 = h16(v1);
          Oh[o] = h0;   Oh[o+1] = h1;
          Ol[o] = h16(v0 - h2f(h0)); Ol[o+1] = h16(v1 - h2f(h1));
        }
        if (rb < Meff){
          size_t o = (size_t)rb*ldc + col;
          float v0 = cacc[2]*alpha, v1 = cacc[3]*alpha;
          u16 h0 = h16(v0), h1 = h16(v1);
          Oh[o] = h0;   Oh[o+1] = h1;
          Ol[o] = h16(v0 - h2f(h0)); Ol[o+1] = h16(v1 - h2f(h1));
        }
      } else {
        if (ra < Meff){
          float w = aw[ra];
          float* p = C + (size_t)arow[ra]*ldc + col;
          atomicAdd(p,   w*cacc[0]*alpha);
          atomicAdd(p+1, w*cacc[1]*alpha);
        }
        if (rb < Meff){
          float w = aw[rb];
          float* p = C + (size_t)arow[rb]*ldc + col;
          atomicAdd(p,   w*cacc[2]*alpha);
          atomicAdd(p+1, w*cacc[3]*alpha);
        }
      }
    }
  }
}

// ---------------- reduction helpers ----------------
__device__ __forceinline__ float warp_sum(float v){
  #pragma unroll
  for(int o=16;o;o>>=1) v += __shfl_xor_sync(0xffffffffu, v, o);
  return v;
}
__device__ __forceinline__ float warp_max(float v){
  #pragma unroll
  for(int o=16;o;o>>=1) v = fmaxf(v, __shfl_xor_sync(0xffffffffu, v, o));
  return v;
}

// ---------------- LayerNorm (fp32 + fp16 hi[/lo]) ----------------
__global__ void ln_kernel(const float* __restrict__ x, const float* __restrict__ w,
                          float* __restrict__ y, u16* __restrict__ yh, u16* __restrict__ yl){
  int row = blockIdx.x;
  const float* xr = x + (size_t)row*TD;
  float s=0.f, s2=0.f;
  for(int d=threadIdx.x; d<TD; d+=blockDim.x){ float v=xr[d]; s+=v; s2+=v*v; }
  __shared__ float shs[8], shs2[8];
  int lane=threadIdx.x&31, wp=threadIdx.x>>5;
  s = warp_sum(s); s2 = warp_sum(s2);
  if(!lane){ shs[wp]=s; shs2[wp]=s2; }
  __syncthreads();
  if (threadIdx.x < 32){
    float a = (threadIdx.x<8)? shs[threadIdx.x] : 0.f;
    float b = (threadIdx.x<8)? shs2[threadIdx.x] : 0.f;
    a = warp_sum(a); b = warp_sum(b);
    if(!threadIdx.x){ shs[0]=a; shs2[0]=b; }
  }
  __syncthreads();
  float mu = shs[0]*(1.f/TD);
  float var = shs2[0]*(1.f/TD) - mu*mu;
  float rstd = rsqrtf(var + 1e-5f);
  for(int d=threadIdx.x; d<TD; d+=blockDim.x){
    float v = (xr[d]-mu)*rstd*w[d];
    y[(size_t)row*TD + d] = v;
    u16 h = h16(v);
    yh[(size_t)row*TD + d] = h;
    if (yl) yl[(size_t)row*TD + d] = h16(v - h2f(h));
  }
}

// ---------------- RoPE -> fp16 split ----------------
__global__ void rope_kernel(const float* __restrict__ qkv,
                            const float* __restrict__ cosb,
                            const float* __restrict__ sinb,
                            u16* __restrict__ qh, u16* __restrict__ ql){
  int idx = blockIdx.x*blockDim.x + threadIdx.x;
  const int total = TT*(TH+TKV)*(THD/2);
  if (idx >= total) return;
  int i  = idx & 63;
  int rest = idx >> 6;
  int hh = rest % (TH+TKV);
  int t  = rest / (TH+TKV);
  int s  = t % TS_;
  float c  = cosb[s*THD + i];
  float sn = sinb[s*THD + i];
  const float* p = qkv + (size_t)t*OQKV + hh*THD;
  float x1 = p[i], x2 = p[i+64];
  float r1 = x1*c - x2*sn;
  float r2 = x2*c + x1*sn;
  size_t o = (size_t)t*OQKV + hh*THD;
  u16 h1 = h16(r1), h2 = h16(r2);
  qh[o+i] = h1;    ql[o+i]    = h16(r1 - h2f(h1));
  qh[o+i+64] = h2; ql[o+i+64] = h16(r2 - h2f(h2));
}

// ---------------- causal softmax -> fp16 split P (single exp pass) --------
__global__ void softmax_kernel(const float* __restrict__ s,
                               u16* __restrict__ ph, u16* __restrict__ pl){
  int row = blockIdx.x;
  int q = row % TS_;
  int L = q + 1;
  int pad = ((q>>7)+1)<<7;
  const float* r = s + (size_t)row*TS_;
  u16* oh = ph + (size_t)row*TS_;
  u16* ol = pl + (size_t)row*TS_;
  int tid = threadIdx.x;
  int lane = tid&31, wp = tid>>5;
  __shared__ float sh[8];

  float mx = -1e30f;
  for(int d=tid; d<L; d+=256) mx = fmaxf(mx, r[d]);
  mx = warp_max(mx);
  if(!lane) sh[wp]=mx;
  __syncthreads();
  if (tid<32){ float v=(tid<8)?sh[tid]:-1e30f; v=warp_max(v); if(!tid) sh[0]=v; }
  __syncthreads();
  mx = sh[0];
  __syncthreads();

  float ev[4];
  int cnt = 0;
  float sum = 0.f;
  for(int d=tid; d<L; d+=256){
    float e = __expf(r[d]-mx);
    ev[cnt++] = e;
    sum += e;
  }
  sum = warp_sum(sum);
  if(!lane) sh[wp]=sum;
  __syncthreads();
  if (tid<32){ float v=(tid<8)?sh[tid]:0.f; v=warp_sum(v); if(!tid) sh[0]=v; }
  __syncthreads();
  float inv = 1.f/sh[0];

  cnt = 0;
  for(int d=tid; d<L; d+=256){
    float p = ev[cnt++]*inv;
    u16 h = h16(p);
    oh[d] = h;
    ol[d] = h16(p - h2f(h));
  }
  for(int d=L+tid; d<pad; d+=256){ oh[d]=0; ol[d]=0; }
}

// ---------------- elementwise ----------------
__global__ void zero_kernel(float* __restrict__ p, int n){
  int i = blockIdx.x*blockDim.x + threadIdx.x;
  if (i<n) p[i]=0.f;
}
__global__ void zero_cnt_kernel(){
  if (threadIdx.x < TE) g_ecnt[threadIdx.x]=0;
}

// ---------------- router ----------------
__global__ void router_kernel(const float* __restrict__ x, const float* __restrict__ wr){
  int t = blockIdx.x;
  int tid = threadIdx.x;
  const float* xr = x + (size_t)t*TD;
  float acc[TE];
  #pragma unroll
  for(int e=0;e<TE;e++) acc[e]=0.f;
  for(int d=tid; d<TD; d+=128){
    float xv = xr[d];
    #pragma unroll
    for(int e=0;e<TE;e++) acc[e] += xv*wr[e*TD+d];
  }
  __shared__ float sh[TE][4];
  int lane=tid&31, wp=tid>>5;
  #pragma unroll
  for(int e=0;e<TE;e++){
    float v = warp_sum(acc[e]);
    if(!lane) sh[e][wp]=v;
  }
  __syncthreads();
  if (tid==0){
    float lg[TE];
    float mx=-1e30f;
    #pragma unroll
    for(int e=0;e<TE;e++){ lg[e]=sh[e][0]+sh[e][1]+sh[e][2]+sh[e][3]; mx=fmaxf(mx,lg[e]); }
    float p[TE]; float s=0.f;
    #pragma unroll
    for(int e=0;e<TE;e++){ p[e]=expf(lg[e]-mx); s+=p[e]; }
    float inv=1.f/s;
    #pragma unroll
    for(int e=0;e<TE;e++) p[e]*=inv;
    int e0=0;
    #pragma unroll
    for(int e=1;e<TE;e++) if (p[e]>p[e0]) e0=e;
    int e1=-1;
    #pragma unroll
    for(int e=0;e<TE;e++){ if(e==e0) continue; if (e1<0 || p[e]>p[e1]) e1=e; }
    float w0=p[e0], w1=p[e1];
    float tot = w0+w1;
    w0/=tot; w1/=tot;
    int pos = atomicAdd(&g_ecnt[e0],1);
    g_elist[e0*TT+pos]=t; g_ew[e0*TT+pos]=w0;
    pos = atomicAdd(&g_ecnt[e1],1);
    g_elist[e1*TT+pos]=t; g_ew[e1*TT+pos]=w1;
  }
}

// ---------------- launcher ----------------
extern "C" void kernel_launch(void* const* d_in, const int* in_sizes, int n_in,
                              void* d_out, int out_size){
  const float* hidden  = (const float*)d_in[0];
  const float* cosb    = (const float*)d_in[1];
  const float* sinb    = (const float*)d_in[2];
  const float* ln1w    = (const float*)d_in[3];
  const float* ln2w    = (const float*)d_in[4];
  const float* wqkv    = (const float*)d_in[5];
  const float* wout    = (const float*)d_in[6];
  const float* wrouter = (const float*)d_in[7];
  const float* wgate   = (const float*)d_in[8];
  const float* wup     = (const float*)d_in[9];
  const float* wdown   = (const float*)d_in[10];
  float* out = (float*)d_out;

  float *p_h,*p_qkv,*p_scores,*p_res,*p_ew;
  int *p_elist,*p_ecnt;
  u16 *p_wqkv,*p_wout,*p_wgu,*p_wd;
  u16 *p_xh,*p_xl,*p_ah,*p_al,*p_gh,*p_qh,*p_ql,*p_ph,*p_pl,*p_vt;
  cudaGetSymbolAddress((void**)&p_h, g_h);
  cudaGetSymbolAddress((void**)&p_qkv, g_qkv);
  cudaGetSymbolAddress((void**)&p_scores, g_scores);
  cudaGetSymbolAddress((void**)&p_res, g_res);
  cudaGetSymbolAddress((void**)&p_ew, g_ew);
  cudaGetSymbolAddress((void**)&p_elist, g_elist);
  cudaGetSymbolAddress((void**)&p_ecnt, g_ecnt);
  cudaGetSymbolAddress((void**)&p_wqkv, g_wqkv_h);
  cudaGetSymbolAddress((void**)&p_wout, g_wout_h);
  cudaGetSymbolAddress((void**)&p_wgu, g_wgu_h);
  cudaGetSymbolAddress((void**)&p_wd, g_wd_h);
  cudaGetSymbolAddress((void**)&p_xh, g_xh);
  cudaGetSymbolAddress((void**)&p_xl, g_xl);
  cudaGetSymbolAddress((void**)&p_ah, g_ah);
  cudaGetSymbolAddress((void**)&p_al, g_al);
  cudaGetSymbolAddress((void**)&p_gh, g_gh);
  cudaGetSymbolAddress((void**)&p_qh, g_qh);
  cudaGetSymbolAddress((void**)&p_ql, g_ql);
  cudaGetSymbolAddress((void**)&p_ph, g_ph);
  cudaGetSymbolAddress((void**)&p_pl, g_pl);
  cudaGetSymbolAddress((void**)&p_vt, g_vt);

  const int SMEM_S = 2*3*MATB;   // split: 2 stages x 3 mats
  const int SMEM_N = 3*2*MATB;   // non-split: 3 stages x 2 mats
  cudaFuncSetAttribute(tgemm<0,false,0,true>,  cudaFuncAttributeMaxDynamicSharedMemorySize, SMEM_S);
  cudaFuncSetAttribute(tgemm<0,false,1,true>,  cudaFuncAttributeMaxDynamicSharedMemorySize, SMEM_S);
  cudaFuncSetAttribute(tgemm<4,false,2,true>,  cudaFuncAttributeMaxDynamicSharedMemorySize, SMEM_S);
  cudaFuncSetAttribute(tgemm<2,false,0,true>,  cudaFuncAttributeMaxDynamicSharedMemorySize, SMEM_S);
  cudaFuncSetAttribute(tgemm<1,true,3,false>,  cudaFuncAttributeMaxDynamicSharedMemorySize, SMEM_N);
  cudaFuncSetAttribute(tgemm<3,false,4,false>, cudaFuncAttributeMaxDynamicSharedMemorySize, SMEM_N);

  const int n_td = TT*TD;
  float* resid = (out_size >= 2*n_td) ? (out + (size_t)n_td) : p_res;

  // ---- fork side stream for independent weight conversions + output zero ----
  cudaStream_t s2;
  cudaStreamCreate(&s2);
  cudaEvent_t evFork, evJoin;
  cudaEventCreateWithFlags(&evFork, cudaEventDisableTiming);
  cudaEventCreateWithFlags(&evJoin, cudaEventDisableTiming);
  cudaEventRecord(evFork, 0);
  cudaStreamWaitEvent(s2, evFork, 0);

  // side stream: wout, wgate/wup/wdown conversions + out zeroing
  convhalf<<<(TD*TD/4+255)/256,256,0,s2>>>(wout, p_wout, TD*TD/4);
  transhalf<<<dim3(TF/32, TD/32, TE), dim3(32,8),0,s2>>>(wgate, p_wgu, TD, TF,
      (size_t)TD*TF, (size_t)2*TF*TD, 2, 0);
  transhalf<<<dim3(TF/32, TD/32, TE), dim3(32,8),0,s2>>>(wup, p_wgu, TD, TF,
      (size_t)TD*TF, (size_t)2*TF*TD, 2, 1);
  transhalf<<<dim3(TD/32, TF/32, TE), dim3(32,8),0,s2>>>(wdown, p_wd, TF, TD,
      (size_t)TF*TD, (size_t)TD*TF, 1, 0);
  zero_kernel<<<(n_td+255)/256,256,0,s2>>>(out, n_td);
  cudaEventRecord(evJoin, s2);

  // main stream: attention chain
  convhalf<<<(OQKV*TD/4+255)/256,256>>>(wqkv, p_wqkv, OQKV*TD/4);
  ln_kernel<<<TT,256>>>(hidden, ln1w, p_h, p_xh, p_xl);
  tgemm<0,false,0,true><<<dim3(OQKV/128, TT/128), 256, SMEM_S>>>(
      TT, OQKV, TD, p_xh, p_xl, TD, p_wqkv, TD,
      p_qkv, OQKV, 1.f, nullptr, nullptr, nullptr, 0,0,0);
  {
    int total = TT*(TH+TKV)*(THD/2);
    rope_kernel<<<(total+255)/256,256>>>(p_qkv, cosb, sinb, p_qh, p_ql);
  }
  vtrans<<<dim3(TS_/32, THD/32, TBATCH*TKV), dim3(32,8)>>>(p_qkv, p_vt);
  tgemm<0,false,1,true><<<dim3(TS_/128, TS_/128, TBATCH*TH), 256, SMEM_S>>>(
      TS_, TS_, THD, p_qh, p_ql, 0, p_qh, 0,
      p_scores, 0, 1.f/sqrtf((float)THD), nullptr, nullptr, nullptr, 0,0,0);
  softmax_kernel<<<TBATCH*TH*TS_,256>>>(p_scores, p_ph, p_pl);

  // PV with fused fp16 hi/lo split store -> ah/al
  tgemm<4,false,2,true><<<dim3(1, TS_/128, TBATCH*TH), 256, SMEM_S>>>(
      TS_, THD, TS_, p_ph, p_pl, 0, p_vt, 0,
      (float*)p_ah, 0, 1.f, nullptr, (const float*)p_al, nullptr, 0,0,0);

  // join side stream before out-proj
  cudaStreamWaitEvent(0, evJoin, 0);

  // out-proj (split A) with fused residual add -> resid
  tgemm<2,false,0,true><<<dim3(TD/128, TT/128), 256, SMEM_S>>>(
      TT, TD, TH*THD, p_ah, p_al, TH*THD, p_wout, TH*THD,
      resid, TD, 1.f, nullptr, hidden, nullptr, 0,0,0);

  // LN2 (hi only)
  ln_kernel<<<TT,256>>>(resid, ln2w, p_h, p_xh, nullptr);

  // router
  zero_cnt_kernel<<<1,32>>>();
  router_kernel<<<TT,128>>>(p_h, wrouter);

  // MoE: GU GEMM with fused silu -> gh (fp16), then down (atomic scatter)
  tgemm<1,true,3,false><<<dim3(2*TF/128, TT/128, TE), 256, SMEM_N>>>(
      TT, 2*TF, TD, p_xh, nullptr, TD, p_wgu, TD,
      (float*)p_gh, 2*TF, 1.f, p_elist, nullptr, p_ecnt,
      0, (size_t)2*TF*TD, (size_t)TT*TF);
  tgemm<3,false,4,false><<<dim3(TD/128, TT/128, TE), 256, SMEM_N>>>(
      TT, TD, TF, p_gh, nullptr, TF, p_wd, TF,
      out, TD, 1.f, p_elist, p_ew, p_ecnt,
      (size_t)TT*TF, (size_t)TD*TF, 0);

  cudaStreamDestroy(s2);
  cudaEventDestroy(evFork);
  cudaEventDestroy(evJoin);
}

// round 12
// speedup vs baseline: 12.0775x; 1.0076x over previous
#include <cuda_runtime.h>
#include <cuda_fp16.h>
#include <math.h>
#include <stdint.h>

// Problem constants
#define TS_ 1024
#define TBATCH 2
#define TD 2048
#define TH 16
#define TKV 4
#define THD 128
#define TE 8
#define TF 2048
#define TT (TBATCH*TS_)            // 2048 tokens
#define OQKV ((TH+2*TKV)*THD)      // 3072
#define REP (TH/TKV)               // 4

typedef unsigned short u16;

// ---------------- scratch (device globals) ----------
__device__ float g_h[(size_t)TT*TD];
__device__ float g_qkv[(size_t)TT*OQKV];
__device__ float g_scores[(size_t)TBATCH*TH*TS_*TS_];
__device__ float g_res[(size_t)TT*TD];
__device__ int   g_elist[TE*TT];
__device__ float g_ew[TE*TT];
__device__ int   g_ecnt[TE];

// fp16 buffers
__device__ u16 g_wqkv_h[(size_t)OQKV*TD];
__device__ u16 g_wout_h[(size_t)TD*TD];
__device__ u16 g_wgu_h[(size_t)TE*2*TF*TD];    // [e][2F][D], rows interleaved gate/up
__device__ u16 g_wd_h[(size_t)TE*TD*TF];       // [e][D][F]
__device__ u16 g_xh[(size_t)TT*TD],  g_xl[(size_t)TT*TD];
__device__ u16 g_ah[(size_t)TT*TD],  g_al[(size_t)TT*TD];
__device__ u16 g_gh[(size_t)TE*TT*TF];
__device__ u16 g_qh[(size_t)TT*OQKV], g_ql[(size_t)TT*OQKV];
__device__ u16 g_ph[(size_t)TBATCH*TH*TS_*TS_], g_pl[(size_t)TBATCH*TH*TS_*TS_];
__device__ u16 g_vt[(size_t)TBATCH*TKV*THD*TS_];

// ---------------- helpers ----------------
__device__ __forceinline__ u16 h16(float x){
  __half h = __float2half_rn(x);
  return *reinterpret_cast<u16*>(&h);
}
__device__ __forceinline__ float h2f(u16 b){
  __half h = *reinterpret_cast<__half*>(&b);
  return __half2float(h);
}
__device__ __forceinline__ uint32_t smem_u32(const void* p){
  uint32_t a;
  asm("{ .reg .u64 t; cvta.to.shared.u64 t, %1; cvt.u32.u64 %0, t; }" : "=r"(a) : "l"(p));
  return a;
}
__device__ __forceinline__ void ldsm_x4(uint32_t* r, uint32_t addr){
  asm volatile("ldmatrix.sync.aligned.m8n8.x4.shared.b16 {%0,%1,%2,%3}, [%4];"
    : "=r"(r[0]),"=r"(r[1]),"=r"(r[2]),"=r"(r[3]) : "r"(addr));
}
__device__ __forceinline__ void mma16816(float* c, const uint32_t* a, const uint32_t* b){
  asm volatile("mma.sync.aligned.m16n8k16.row.col.f32.f16.f16.f32 "
    "{%0,%1,%2,%3}, {%4,%5,%6,%7}, {%8,%9}, {%0,%1,%2,%3};"
    : "+f"(c[0]),"+f"(c[1]),"+f"(c[2]),"+f"(c[3])
    : "r"(a[0]),"r"(a[1]),"r"(a[2]),"r"(a[3]), "r"(b[0]),"r"(b[1]));
}
__device__ __forceinline__ void cp16(uint32_t dst, const void* src, int ssz){
  asm volatile("cp.async.cg.shared.global [%0], [%1], 16, %2;"
    :: "r"(dst), "l"(src), "r"(ssz) : "memory");
}
__device__ __forceinline__ void cp16f(uint32_t dst, const void* src){
  asm volatile("cp.async.cg.shared.global [%0], [%1], 16;"
    :: "r"(dst), "l"(src) : "memory");
}
#define CP_COMMIT() asm volatile("cp.async.commit_group;":::"memory")
#define CP_WAIT(n)  asm volatile("cp.async.wait_group %0;"::"n"(n):"memory")

// ---------------- conversion kernels ----------------
__global__ void convhalf(const float* __restrict__ src, u16* __restrict__ d, int n4){
  int i = blockIdx.x*blockDim.x + threadIdx.x;
  if (i >= n4) return;
  float4 v = reinterpret_cast<const float4*>(src)[i];
  ushort4 hv; hv.x=h16(v.x); hv.y=h16(v.y); hv.z=h16(v.z); hv.w=h16(v.w);
  reinterpret_cast<ushort4*>(d)[i]=hv;
}
// transpose [R,C] -> [C,R] fp16; dst row = rmul*c + roff (for gate/up interleave)
__global__ void transhalf(const float* __restrict__ src, u16* __restrict__ dst,
                          int R, int C, size_t sstr, size_t dstr, int rmul, int roff){
  __shared__ float t[32][33];
  src += (size_t)blockIdx.z * sstr;
  dst += (size_t)blockIdx.z * dstr;
  int c0 = blockIdx.x*32, r0 = blockIdx.y*32;
  int tx = threadIdx.x, ty = threadIdx.y;
  #pragma unroll
  for (int j=0;j<4;j++)
    t[ty+j*8][tx] = src[(size_t)(r0+ty+j*8)*C + c0+tx];
  __syncthreads();
  #pragma unroll
  for (int j=0;j<4;j++)
    dst[(size_t)(rmul*(c0+ty+j*8)+roff)*R + r0+tx] = h16(t[tx][ty+j*8]);
}
__global__ void vtrans(const float* __restrict__ qkv, u16* __restrict__ vt){
  __shared__ float t[32][33];
  int z = blockIdx.z; int b = z/TKV, kv = z%TKV;
  int s0 = blockIdx.x*32, h0 = blockIdx.y*32;
  int tx = threadIdx.x, ty = threadIdx.y;
  #pragma unroll
  for (int j=0;j<4;j++){
    int s = s0+ty+j*8;
    t[ty+j*8][tx] = qkv[(size_t)(b*TS_+s)*OQKV + (TH+TKV+kv)*THD + h0+tx];
  }
  __syncthreads();
  #pragma unroll
  for (int j=0;j<4;j++){
    int hd = h0+ty+j*8;
    vt[((size_t)z*THD + hd)*TS_ + s0+tx] = h16(t[tx][ty+j*8]);
  }
}

// ---------------- tensor-core GEMM (fp16, optional A hi/lo split) ----------
// C[M,N] = alpha * (Ah[+Al])[M,K] @ Bh[N,K]^T     BK=64 cp.async pipeline
// Single-__syncthreads mainloop: issue(c+NST-1) placed AFTER the barrier —
// the stage it overwrites was consumed in iteration c-1, and all threads
// passed this barrier after computing c-1, so no trailing barrier is needed.
// EPI 0: store fp32. EPI 1: fused silu(gate)*up -> fp16 (interleaved cols).
// EPI 2: store + hres add. EPI 3: atomicAdd C[arow[m]] += aw[m]*v.
// EPI 4: fp16 hi/lo split store (C=hi base, aw=lo base).
// ADDR 0: plain. 1: attn scores. 2: PV. 3: expert-batched gather.
// 4: expert-batched (A per-expert) atomic scatter.
#define TPAD 144
#define MATB (128*TPAD)   // 18432

template<int EPI, bool GATHER, int ADDR, bool ASPLIT>
__global__ __launch_bounds__(256,2) void tgemm(
    int M, int N, int K,
    const u16* __restrict__ Ah, const u16* __restrict__ Al, int lda,
    const u16* __restrict__ Bh, int ldb,
    float* __restrict__ C, int ldc, float alpha,
    const int* __restrict__ arow, const float* __restrict__ aw,
    const int* __restrict__ cntp,
    size_t astride, size_t bstride, size_t cstride)
{
  constexpr int NMAT = ASPLIT ? 3 : 2;
  constexpr int NST  = ASPLIT ? 2 : 3;     // pipeline stages
  constexpr int STB  = NMAT*MATB;
  constexpr int BOFF = (ASPLIT ? 2 : 1)*MATB;
  extern __shared__ __align__(16) char smem[];
  int row0 = blockIdx.y*128, col0 = blockIdx.x*128;
  int Klim = K;
  size_t cbase = 0;

  if (ADDR==1){
    if (col0 > row0 + 127) return;
    int z = blockIdx.z, b = z/TH, h = z%TH;
    size_t off = (size_t)b*TS_*OQKV + h*THD;
    Ah += off; if (ASPLIT) Al += off;
    lda = OQKV;
    Bh += (size_t)b*TS_*OQKV + (TH + h/REP)*THD;
    ldb = OQKV;
    C  += (size_t)z*TS_*TS_;
    ldc = TS_;
  } else if (ADDR==2){
    int z = blockIdx.z, b = z/TH, h = z%TH;
    size_t off = (size_t)z*TS_*TS_;
    Ah += off; if (ASPLIT) Al += off;
    lda = TS_;
    Bh += ((size_t)(b*TKV + h/REP))*THD*TS_;
    ldb = TS_;
    cbase = (size_t)b*TS_*(TH*THD) + h*THD;
    if (EPI != 4) C += cbase;
    ldc = TH*THD;
    Klim = min(K, row0 + 128);
  } else if (ADDR==3 || ADDR==4){
    int z = blockIdx.z;
    arow += z*TT;
    if (ADDR==4){ aw += z*TT; Ah += (size_t)z*astride; }
    cntp += z;
    Bh += (size_t)z*bstride;
    if (EPI != 1) C += (size_t)z*cstride;
  }

  int Meff = cntp ? *cntp : M;
  if (row0 >= Meff) return;

  int tid = threadIdx.x, wid = tid>>5, lane = tid&31;
  int wm = wid>>2, wn = wid&3;
  uint32_t sbase = smem_u32(smem);

  uint32_t laneA  = (uint32_t)((lane&15)*TPAD) + (uint32_t)((lane>>4)*16);
  uint32_t laneB4 = (uint32_t)((lane&7)*TPAD) + (uint32_t)(((lane>>3)&1)*16)
                  + (uint32_t)((lane>>4)*(8*TPAD));

  float acc[4][4][4];
  #pragma unroll
  for(int i=0;i<4;i++)
    #pragma unroll
    for(int j=0;j<4;j++)
      #pragma unroll
      for(int q=0;q<4;q++) acc[i][j][q]=0.f;

  const int NC = Klim/64;

  int c16 = tid&7, rt = tid>>3;     // rt 0..31
  uint32_t doff0 = (uint32_t)(rt*TPAD + c16*16);
  long aoff[4]; int apred[4];
  #pragma unroll
  for (int it=0; it<4; it++){
    int gm = row0 + rt + it*32;
    apred[it] = gm < Meff;
    long src = apred[it] ? ((GATHER||ADDR==3) ? (long)arow[gm] : (long)gm) : 0;
    aoff[it] = src*(long)lda + c16*8;
  }
  const u16* pb0 = Bh + (long)(col0 + rt)*ldb + c16*8;

  auto issue = [&](int c){
    uint32_t dst0 = sbase + (c%NST)*STB;
    int k0 = c*64;
    #pragma unroll
    for (int it=0; it<4; it++){
      uint32_t d = dst0 + doff0 + it*32*TPAD;
      int ssz = apred[it] ? 16 : 0;
      cp16(d, Ah + aoff[it] + k0, ssz);
      if (ASPLIT) cp16(d + MATB, Al + aoff[it] + k0, ssz);
      cp16f(d + BOFF, pb0 + (long)it*32*ldb + k0);
    }
    CP_COMMIT();
  };

  issue(0);
  if (NST >= 3 && NC > 1) issue(1);
  for (int c = 0; c < NC; c++){
    // wait for stage c to be resident
    if (NST == 2){
      CP_WAIT(0);
    } else {
      if (c+1 < NC) { CP_WAIT(1); } else { CP_WAIT(0); }
    }
    __syncthreads();
    // issue next chunk into the stage consumed at iteration c-1 (safe post-barrier)
    if (NST == 2){ if (c+1 < NC) issue(c+1); }
    else         { if (c+2 < NC) issue(c+2); }

    uint32_t st = sbase + (c%NST)*STB;
    #pragma unroll
    for (int ks = 0; ks < 4; ks++){
      uint32_t rowA = st + (uint32_t)((wm*64)*TPAD + ks*32) + laneA;
      uint32_t rowB = st + BOFF + (uint32_t)((wn*32)*TPAD + ks*32) + laneB4;
      uint32_t aH[4][4], bH[4][2];
      #pragma unroll
      for (int mf=0; mf<4; mf++) ldsm_x4(aH[mf], rowA + mf*16*TPAD);
      #pragma unroll
      for (int np=0; np<2; np++){
        uint32_t t4[4];
        ldsm_x4(t4, rowB + np*16*TPAD);
        bH[2*np][0]=t4[0]; bH[2*np][1]=t4[1];
        bH[2*np+1][0]=t4[2]; bH[2*np+1][1]=t4[3];
      }
      #pragma unroll
      for (int mf=0; mf<4; mf++)
        #pragma unroll
        for (int nf=0; nf<4; nf++) mma16816(acc[mf][nf], aH[mf], bH[nf]);
      if (ASPLIT){
        uint32_t aL[4][4];
        #pragma unroll
        for (int mf=0; mf<4; mf++) ldsm_x4(aL[mf], rowA + MATB + mf*16*TPAD);
        #pragma unroll
        for (int mf=0; mf<4; mf++)
          #pragma unroll
          for (int nf=0; nf<4; nf++) mma16816(acc[mf][nf], aL[mf], bH[nf]);
      }
    }
  }

  // ---- epilogue ----
  int g = lane>>2, tig = lane&3;
  u16* G = nullptr;
  if (EPI == 1) G = reinterpret_cast<u16*>(C) + (size_t)blockIdx.z*cstride;
  u16* Oh = nullptr; u16* Ol = nullptr;
  if (EPI == 4){
    Oh = reinterpret_cast<u16*>(C) + cbase;
    Ol = const_cast<u16*>(reinterpret_cast<const u16*>(aw)) + cbase;
  }
  #pragma unroll
  for (int mf=0; mf<4; mf++){
    int ra = row0 + wm*64 + mf*16 + g;
    int rb = ra + 8;
    #pragma unroll
    for (int nf=0; nf<4; nf++){
      int col = col0 + wn*32 + nf*8 + tig*2;
      float* cacc = acc[mf][nf];
      if (EPI == 0){
        if (ra < Meff){
          float* p = C + (size_t)ra*ldc + col;
          p[0] = cacc[0]*alpha; p[1] = cacc[1]*alpha;
        }
        if (rb < Meff){
          float* p = C + (size_t)rb*ldc + col;
          p[0] = cacc[2]*alpha; p[1] = cacc[3]*alpha;
        }
      } else if (EPI == 1){
        int f = col >> 1;
        if (ra < Meff){
          float gg = cacc[0];
          G[(size_t)ra*(ldc>>1) + f] = h16((gg/(1.f+__expf(-gg)))*cacc[1]);
        }
        if (rb < Meff){
          float gg = cacc[2];
          G[(size_t)rb*(ldc>>1) + f] = h16((gg/(1.f+__expf(-gg)))*cacc[3]);
        }
      } else if (EPI == 2){
        if (ra < Meff){
          float* p = C + (size_t)ra*ldc + col;
          const float* hr = aw + (size_t)ra*ldc + col;
          p[0] = cacc[0]*alpha + hr[0]; p[1] = cacc[1]*alpha + hr[1];
        }
        if (rb < Meff){
          float* p = C + (size_t)rb*ldc + col;
          const float* hr = aw + (size_t)rb*ldc + col;
          p[0] = cacc[2]*alpha + hr[0]; p[1] = cacc[3]*alpha + hr[1];
        }
      } else if (EPI == 4){
        if (ra < Meff){
          size_t o = (size_t)ra*ldc + col;
          float v0 = cacc[0]*alpha, v1 = cacc[1]*alpha;
          u16 h0 = h16(v0), h1 = h16(v1);
          Oh[o] = h0;   Oh[o+1] = h1;
          Ol[o] = h16(v0 - h2f(h0)); Ol[o+1] = h16(v1 - h2f(h1));
        }
        if (rb < Meff){
          size_t o = (size_t)rb*ldc + col;
          float v0 = cacc[2]*alpha, v1 = cacc[3]*alpha;
          u16 h0 = h16(v0), h1 = h16(v1);
          Oh[o] = h0;   Oh[o+1] = h1;
          Ol[o] = h16(v0 - h2f(h0)); Ol[o+1] = h16(v1 - h2f(h1));
        }
      } else {
        if (ra < Meff){
          float w = aw[ra];
          float* p = C + (size_t)arow[ra]*ldc + col;
          atomicAdd(p,   w*cacc[0]*alpha);
          atomicAdd(p+1, w*cacc[1]*alpha);
        }
        if (rb < Meff){
          float w = aw[rb];
          float* p = C + (size_t)arow[rb]*ldc + col;
          atomicAdd(p,   w*cacc[2]*alpha);
          atomicAdd(p+1, w*cacc[3]*alpha);
        }
      }
    }
  }
}

// ---------------- reduction helpers ----------------
__device__ __forceinline__ float warp_sum(float v){
  #pragma unroll
  for(int o=16;o;o>>=1) v += __shfl_xor_sync(0xffffffffu, v, o);
  return v;
}
__device__ __forceinline__ float warp_max(float v){
  #pragma unroll
  for(int o=16;o;o>>=1) v = fmaxf(v, __shfl_xor_sync(0xffffffffu, v, o));
  return v;
}

// ---------------- LayerNorm (optional fp32 out + fp16 hi[/lo]) -------------
__global__ void ln_kernel(const float* __restrict__ x, const float* __restrict__ w,
                          float* __restrict__ y, u16* __restrict__ yh, u16* __restrict__ yl){
  int row = blockIdx.x;
  const float* xr = x + (size_t)row*TD;
  float s=0.f, s2=0.f;
  for(int d=threadIdx.x; d<TD; d+=blockDim.x){ float v=xr[d]; s+=v; s2+=v*v; }
  __shared__ float shs[8], shs2[8];
  int lane=threadIdx.x&31, wp=threadIdx.x>>5;
  s = warp_sum(s); s2 = warp_sum(s2);
  if(!lane){ shs[wp]=s; shs2[wp]=s2; }
  __syncthreads();
  if (threadIdx.x < 32){
    float a = (threadIdx.x<8)? shs[threadIdx.x] : 0.f;
    float b = (threadIdx.x<8)? shs2[threadIdx.x] : 0.f;
    a = warp_sum(a); b = warp_sum(b);
    if(!threadIdx.x){ shs[0]=a; shs2[0]=b; }
  }
  __syncthreads();
  float mu = shs[0]*(1.f/TD);
  float var = shs2[0]*(1.f/TD) - mu*mu;
  float rstd = rsqrtf(var + 1e-5f);
  for(int d=threadIdx.x; d<TD; d+=blockDim.x){
    float v = (xr[d]-mu)*rstd*w[d];
    if (y) y[(size_t)row*TD + d] = v;
    u16 h = h16(v);
    yh[(size_t)row*TD + d] = h;
    if (yl) yl[(size_t)row*TD + d] = h16(v - h2f(h));
  }
}

// ---------------- RoPE -> fp16 split ----------------
__global__ void rope_kernel(const float* __restrict__ qkv,
                            const float* __restrict__ cosb,
                            const float* __restrict__ sinb,
                            u16* __restrict__ qh, u16* __restrict__ ql){
  int idx = blockIdx.x*blockDim.x + threadIdx.x;
  const int total = TT*(TH+TKV)*(THD/2);
  if (idx >= total) return;
  int i  = idx & 63;
  int rest = idx >> 6;
  int hh = rest % (TH+TKV);
  int t  = rest / (TH+TKV);
  int s  = t % TS_;
  float c  = cosb[s*THD + i];
  float sn = sinb[s*THD + i];
  const float* p = qkv + (size_t)t*OQKV + hh*THD;
  float x1 = p[i], x2 = p[i+64];
  float r1 = x1*c - x2*sn;
  float r2 = x2*c + x1*sn;
  size_t o = (size_t)t*OQKV + hh*THD;
  u16 h1 = h16(r1), h2 = h16(r2);
  qh[o+i] = h1;    ql[o+i]    = h16(r1 - h2f(h1));
  qh[o+i+64] = h2; ql[o+i+64] = h16(r2 - h2f(h2));
}

// ---------------- causal softmax -> fp16 split P (single exp pass) --------
__global__ void softmax_kernel(const float* __restrict__ s,
                               u16* __restrict__ ph, u16* __restrict__ pl){
  int row = blockIdx.x;
  int q = row % TS_;
  int L = q + 1;
  int pad = ((q>>7)+1)<<7;
  const float* r = s + (size_t)row*TS_;
  u16* oh = ph + (size_t)row*TS_;
  u16* ol = pl + (size_t)row*TS_;
  int tid = threadIdx.x;
  int lane = tid&31, wp = tid>>5;
  __shared__ float sh[8];

  float mx = -1e30f;
  for(int d=tid; d<L; d+=256) mx = fmaxf(mx, r[d]);
  mx = warp_max(mx);
  if(!lane) sh[wp]=mx;
  __syncthreads();
  if (tid<32){ float v=(tid<8)?sh[tid]:-1e30f; v=warp_max(v); if(!tid) sh[0]=v; }
  __syncthreads();
  mx = sh[0];
  __syncthreads();

  float ev[4];
  int cnt = 0;
  float sum = 0.f;
  for(int d=tid; d<L; d+=256){
    float e = __expf(r[d]-mx);
    ev[cnt++] = e;
    sum += e;
  }
  sum = warp_sum(sum);
  if(!lane) sh[wp]=sum;
  __syncthreads();
  if (tid<32){ float v=(tid<8)?sh[tid]:0.f; v=warp_sum(v); if(!tid) sh[0]=v; }
  __syncthreads();
  float inv = 1.f/sh[0];

  cnt = 0;
  for(int d=tid; d<L; d+=256){
    float p = ev[cnt++]*inv;
    u16 h = h16(p);
    oh[d] = h;
    ol[d] = h16(p - h2f(h));
  }
  for(int d=L+tid; d<pad; d+=256){ oh[d]=0; ol[d]=0; }
}

// ---------------- elementwise ----------------
__global__ void zero_kernel(float* __restrict__ p, int n){
  int i = blockIdx.x*blockDim.x + threadIdx.x;
  if (i<n) p[i]=0.f;
}
__global__ void zero_cnt_kernel(){
  if (threadIdx.x < TE) g_ecnt[threadIdx.x]=0;
}

// ---------------- router ----------------
__global__ void router_kernel(const float* __restrict__ x, const float* __restrict__ wr){
  int t = blockIdx.x;
  int tid = threadIdx.x;
  const float* xr = x + (size_t)t*TD;
  float acc[TE];
  #pragma unroll
  for(int e=0;e<TE;e++) acc[e]=0.f;
  for(int d=tid; d<TD; d+=128){
    float xv = xr[d];
    #pragma unroll
    for(int e=0;e<TE;e++) acc[e] += xv*wr[e*TD+d];
  }
  __shared__ float sh[TE][4];
  int lane=tid&31, wp=tid>>5;
  #pragma unroll
  for(int e=0;e<TE;e++){
    float v = warp_sum(acc[e]);
    if(!lane) sh[e][wp]=v;
  }
  __syncthreads();
  if (tid==0){
    float lg[TE];
    float mx=-1e30f;
    #pragma unroll
    for(int e=0;e<TE;e++){ lg[e]=sh[e][0]+sh[e][1]+sh[e][2]+sh[e][3]; mx=fmaxf(mx,lg[e]); }
    float p[TE]; float s=0.f;
    #pragma unroll
    for(int e=0;e<TE;e++){ p[e]=expf(lg[e]-mx); s+=p[e]; }
    float inv=1.f/s;
    #pragma unroll
    for(int e=0;e<TE;e++) p[e]*=inv;
    int e0=0;
    #pragma unroll
    for(int e=1;e<TE;e++) if (p[e]>p[e0]) e0=e;
    int e1=-1;
    #pragma unroll
    for(int e=0;e<TE;e++){ if(e==e0) continue; if (e1<0 || p[e]>p[e1]) e1=e; }
    float w0=p[e0], w1=p[e1];
    float tot = w0+w1;
    w0/=tot; w1/=tot;
    int pos = atomicAdd(&g_ecnt[e0],1);
    g_elist[e0*TT+pos]=t; g_ew[e0*TT+pos]=w0;
    pos = atomicAdd(&g_ecnt[e1],1);
    g_elist[e1*TT+pos]=t; g_ew[e1*TT+pos]=w1;
  }
}

// ---------------- launcher ----------------
extern "C" void kernel_launch(void* const* d_in, const int* in_sizes, int n_in,
                              void* d_out, int out_size){
  const float* hidden  = (const float*)d_in[0];
  const float* cosb    = (const float*)d_in[1];
  const float* sinb    = (const float*)d_in[2];
  const float* ln1w    = (const float*)d_in[3];
  const float* ln2w    = (const float*)d_in[4];
  const float* wqkv    = (const float*)d_in[5];
  const float* wout    = (const float*)d_in[6];
  const float* wrouter = (const float*)d_in[7];
  const float* wgate   = (const float*)d_in[8];
  const float* wup     = (const float*)d_in[9];
  const float* wdown   = (const float*)d_in[10];
  float* out = (float*)d_out;

  float *p_h,*p_qkv,*p_scores,*p_res,*p_ew;
  int *p_elist,*p_ecnt;
  u16 *p_wqkv,*p_wout,*p_wgu,*p_wd;
  u16 *p_xh,*p_xl,*p_ah,*p_al,*p_gh,*p_qh,*p_ql,*p_ph,*p_pl,*p_vt;
  cudaGetSymbolAddress((void**)&p_h, g_h);
  cudaGetSymbolAddress((void**)&p_qkv, g_qkv);
  cudaGetSymbolAddress((void**)&p_scores, g_scores);
  cudaGetSymbolAddress((void**)&p_res, g_res);
  cudaGetSymbolAddress((void**)&p_ew, g_ew);
  cudaGetSymbolAddress((void**)&p_elist, g_elist);
  cudaGetSymbolAddress((void**)&p_ecnt, g_ecnt);
  cudaGetSymbolAddress((void**)&p_wqkv, g_wqkv_h);
  cudaGetSymbolAddress((void**)&p_wout, g_wout_h);
  cudaGetSymbolAddress((void**)&p_wgu, g_wgu_h);
  cudaGetSymbolAddress((void**)&p_wd, g_wd_h);
  cudaGetSymbolAddress((void**)&p_xh, g_xh);
  cudaGetSymbolAddress((void**)&p_xl, g_xl);
  cudaGetSymbolAddress((void**)&p_ah, g_ah);
  cudaGetSymbolAddress((void**)&p_al, g_al);
  cudaGetSymbolAddress((void**)&p_gh, g_gh);
  cudaGetSymbolAddress((void**)&p_qh, g_qh);
  cudaGetSymbolAddress((void**)&p_ql, g_ql);
  cudaGetSymbolAddress((void**)&p_ph, g_ph);
  cudaGetSymbolAddress((void**)&p_pl, g_pl);
  cudaGetSymbolAddress((void**)&p_vt, g_vt);

  const int SMEM_S = 2*3*MATB;   // split: 2 stages x 3 mats
  const int SMEM_N = 3*2*MATB;   // non-split: 3 stages x 2 mats
  cudaFuncSetAttribute(tgemm<0,false,0,true>,  cudaFuncAttributeMaxDynamicSharedMemorySize, SMEM_S);
  cudaFuncSetAttribute(tgemm<0,false,1,true>,  cudaFuncAttributeMaxDynamicSharedMemorySize, SMEM_S);
  cudaFuncSetAttribute(tgemm<4,false,2,true>,  cudaFuncAttributeMaxDynamicSharedMemorySize, SMEM_S);
  cudaFuncSetAttribute(tgemm<2,false,0,true>,  cudaFuncAttributeMaxDynamicSharedMemorySize, SMEM_S);
  cudaFuncSetAttribute(tgemm<1,true,3,false>,  cudaFuncAttributeMaxDynamicSharedMemorySize, SMEM_N);
  cudaFuncSetAttribute(tgemm<3,false,4,false>, cudaFuncAttributeMaxDynamicSharedMemorySize, SMEM_N);

  const int n_td = TT*TD;
  float* resid = (out_size >= 2*n_td) ? (out + (size_t)n_td) : p_res;

  // ---- fork side stream for independent weight conversions + output zero ----
  cudaStream_t s2;
  cudaStreamCreate(&s2);
  cudaEvent_t evFork, evJoin;
  cudaEventCreateWithFlags(&evFork, cudaEventDisableTiming);
  cudaEventCreateWithFlags(&evJoin, cudaEventDisableTiming);
  cudaEventRecord(evFork, 0);
  cudaStreamWaitEvent(s2, evFork, 0);

  // side stream: wout, wgate/wup/wdown conversions + out zeroing
  convhalf<<<(TD*TD/4+255)/256,256,0,s2>>>(wout, p_wout, TD*TD/4);
  transhalf<<<dim3(TF/32, TD/32, TE), dim3(32,8),0,s2>>>(wgate, p_wgu, TD, TF,
      (size_t)TD*TF, (size_t)2*TF*TD, 2, 0);
  transhalf<<<dim3(TF/32, TD/32, TE), dim3(32,8),0,s2>>>(wup, p_wgu, TD, TF,
      (size_t)TD*TF, (size_t)2*TF*TD, 2, 1);
  transhalf<<<dim3(TD/32, TF/32, TE), dim3(32,8),0,s2>>>(wdown, p_wd, TF, TD,
      (size_t)TF*TD, (size_t)TD*TF, 1, 0);
  zero_kernel<<<(n_td+255)/256,256,0,s2>>>(out, n_td);
  cudaEventRecord(evJoin, s2);

  // main stream: attention chain
  convhalf<<<(OQKV*TD/4+255)/256,256>>>(wqkv, p_wqkv, OQKV*TD/4);
  ln_kernel<<<TT,256>>>(hidden, ln1w, nullptr, p_xh, p_xl);
  tgemm<0,false,0,true><<<dim3(OQKV/128, TT/128), 256, SMEM_S>>>(
      TT, OQKV, TD, p_xh, p_xl, TD, p_wqkv, TD,
      p_qkv, OQKV, 1.f, nullptr, nullptr, nullptr, 0,0,0);
  {
    int total = TT*(TH+TKV)*(THD/2);
    rope_kernel<<<(total+255)/256,256>>>(p_qkv, cosb, sinb, p_qh, p_ql);
  }
  vtrans<<<dim3(TS_/32, THD/32, TBATCH*TKV), dim3(32,8)>>>(p_qkv, p_vt);
  tgemm<0,false,1,true><<<dim3(TS_/128, TS_/128, TBATCH*TH), 256, SMEM_S>>>(
      TS_, TS_, THD, p_qh, p_ql, 0, p_qh, 0,
      p_scores, 0, 1.f/sqrtf((float)THD), nullptr, nullptr, nullptr, 0,0,0);
  softmax_kernel<<<TBATCH*TH*TS_,256>>>(p_scores, p_ph, p_pl);

  // PV with fused fp16 hi/lo split store -> ah/al
  tgemm<4,false,2,true><<<dim3(1, TS_/128, TBATCH*TH), 256, SMEM_S>>>(
      TS_, THD, TS_, p_ph, p_pl, 0, p_vt, 0,
      (float*)p_ah, 0, 1.f, nullptr, (const float*)p_al, nullptr, 0,0,0);

  // join side stream before out-proj
  cudaStreamWaitEvent(0, evJoin, 0);

  // out-proj (split A) with fused residual add -> resid
  tgemm<2,false,0,true><<<dim3(TD/128, TT/128), 256, SMEM_S>>>(
      TT, TD, TH*THD, p_ah, p_al, TH*THD, p_wout, TH*THD,
      resid, TD, 1.f, nullptr, hidden, nullptr, 0,0,0);

  // LN2 (fp32 h for router + hi only for MoE)
  ln_kernel<<<TT,256>>>(resid, ln2w, p_h, p_xh, nullptr);

  // router
  zero_cnt_kernel<<<1,32>>>();
  router_kernel<<<TT,128>>>(p_h, wrouter);

  // MoE: GU GEMM with fused silu -> gh (fp16), then down (atomic scatter)
  tgemm<1,true,3,false><<<dim3(2*TF/128, TT/128, TE), 256, SMEM_N>>>(
      TT, 2*TF, TD, p_xh, nullptr, TD, p_wgu, TD,
      (float*)p_gh, 2*TF, 1.f, p_elist, nullptr, p_ecnt,
      0, (size_t)2*TF*TD, (size_t)TT*TF);
  tgemm<3,false,4,false><<<dim3(TD/128, TT/128, TE), 256, SMEM_N>>>(
      TT, TD, TF, p_gh, nullptr, TF, p_wd, TF,
      out, TD, 1.f, p_elist, p_ew, p_ecnt,
      (size_t)TT*TF, (size_t)TD*TF, 0);

  cudaStreamDestroy(s2);
  cudaEventDestroy(evFork);
  cudaEventDestroy(evJoin);
}

// round 14
// speedup vs baseline: 13.4319x; 1.1121x over previous
#include <cuda_runtime.h>
#include <cuda_fp16.h>
#include <math.h>
#include <stdint.h>

// Problem constants
#define TS_ 1024
#define TBATCH 2
#define TD 2048
#define TH 16
#define TKV 4
#define THD 128
#define TE 8
#define TF 2048
#define TT (TBATCH*TS_)            // 2048 tokens
#define OQKV ((TH+2*TKV)*THD)      // 3072
#define REP (TH/TKV)               // 4

typedef unsigned short u16;

// ---------------- scratch (device globals) ----------
__device__ float g_h[(size_t)TT*TD];
__device__ float g_qkv[(size_t)TT*OQKV];
__device__ float g_res[(size_t)TT*TD];
__device__ int   g_elist[TE*TT];
__device__ float g_ew[TE*TT];
__device__ int   g_ecnt[TE];

// fp16 buffers
__device__ u16 g_wqkv_h[(size_t)OQKV*TD];
__device__ u16 g_wout_h[(size_t)TD*TD];
__device__ u16 g_wgu_h[(size_t)TE*2*TF*TD];    // [e][2F][D], rows interleaved gate/up
__device__ u16 g_wd_h[(size_t)TE*TD*TF];       // [e][D][F]
__device__ u16 g_xh[(size_t)TT*TD],  g_xl[(size_t)TT*TD];
__device__ u16 g_ah[(size_t)TT*TD],  g_al[(size_t)TT*TD];
__device__ u16 g_gh[(size_t)TE*TT*TF];
__device__ u16 g_qh[(size_t)TT*OQKV], g_ql[(size_t)TT*OQKV];
__device__ u16 g_vt[(size_t)TBATCH*TKV*THD*TS_];

// ---------------- helpers ----------------
__device__ __forceinline__ u16 h16(float x){
  __half h = __float2half_rn(x);
  return *reinterpret_cast<u16*>(&h);
}
__device__ __forceinline__ float h2f(u16 b){
  __half h = *reinterpret_cast<__half*>(&b);
  return __half2float(h);
}
__device__ __forceinline__ uint32_t smem_u32(const void* p){
  uint32_t a;
  asm("{ .reg .u64 t; cvta.to.shared.u64 t, %1; cvt.u32.u64 %0, t; }" : "=r"(a) : "l"(p));
  return a;
}
__device__ __forceinline__ void ldsm_x4(uint32_t* r, uint32_t addr){
  asm volatile("ldmatrix.sync.aligned.m8n8.x4.shared.b16 {%0,%1,%2,%3}, [%4];"
    : "=r"(r[0]),"=r"(r[1]),"=r"(r[2]),"=r"(r[3]) : "r"(addr));
}
__device__ __forceinline__ void mma16816(float* c, const uint32_t* a, const uint32_t* b){
  asm volatile("mma.sync.aligned.m16n8k16.row.col.f32.f16.f16.f32 "
    "{%0,%1,%2,%3}, {%4,%5,%6,%7}, {%8,%9}, {%0,%1,%2,%3};"
    : "+f"(c[0]),"+f"(c[1]),"+f"(c[2]),"+f"(c[3])
    : "r"(a[0]),"r"(a[1]),"r"(a[2]),"r"(a[3]), "r"(b[0]),"r"(b[1]));
}
__device__ __forceinline__ void cp16(uint32_t dst, const void* src, int ssz){
  asm volatile("cp.async.cg.shared.global [%0], [%1], 16, %2;"
    :: "r"(dst), "l"(src), "r"(ssz) : "memory");
}
__device__ __forceinline__ void cp16f(uint32_t dst, const void* src){
  asm volatile("cp.async.cg.shared.global [%0], [%1], 16;"
    :: "r"(dst), "l"(src) : "memory");
}
#define CP_COMMIT() asm volatile("cp.async.commit_group;":::"memory")
#define CP_WAIT(n)  asm volatile("cp.async.wait_group %0;"::"n"(n):"memory")

// ---------------- conversion kernels ----------------
__global__ void convhalf(const float* __restrict__ src, u16* __restrict__ d, int n4){
  int i = blockIdx.x*blockDim.x + threadIdx.x;
  if (i >= n4) return;
  float4 v = reinterpret_cast<const float4*>(src)[i];
  ushort4 hv; hv.x=h16(v.x); hv.y=h16(v.y); hv.z=h16(v.z); hv.w=h16(v.w);
  reinterpret_cast<ushort4*>(d)[i]=hv;
}
__global__ void transhalf(const float* __restrict__ src, u16* __restrict__ dst,
                          int R, int C, size_t sstr, size_t dstr, int rmul, int roff){
  __shared__ float t[32][33];
  src += (size_t)blockIdx.z * sstr;
  dst += (size_t)blockIdx.z * dstr;
  int c0 = blockIdx.x*32, r0 = blockIdx.y*32;
  int tx = threadIdx.x, ty = threadIdx.y;
  #pragma unroll
  for (int j=0;j<4;j++)
    t[ty+j*8][tx] = src[(size_t)(r0+ty+j*8)*C + c0+tx];
  __syncthreads();
  #pragma unroll
  for (int j=0;j<4;j++)
    dst[(size_t)(rmul*(c0+ty+j*8)+roff)*R + r0+tx] = h16(t[tx][ty+j*8]);
}
__global__ void vtrans(const float* __restrict__ qkv, u16* __restrict__ vt){
  __shared__ float t[32][33];
  int z = blockIdx.z; int b = z/TKV, kv = z%TKV;
  int s0 = blockIdx.x*32, h0 = blockIdx.y*32;
  int tx = threadIdx.x, ty = threadIdx.y;
  #pragma unroll
  for (int j=0;j<4;j++){
    int s = s0+ty+j*8;
    t[ty+j*8][tx] = qkv[(size_t)(b*TS_+s)*OQKV + (TH+TKV+kv)*THD + h0+tx];
  }
  __syncthreads();
  #pragma unroll
  for (int j=0;j<4;j++){
    int hd = h0+ty+j*8;
    vt[((size_t)z*THD + hd)*TS_ + s0+tx] = h16(t[tx][ty+j*8]);
  }
}

// ---------------- tensor-core GEMM (fp16, optional A hi/lo split) ----------
#define TPAD 144
#define MATB (128*TPAD)   // 18432

template<int EPI, bool GATHER, int ADDR, bool ASPLIT>
__global__ __launch_bounds__(256,2) void tgemm(
    int M, int N, int K,
    const u16* __restrict__ Ah, const u16* __restrict__ Al, int lda,
    const u16* __restrict__ Bh, int ldb,
    float* __restrict__ C, int ldc, float alpha,
    const int* __restrict__ arow, const float* __restrict__ aw,
    const int* __restrict__ cntp,
    size_t astride, size_t bstride, size_t cstride)
{
  constexpr int NMAT = ASPLIT ? 3 : 2;
  constexpr int NST  = ASPLIT ? 2 : 3;
  constexpr int STB  = NMAT*MATB;
  constexpr int BOFF = (ASPLIT ? 2 : 1)*MATB;
  extern __shared__ __align__(16) char smem[];
  int row0 = blockIdx.y*128, col0 = blockIdx.x*128;
  int Klim = K;

  if (ADDR==3 || ADDR==4){
    int z = blockIdx.z;
    arow += z*TT;
    if (ADDR==4){ aw += z*TT; Ah += (size_t)z*astride; }
    cntp += z;
    Bh += (size_t)z*bstride;
    if (EPI != 1) C += (size_t)z*cstride;
  }

  int Meff = cntp ? *cntp : M;
  if (row0 >= Meff) return;

  int tid = threadIdx.x, wid = tid>>5, lane = tid&31;
  int wm = wid>>2, wn = wid&3;
  uint32_t sbase = smem_u32(smem);

  uint32_t laneA  = (uint32_t)((lane&15)*TPAD) + (uint32_t)((lane>>4)*16);
  uint32_t laneB4 = (uint32_t)((lane&7)*TPAD) + (uint32_t)(((lane>>3)&1)*16)
                  + (uint32_t)((lane>>4)*(8*TPAD));

  float acc[4][4][4];
  #pragma unroll
  for(int i=0;i<4;i++)
    #pragma unroll
    for(int j=0;j<4;j++)
      #pragma unroll
      for(int q=0;q<4;q++) acc[i][j][q]=0.f;

  const int NC = Klim/64;

  int c16 = tid&7, rt = tid>>3;
  uint32_t doff0 = (uint32_t)(rt*TPAD + c16*16);
  long aoff[4]; int apred[4];
  #pragma unroll
  for (int it=0; it<4; it++){
    int gm = row0 + rt + it*32;
    apred[it] = gm < Meff;
    long src = apred[it] ? ((GATHER||ADDR==3) ? (long)arow[gm] : (long)gm) : 0;
    aoff[it] = src*(long)lda + c16*8;
  }
  const u16* pb0 = Bh + (long)(col0 + rt)*ldb + c16*8;

  auto issue = [&](int c){
    uint32_t dst0 = sbase + (c%NST)*STB;
    int k0 = c*64;
    #pragma unroll
    for (int it=0; it<4; it++){
      uint32_t d = dst0 + doff0 + it*32*TPAD;
      int ssz = apred[it] ? 16 : 0;
      cp16(d, Ah + aoff[it] + k0, ssz);
      if (ASPLIT) cp16(d + MATB, Al + aoff[it] + k0, ssz);
      cp16f(d + BOFF, pb0 + (long)it*32*ldb + k0);
    }
    CP_COMMIT();
  };

  issue(0);
  if (NST >= 3 && NC > 1) issue(1);
  for (int c = 0; c < NC; c++){
    if (NST == 2){
      CP_WAIT(0);
    } else {
      if (c+1 < NC) { CP_WAIT(1); } else { CP_WAIT(0); }
    }
    __syncthreads();
    if (NST == 2){ if (c+1 < NC) issue(c+1); }
    else         { if (c+2 < NC) issue(c+2); }

    uint32_t st = sbase + (c%NST)*STB;
    #pragma unroll
    for (int ks = 0; ks < 4; ks++){
      uint32_t rowA = st + (uint32_t)((wm*64)*TPAD + ks*32) + laneA;
      uint32_t rowB = st + BOFF + (uint32_t)((wn*32)*TPAD + ks*32) + laneB4;
      uint32_t aH[4][4], bH[4][2];
      #pragma unroll
      for (int mf=0; mf<4; mf++) ldsm_x4(aH[mf], rowA + mf*16*TPAD);
      #pragma unroll
      for (int np=0; np<2; np++){
        uint32_t t4[4];
        ldsm_x4(t4, rowB + np*16*TPAD);
        bH[2*np][0]=t4[0]; bH[2*np][1]=t4[1];
        bH[2*np+1][0]=t4[2]; bH[2*np+1][1]=t4[3];
      }
      #pragma unroll
      for (int mf=0; mf<4; mf++)
        #pragma unroll
        for (int nf=0; nf<4; nf++) mma16816(acc[mf][nf], aH[mf], bH[nf]);
      if (ASPLIT){
        uint32_t aL[4][4];
        #pragma unroll
        for (int mf=0; mf<4; mf++) ldsm_x4(aL[mf], rowA + MATB + mf*16*TPAD);
        #pragma unroll
        for (int mf=0; mf<4; mf++)
          #pragma unroll
          for (int nf=0; nf<4; nf++) mma16816(acc[mf][nf], aL[mf], bH[nf]);
      }
    }
  }

  // ---- epilogue ----
  int g = lane>>2, tig = lane&3;
  u16* G = nullptr;
  if (EPI == 1) G = reinterpret_cast<u16*>(C) + (size_t)blockIdx.z*cstride;
  #pragma unroll
  for (int mf=0; mf<4; mf++){
    int ra = row0 + wm*64 + mf*16 + g;
    int rb = ra + 8;
    #pragma unroll
    for (int nf=0; nf<4; nf++){
      int col = col0 + wn*32 + nf*8 + tig*2;
      float* cacc = acc[mf][nf];
      if (EPI == 0){
        if (ra < Meff){
          float* p = C + (size_t)ra*ldc + col;
          p[0] = cacc[0]*alpha; p[1] = cacc[1]*alpha;
        }
        if (rb < Meff){
          float* p = C + (size_t)rb*ldc + col;
          p[0] = cacc[2]*alpha; p[1] = cacc[3]*alpha;
        }
      } else if (EPI == 1){
        int f = col >> 1;
        if (ra < Meff){
          float gg = cacc[0];
          G[(size_t)ra*(ldc>>1) + f] = h16((gg/(1.f+__expf(-gg)))*cacc[1]);
        }
        if (rb < Meff){
          float gg = cacc[2];
          G[(size_t)rb*(ldc>>1) + f] = h16((gg/(1.f+__expf(-gg)))*cacc[3]);
        }
      } else if (EPI == 2){
        if (ra < Meff){
          float* p = C + (size_t)ra*ldc + col;
          const float* hr = aw + (size_t)ra*ldc + col;
          p[0] = cacc[0]*alpha + hr[0]; p[1] = cacc[1]*alpha + hr[1];
        }
        if (rb < Meff){
          float* p = C + (size_t)rb*ldc + col;
          const float* hr = aw + (size_t)rb*ldc + col;
          p[0] = cacc[2]*alpha + hr[0]; p[1] = cacc[3]*alpha + hr[1];
        }
      } else {
        if (ra < Meff){
          float w = aw[ra];
          float* p = C + (size_t)arow[ra]*ldc + col;
          atomicAdd(p,   w*cacc[0]*alpha);
          atomicAdd(p+1, w*cacc[1]*alpha);
        }
        if (rb < Meff){
          float w = aw[rb];
          float* p = C + (size_t)arow[rb]*ldc + col;
          atomicAdd(p,   w*cacc[2]*alpha);
          atomicAdd(p+1, w*cacc[3]*alpha);
        }
      }
    }
  }
}

// ---------------- fused flash attention ----------------
// grid (TBATCH*TH, 8): z = b*TH+h, qb descending. 8 warps x 16 q-rows.
// Tiles are 128 rows x 128 fp16 (256 data bytes); row stride FTP=272 (16B pad).
// Q (hi/lo) in smem once; K/V double-buffered cp.async. S,P,O in registers.
// Q pre-scaled by 1/sqrt(HD) in rope. Output: fp16 hi/lo split -> ah/al.
#define FTP 272
#define FMAT (128*FTP)            // 34816
#define FSM  (2*FMAT + 2*2*FMAT)  // Qh,Ql + 2 stages x (K,V) = 208896

__global__ __launch_bounds__(256,1) void flashattn(
    const u16* __restrict__ qh, const u16* __restrict__ ql,
    const u16* __restrict__ vt,
    u16* __restrict__ oh, u16* __restrict__ ol)
{
  extern __shared__ __align__(16) char smem[];
  int z = blockIdx.x;
  int qb = (int)(gridDim.y - 1 - blockIdx.y);   // long blocks first
  int b = z/TH, h = z%TH;
  int NT = qb + 1;
  uint32_t sb = smem_u32(smem);
  int tid = threadIdx.x, wid = tid>>5, lane = tid&31;
  int g = lane>>2, tig = lane&3;

  const u16* Qsrc = qh + ((size_t)(b*TS_ + qb*128))*OQKV + h*THD;
  const u16* Qsrl = ql + ((size_t)(b*TS_ + qb*128))*OQKV + h*THD;
  const u16* Ksrc = qh + (size_t)(b*TS_)*OQKV + (TH + h/REP)*THD;
  const u16* Vsrc = vt + ((size_t)(b*TKV + h/REP))*THD*TS_;

  int lr = tid & 127, lhalf = tid >> 7;   // row, 64-half selector

  // Q load (hi+lo), committed together with KV stage 0
  {
    uint32_t dq = sb + (uint32_t)(lr*FTP + lhalf*128);
    const u16* sq = Qsrc + (long)lr*OQKV + lhalf*64;
    const u16* sl = Qsrl + (long)lr*OQKV + lhalf*64;
    #pragma unroll
    for (int i=0;i<8;i++){
      cp16f(dq + i*16,        sq + i*8);
      cp16f(dq + FMAT + i*16, sl + i*8);
    }
  }
  auto issueKV = [&](int t){
    uint32_t dst = sb + 2*FMAT + (uint32_t)((t&1)*(2*FMAT));
    uint32_t dk = dst + (uint32_t)(lr*FTP + lhalf*128);
    const u16* sk = Ksrc + ((long)(t*128 + lr))*OQKV + lhalf*64;
    const u16* sv = Vsrc + (long)lr*TS_ + t*128 + lhalf*64;
    #pragma unroll
    for (int i=0;i<8;i++){
      cp16f(dk + i*16,        sk + i*8);
      cp16f(dk + FMAT + i*16, sv + i*8);
    }
    CP_COMMIT();
  };
  issueKV(0);

  float sacc[16][4], oacc[16][4];
  float m0=-1e30f, m1=-1e30f, l0=0.f, l1=0.f;
  #pragma unroll
  for (int i=0;i<16;i++){ oacc[i][0]=0.f; oacc[i][1]=0.f; oacc[i][2]=0.f; oacc[i][3]=0.f; }

  uint32_t laneA  = (uint32_t)((lane&15)*FTP) + (uint32_t)((lane>>4)*16);
  uint32_t laneB4 = (uint32_t)((lane&7)*FTP) + (uint32_t)(((lane>>3)&1)*16)
                  + (uint32_t)((lane>>4)*(8*FTP));
  uint32_t qbase = sb + (uint32_t)(wid*16*FTP) + laneA;

  for (int t=0; t<NT; t++){
    CP_WAIT(0);
    __syncthreads();
    if (t+1 < NT) issueKV(t+1);

    uint32_t kb = sb + 2*FMAT + (uint32_t)((t&1)*(2*FMAT));
    uint32_t vb = kb + FMAT;

    // S = Q K^T (Q pre-scaled)
    #pragma unroll
    for (int i=0;i<16;i++){ sacc[i][0]=0.f; sacc[i][1]=0.f; sacc[i][2]=0.f; sacc[i][3]=0.f; }
    #pragma unroll
    for (int kg=0; kg<8; kg++){
      uint32_t aH[4], aL[4];
      ldsm_x4(aH, qbase + kg*32);
      ldsm_x4(aL, qbase + FMAT + kg*32);
      #pragma unroll
      for (int nf2=0; nf2<8; nf2++){
        uint32_t t4[4];
        ldsm_x4(t4, kb + laneB4 + nf2*16*FTP + kg*32);
        mma16816(sacc[2*nf2],   aH, t4);
        mma16816(sacc[2*nf2+1], aH, t4+2);
        mma16816(sacc[2*nf2],   aL, t4);
        mma16816(sacc[2*nf2+1], aL, t4+2);
      }
    }

    // causal mask on diagonal tile
    if (t == qb){
      int r0 = wid*16 + g, r1 = r0 + 8;
      #pragma unroll
      for (int nf=0; nf<16; nf++){
        int c = nf*8 + 2*tig;
        if (c   > r0) sacc[nf][0] = -1e30f;
        if (c+1 > r0) sacc[nf][1] = -1e30f;
        if (c   > r1) sacc[nf][2] = -1e30f;
        if (c+1 > r1) sacc[nf][3] = -1e30f;
      }
    }

    // online softmax
    float mr0=-1e30f, mr1=-1e30f;
    #pragma unroll
    for (int nf=0; nf<16; nf++){
      mr0 = fmaxf(mr0, fmaxf(sacc[nf][0], sacc[nf][1]));
      mr1 = fmaxf(mr1, fmaxf(sacc[nf][2], sacc[nf][3]));
    }
    mr0 = fmaxf(mr0, __shfl_xor_sync(0xffffffffu, mr0, 1));
    mr0 = fmaxf(mr0, __shfl_xor_sync(0xffffffffu, mr0, 2));
    mr1 = fmaxf(mr1, __shfl_xor_sync(0xffffffffu, mr1, 1));
    mr1 = fmaxf(mr1, __shfl_xor_sync(0xffffffffu, mr1, 2));
    float mn0 = fmaxf(m0, mr0), mn1 = fmaxf(m1, mr1);
    float f0 = __expf(m0 - mn0), f1 = __expf(m1 - mn1);
    float s0 = 0.f, s1 = 0.f;
    #pragma unroll
    for (int nf=0; nf<16; nf++){
      sacc[nf][0] = __expf(sacc[nf][0] - mn0);
      sacc[nf][1] = __expf(sacc[nf][1] - mn0);
      sacc[nf][2] = __expf(sacc[nf][2] - mn1);
      sacc[nf][3] = __expf(sacc[nf][3] - mn1);
      s0 += sacc[nf][0] + sacc[nf][1];
      s1 += sacc[nf][2] + sacc[nf][3];
    }
    s0 += __shfl_xor_sync(0xffffffffu, s0, 1);
    s0 += __shfl_xor_sync(0xffffffffu, s0, 2);
    s1 += __shfl_xor_sync(0xffffffffu, s1, 1);
    s1 += __shfl_xor_sync(0xffffffffu, s1, 2);
    l0 = l0*f0 + s0; l1 = l1*f1 + s1;
    m0 = mn0; m1 = mn1;
    #pragma unroll
    for (int nf=0; nf<16; nf++){
      oacc[nf][0]*=f0; oacc[nf][1]*=f0; oacc[nf][2]*=f1; oacc[nf][3]*=f1;
    }

    // O += P @ V  (P packed from registers, hi/lo split)
    #pragma unroll
    for (int kf=0; kf<8; kf++){
      uint32_t aH[4], aL[4];
      {
        float p00=sacc[2*kf][0],  p01=sacc[2*kf][1],  p10=sacc[2*kf][2],  p11=sacc[2*kf][3];
        float q00=sacc[2*kf+1][0],q01=sacc[2*kf+1][1],q10=sacc[2*kf+1][2],q11=sacc[2*kf+1][3];
        __half2 hh0 = __floats2half2_rn(p00,p01);
        __half2 hh1 = __floats2half2_rn(p10,p11);
        __half2 hh2 = __floats2half2_rn(q00,q01);
        __half2 hh3 = __floats2half2_rn(q10,q11);
        aH[0]=*reinterpret_cast<uint32_t*>(&hh0);
        aH[1]=*reinterpret_cast<uint32_t*>(&hh1);
        aH[2]=*reinterpret_cast<uint32_t*>(&hh2);
        aH[3]=*reinterpret_cast<uint32_t*>(&hh3);
        __half2 ll0 = __floats2half2_rn(p00-__low2float(hh0), p01-__high2float(hh0));
        __half2 ll1 = __floats2half2_rn(p10-__low2float(hh1), p11-__high2float(hh1));
        __half2 ll2 = __floats2half2_rn(q00-__low2float(hh2), q01-__high2float(hh2));
        __half2 ll3 = __floats2half2_rn(q10-__low2float(hh3), q11-__high2float(hh3));
        aL[0]=*reinterpret_cast<uint32_t*>(&ll0);
        aL[1]=*reinterpret_cast<uint32_t*>(&ll1);
        aL[2]=*reinterpret_cast<uint32_t*>(&ll2);
        aL[3]=*reinterpret_cast<uint32_t*>(&ll3);
      }
      #pragma unroll
      for (int nf2=0; nf2<8; nf2++){
        uint32_t t4[4];
        ldsm_x4(t4, vb + laneB4 + nf2*16*FTP + kf*32);
        mma16816(oacc[2*nf2],   aH, t4);
        mma16816(oacc[2*nf2+1], aH, t4+2);
        mma16816(oacc[2*nf2],   aL, t4);
        mma16816(oacc[2*nf2+1], aL, t4+2);
      }
    }
  }

  // epilogue: O/l -> fp16 hi/lo split at [token][h*THD + hd]
  float inv0 = 1.f/l0, inv1 = 1.f/l1;
  int q0 = qb*128 + wid*16 + g;
  size_t base0 = ((size_t)(b*TS_) + q0)*(TH*THD) + (size_t)h*THD;
  size_t base1 = base0 + (size_t)8*(TH*THD);
  #pragma unroll
  for (int nf=0; nf<16; nf++){
    int c = nf*8 + 2*tig;
    float v0 = oacc[nf][0]*inv0, v1 = oacc[nf][1]*inv0;
    float w0 = oacc[nf][2]*inv1, w1 = oacc[nf][3]*inv1;
    u16 a0 = h16(v0), a1 = h16(v1), b0 = h16(w0), b1 = h16(w1);
    oh[base0+c] = a0; oh[base0+c+1] = a1;
    ol[base0+c] = h16(v0 - h2f(a0)); ol[base0+c+1] = h16(v1 - h2f(a1));
    oh[base1+c] = b0; oh[base1+c+1] = b1;
    ol[base1+c] = h16(w0 - h2f(b0)); ol[base1+c+1] = h16(w1 - h2f(b1));
  }
}

// ---------------- reduction helpers ----------------
__device__ __forceinline__ float warp_sum(float v){
  #pragma unroll
  for(int o=16;o;o>>=1) v += __shfl_xor_sync(0xffffffffu, v, o);
  return v;
}

// ---------------- LayerNorm ----------------
__global__ void ln_kernel(const float* __restrict__ x, const float* __restrict__ w,
                          float* __restrict__ y, u16* __restrict__ yh, u16* __restrict__ yl){
  int row = blockIdx.x;
  const float* xr = x + (size_t)row*TD;
  float s=0.f, s2=0.f;
  for(int d=threadIdx.x; d<TD; d+=blockDim.x){ float v=xr[d]; s+=v; s2+=v*v; }
  __shared__ float shs[8], shs2[8];
  int lane=threadIdx.x&31, wp=threadIdx.x>>5;
  s = warp_sum(s); s2 = warp_sum(s2);
  if(!lane){ shs[wp]=s; shs2[wp]=s2; }
  __syncthreads();
  if (threadIdx.x < 32){
    float a = (threadIdx.x<8)? shs[threadIdx.x] : 0.f;
    float b = (threadIdx.x<8)? shs2[threadIdx.x] : 0.f;
    a = warp_sum(a); b = warp_sum(b);
    if(!threadIdx.x){ shs[0]=a; shs2[0]=b; }
  }
  __syncthreads();
  float mu = shs[0]*(1.f/TD);
  float var = shs2[0]*(1.f/TD) - mu*mu;
  float rstd = rsqrtf(var + 1e-5f);
  for(int d=threadIdx.x; d<TD; d+=blockDim.x){
    float v = (xr[d]-mu)*rstd*w[d];
    if (y) y[(size_t)row*TD + d] = v;
    u16 h = h16(v);
    yh[(size_t)row*TD + d] = h;
    if (yl) yl[(size_t)row*TD + d] = h16(v - h2f(h));
  }
}

// ---------------- RoPE -> fp16 split (q heads scaled by 1/sqrt(HD)) --------
__global__ void rope_kernel(const float* __restrict__ qkv,
                            const float* __restrict__ cosb,
                            const float* __restrict__ sinb,
                            u16* __restrict__ qh, u16* __restrict__ ql){
  int idx = blockIdx.x*blockDim.x + threadIdx.x;
  const int total = TT*(TH+TKV)*(THD/2);
  if (idx >= total) return;
  int i  = idx & 63;
  int rest = idx >> 6;
  int hh = rest % (TH+TKV);
  int t  = rest / (TH+TKV);
  int s  = t % TS_;
  float c  = cosb[s*THD + i];
  float sn = sinb[s*THD + i];
  const float* p = qkv + (size_t)t*OQKV + hh*THD;
  float sc = (hh < TH) ? 0.088388347648318447f : 1.f;   // 1/sqrt(128)
  float x1 = p[i], x2 = p[i+64];
  float r1 = (x1*c - x2*sn)*sc;
  float r2 = (x2*c + x1*sn)*sc;
  size_t o = (size_t)t*OQKV + hh*THD;
  u16 h1 = h16(r1), h2 = h16(r2);
  qh[o+i] = h1;    ql[o+i]    = h16(r1 - h2f(h1));
  qh[o+i+64] = h2; ql[o+i+64] = h16(r2 - h2f(h2));
}

// ---------------- elementwise ----------------
__global__ void zero_kernel(float* __restrict__ p, int n){
  int i = blockIdx.x*blockDim.x + threadIdx.x;
  if (i<n) p[i]=0.f;
}
__global__ void zero_cnt_kernel(){
  if (threadIdx.x < TE) g_ecnt[threadIdx.x]=0;
}

// ---------------- router ----------------
__global__ void router_kernel(const float* __restrict__ x, const float* __restrict__ wr){
  int t = blockIdx.x;
  int tid = threadIdx.x;
  const float* xr = x + (size_t)t*TD;
  float acc[TE];
  #pragma unroll
  for(int e=0;e<TE;e++) acc[e]=0.f;
  for(int d=tid; d<TD; d+=128){
    float xv = xr[d];
    #pragma unroll
    for(int e=0;e<TE;e++) acc[e] += xv*wr[e*TD+d];
  }
  __shared__ float sh[TE][4];
  int lane=tid&31, wp=tid>>5;
  #pragma unroll
  for(int e=0;e<TE;e++){
    float v = warp_sum(acc[e]);
    if(!lane) sh[e][wp]=v;
  }
  __syncthreads();
  if (tid==0){
    float lg[TE];
    float mx=-1e30f;
    #pragma unroll
    for(int e=0;e<TE;e++){ lg[e]=sh[e][0]+sh[e][1]+sh[e][2]+sh[e][3]; mx=fmaxf(mx,lg[e]); }
    float p[TE]; float s=0.f;
    #pragma unroll
    for(int e=0;e<TE;e++){ p[e]=expf(lg[e]-mx); s+=p[e]; }
    float inv=1.f/s;
    #pragma unroll
    for(int e=0;e<TE;e++) p[e]*=inv;
    int e0=0;
    #pragma unroll
    for(int e=1;e<TE;e++) if (p[e]>p[e0]) e0=e;
    int e1=-1;
    #pragma unroll
    for(int e=0;e<TE;e++){ if(e==e0) continue; if (e1<0 || p[e]>p[e1]) e1=e; }
    float w0=p[e0], w1=p[e1];
    float tot = w0+w1;
    w0/=tot; w1/=tot;
    int pos = atomicAdd(&g_ecnt[e0],1);
    g_elist[e0*TT+pos]=t; g_ew[e0*TT+pos]=w0;
    pos = atomicAdd(&g_ecnt[e1],1);
    g_elist[e1*TT+pos]=t; g_ew[e1*TT+pos]=w1;
  }
}

// ---------------- launcher ----------------
extern "C" void kernel_launch(void* const* d_in, const int* in_sizes, int n_in,
                              void* d_out, int out_size){
  const float* hidden  = (const float*)d_in[0];
  const float* cosb    = (const float*)d_in[1];
  const float* sinb    = (const float*)d_in[2];
  const float* ln1w    = (const float*)d_in[3];
  const float* ln2w    = (const float*)d_in[4];
  const float* wqkv    = (const float*)d_in[5];
  const float* wout    = (const float*)d_in[6];
  const float* wrouter = (const float*)d_in[7];
  const float* wgate   = (const float*)d_in[8];
  const float* wup     = (const float*)d_in[9];
  const float* wdown   = (const float*)d_in[10];
  float* out = (float*)d_out;

  float *p_h,*p_qkv,*p_res,*p_ew;
  int *p_elist,*p_ecnt;
  u16 *p_wqkv,*p_wout,*p_wgu,*p_wd;
  u16 *p_xh,*p_xl,*p_ah,*p_al,*p_gh,*p_qh,*p_ql,*p_vt;
  cudaGetSymbolAddress((void**)&p_h, g_h);
  cudaGetSymbolAddress((void**)&p_qkv, g_qkv);
  cudaGetSymbolAddress((void**)&p_res, g_res);
  cudaGetSymbolAddress((void**)&p_ew, g_ew);
  cudaGetSymbolAddress((void**)&p_elist, g_elist);
  cudaGetSymbolAddress((void**)&p_ecnt, g_ecnt);
  cudaGetSymbolAddress((void**)&p_wqkv, g_wqkv_h);
  cudaGetSymbolAddress((void**)&p_wout, g_wout_h);
  cudaGetSymbolAddress((void**)&p_wgu, g_wgu_h);
  cudaGetSymbolAddress((void**)&p_wd, g_wd_h);
  cudaGetSymbolAddress((void**)&p_xh, g_xh);
  cudaGetSymbolAddress((void**)&p_xl, g_xl);
  cudaGetSymbolAddress((void**)&p_ah, g_ah);
  cudaGetSymbolAddress((void**)&p_al, g_al);
  cudaGetSymbolAddress((void**)&p_gh, g_gh);
  cudaGetSymbolAddress((void**)&p_qh, g_qh);
  cudaGetSymbolAddress((void**)&p_ql, g_ql);
  cudaGetSymbolAddress((void**)&p_vt, g_vt);

  const int SMEM_S = 2*3*MATB;
  const int SMEM_N = 3*2*MATB;
  cudaFuncSetAttribute(tgemm<0,false,0,true>,  cudaFuncAttributeMaxDynamicSharedMemorySize, SMEM_S);
  cudaFuncSetAttribute(tgemm<2,false,0,true>,  cudaFuncAttributeMaxDynamicSharedMemorySize, SMEM_S);
  cudaFuncSetAttribute(tgemm<1,true,3,false>,  cudaFuncAttributeMaxDynamicSharedMemorySize, SMEM_N);
  cudaFuncSetAttribute(tgemm<3,false,4,false>, cudaFuncAttributeMaxDynamicSharedMemorySize, SMEM_N);
  cudaFuncSetAttribute(flashattn, cudaFuncAttributeMaxDynamicSharedMemorySize, FSM);

  const int n_td = TT*TD;
  float* resid = (out_size >= 2*n_td) ? (out + (size_t)n_td) : p_res;

  // ---- fork side stream for independent weight conversions + output zero ----
  cudaStream_t s2;
  cudaStreamCreate(&s2);
  cudaEvent_t evFork, evJoin;
  cudaEventCreateWithFlags(&evFork, cudaEventDisableTiming);
  cudaEventCreateWithFlags(&evJoin, cudaEventDisableTiming);
  cudaEventRecord(evFork, 0);
  cudaStreamWaitEvent(s2, evFork, 0);

  convhalf<<<(TD*TD/4+255)/256,256,0,s2>>>(wout, p_wout, TD*TD/4);
  transhalf<<<dim3(TF/32, TD/32, TE), dim3(32,8),0,s2>>>(wgate, p_wgu, TD, TF,
      (size_t)TD*TF, (size_t)2*TF*TD, 2, 0);
  transhalf<<<dim3(TF/32, TD/32, TE), dim3(32,8),0,s2>>>(wup, p_wgu, TD, TF,
      (size_t)TD*TF, (size_t)2*TF*TD, 2, 1);
  transhalf<<<dim3(TD/32, TF/32, TE), dim3(32,8),0,s2>>>(wdown, p_wd, TF, TD,
      (size_t)TF*TD, (size_t)TD*TF, 1, 0);
  zero_kernel<<<(n_td+255)/256,256,0,s2>>>(out, n_td);
  cudaEventRecord(evJoin, s2);

  // main stream: attention chain
  convhalf<<<(OQKV*TD/4+255)/256,256>>>(wqkv, p_wqkv, OQKV*TD/4);
  ln_kernel<<<TT,256>>>(hidden, ln1w, nullptr, p_xh, p_xl);
  tgemm<0,false,0,true><<<dim3(OQKV/128, TT/128), 256, SMEM_S>>>(
      TT, OQKV, TD, p_xh, p_xl, TD, p_wqkv, TD,
      p_qkv, OQKV, 1.f, nullptr, nullptr, nullptr, 0,0,0);
  {
    int total = TT*(TH+TKV)*(THD/2);
    rope_kernel<<<(total+255)/256,256>>>(p_qkv, cosb, sinb, p_qh, p_ql);
  }
  vtrans<<<dim3(TS_/32, THD/32, TBATCH*TKV), dim3(32,8)>>>(p_qkv, p_vt);

  // fused flash attention -> ah/al (fp16 hi/lo)
  flashattn<<<dim3(TBATCH*TH, TS_/128), 256, FSM>>>(p_qh, p_ql, p_vt, p_ah, p_al);

  // join side stream before out-proj
  cudaStreamWaitEvent(0, evJoin, 0);

  // out-proj (split A) with fused residual add -> resid
  tgemm<2,false,0,true><<<dim3(TD/128, TT/128), 256, SMEM_S>>>(
      TT, TD, TH*THD, p_ah, p_al, TH*THD, p_wout, TH*THD,
      resid, TD, 1.f, nullptr, hidden, nullptr, 0,0,0);

  // LN2 (fp32 h for router + hi only for MoE)
  ln_kernel<<<TT,256>>>(resid, ln2w, p_h, p_xh, nullptr);

  // router
  zero_cnt_kernel<<<1,32>>>();
  router_kernel<<<TT,128>>>(p_h, wrouter);

  // MoE: GU GEMM with fused silu -> gh (fp16), then down (atomic scatter)
  tgemm<1,true,3,false><<<dim3(2*TF/128, TT/128, TE), 256, SMEM_N>>>(
      TT, 2*TF, TD, p_xh, nullptr, TD, p_wgu, TD,
      (float*)p_gh, 2*TF, 1.f, p_elist, nullptr, p_ecnt,
      0, (size_t)2*TF*TD, (size_t)TT*TF);
  tgemm<3,false,4,false><<<dim3(TD/128, TT/128, TE), 256, SMEM_N>>>(
      TT, TD, TF, p_gh, nullptr, TF, p_wd, TF,
      out, TD, 1.f, p_elist, p_ew, p_ecnt,
      (size_t)TT*TF, (size_t)TD*TF, 0);

  cudaStreamDestroy(s2);
  cudaEventDestroy(evFork);
  cudaEventDestroy(evJoin);
}

// round 15
// speedup vs baseline: 13.7737x; 1.0254x over previous
#include <cuda_runtime.h>
#include <cuda_fp16.h>
#include <math.h>
#include <stdint.h>

// Problem constants
#define TS_ 1024
#define TBATCH 2
#define TD 2048
#define TH 16
#define TKV 4
#define THD 128
#define TE 8
#define TF 2048
#define TT (TBATCH*TS_)            // 2048 tokens
#define OQKV ((TH+2*TKV)*THD)      // 3072
#define REP (TH/TKV)               // 4

typedef unsigned short u16;

// ---------------- scratch (device globals) ----------
__device__ float g_h[(size_t)TT*TD];
__device__ float g_qkv[(size_t)TT*OQKV];
__device__ float g_res[(size_t)TT*TD];
__device__ int   g_elist[TE*TT];
__device__ float g_ew[TE*TT];
__device__ int   g_ecnt[TE];

// fp16 buffers
__device__ u16 g_wqkv_h[(size_t)OQKV*TD];
__device__ u16 g_wout_h[(size_t)TD*TD];
__device__ u16 g_wgu_h[(size_t)TE*2*TF*TD];    // [e][2F][D], rows interleaved gate/up
__device__ u16 g_wd_h[(size_t)TE*TD*TF];       // [e][D][F]
__device__ u16 g_xh[(size_t)TT*TD],  g_xl[(size_t)TT*TD];
__device__ u16 g_ah[(size_t)TT*TD],  g_al[(size_t)TT*TD];
__device__ u16 g_gh[(size_t)TE*TT*TF];
__device__ u16 g_qh[(size_t)TT*OQKV];
__device__ u16 g_vt[(size_t)TBATCH*TKV*THD*TS_];

// ---------------- helpers ----------------
__device__ __forceinline__ u16 h16(float x){
  __half h = __float2half_rn(x);
  return *reinterpret_cast<u16*>(&h);
}
__device__ __forceinline__ float h2f(u16 b){
  __half h = *reinterpret_cast<__half*>(&b);
  return __half2float(h);
}
__device__ __forceinline__ uint32_t smem_u32(const void* p){
  uint32_t a;
  asm("{ .reg .u64 t; cvta.to.shared.u64 t, %1; cvt.u32.u64 %0, t; }" : "=r"(a) : "l"(p));
  return a;
}
__device__ __forceinline__ void ldsm_x4(uint32_t* r, uint32_t addr){
  asm volatile("ldmatrix.sync.aligned.m8n8.x4.shared.b16 {%0,%1,%2,%3}, [%4];"
    : "=r"(r[0]),"=r"(r[1]),"=r"(r[2]),"=r"(r[3]) : "r"(addr));
}
__device__ __forceinline__ void mma16816(float* c, const uint32_t* a, const uint32_t* b){
  asm volatile("mma.sync.aligned.m16n8k16.row.col.f32.f16.f16.f32 "
    "{%0,%1,%2,%3}, {%4,%5,%6,%7}, {%8,%9}, {%0,%1,%2,%3};"
    : "+f"(c[0]),"+f"(c[1]),"+f"(c[2]),"+f"(c[3])
    : "r"(a[0]),"r"(a[1]),"r"(a[2]),"r"(a[3]), "r"(b[0]),"r"(b[1]));
}
__device__ __forceinline__ void cp16(uint32_t dst, const void* src, int ssz){
  asm volatile("cp.async.cg.shared.global [%0], [%1], 16, %2;"
    :: "r"(dst), "l"(src), "r"(ssz) : "memory");
}
__device__ __forceinline__ void cp16f(uint32_t dst, const void* src){
  asm volatile("cp.async.cg.shared.global [%0], [%1], 16;"
    :: "r"(dst), "l"(src) : "memory");
}
#define CP_COMMIT() asm volatile("cp.async.commit_group;":::"memory")
#define CP_WAIT(n)  asm volatile("cp.async.wait_group %0;"::"n"(n):"memory")

// ---------------- conversion kernels ----------------
__global__ void convhalf(const float* __restrict__ src, u16* __restrict__ d, int n4){
  int i = blockIdx.x*blockDim.x + threadIdx.x;
  if (i >= n4) return;
  float4 v = reinterpret_cast<const float4*>(src)[i];
  ushort4 hv; hv.x=h16(v.x); hv.y=h16(v.y); hv.z=h16(v.z); hv.w=h16(v.w);
  reinterpret_cast<ushort4*>(d)[i]=hv;
}
__global__ void transhalf(const float* __restrict__ src, u16* __restrict__ dst,
                          int R, int C, size_t sstr, size_t dstr, int rmul, int roff){
  __shared__ float t[32][33];
  src += (size_t)blockIdx.z * sstr;
  dst += (size_t)blockIdx.z * dstr;
  int c0 = blockIdx.x*32, r0 = blockIdx.y*32;
  int tx = threadIdx.x, ty = threadIdx.y;
  #pragma unroll
  for (int j=0;j<4;j++)
    t[ty+j*8][tx] = src[(size_t)(r0+ty+j*8)*C + c0+tx];
  __syncthreads();
  #pragma unroll
  for (int j=0;j<4;j++)
    dst[(size_t)(rmul*(c0+ty+j*8)+roff)*R + r0+tx] = h16(t[tx][ty+j*8]);
}
__global__ void vtrans(const float* __restrict__ qkv, u16* __restrict__ vt){
  __shared__ float t[32][33];
  int z = blockIdx.z; int b = z/TKV, kv = z%TKV;
  int s0 = blockIdx.x*32, h0 = blockIdx.y*32;
  int tx = threadIdx.x, ty = threadIdx.y;
  #pragma unroll
  for (int j=0;j<4;j++){
    int s = s0+ty+j*8;
    t[ty+j*8][tx] = qkv[(size_t)(b*TS_+s)*OQKV + (TH+TKV+kv)*THD + h0+tx];
  }
  __syncthreads();
  #pragma unroll
  for (int j=0;j<4;j++){
    int hd = h0+ty+j*8;
    vt[((size_t)z*THD + hd)*TS_ + s0+tx] = h16(t[tx][ty+j*8]);
  }
}

// ---------------- tensor-core GEMM (fp16, optional A hi/lo split) ----------
#define TPAD 144
#define MATB (128*TPAD)   // 18432

template<int EPI, bool GATHER, int ADDR, bool ASPLIT>
__global__ __launch_bounds__(256,2) void tgemm(
    int M, int N, int K,
    const u16* __restrict__ Ah, const u16* __restrict__ Al, int lda,
    const u16* __restrict__ Bh, int ldb,
    float* __restrict__ C, int ldc, float alpha,
    const int* __restrict__ arow, const float* __restrict__ aw,
    const int* __restrict__ cntp,
    size_t astride, size_t bstride, size_t cstride)
{
  constexpr int NMAT = ASPLIT ? 3 : 2;
  constexpr int NST  = ASPLIT ? 2 : 3;
  constexpr int STB  = NMAT*MATB;
  constexpr int BOFF = (ASPLIT ? 2 : 1)*MATB;
  extern __shared__ __align__(16) char smem[];
  int row0 = blockIdx.y*128, col0 = blockIdx.x*128;
  int Klim = K;

  if (ADDR==3 || ADDR==4){
    int z = blockIdx.z;
    arow += z*TT;
    if (ADDR==4){ aw += z*TT; Ah += (size_t)z*astride; }
    cntp += z;
    Bh += (size_t)z*bstride;
    if (EPI != 1) C += (size_t)z*cstride;
  }

  int Meff = cntp ? *cntp : M;
  if (row0 >= Meff) return;

  int tid = threadIdx.x, wid = tid>>5, lane = tid&31;
  int wm = wid>>2, wn = wid&3;
  uint32_t sbase = smem_u32(smem);

  uint32_t laneA  = (uint32_t)((lane&15)*TPAD) + (uint32_t)((lane>>4)*16);
  uint32_t laneB4 = (uint32_t)((lane&7)*TPAD) + (uint32_t)(((lane>>3)&1)*16)
                  + (uint32_t)((lane>>4)*(8*TPAD));

  float acc[4][4][4];
  #pragma unroll
  for(int i=0;i<4;i++)
    #pragma unroll
    for(int j=0;j<4;j++)
      #pragma unroll
      for(int q=0;q<4;q++) acc[i][j][q]=0.f;

  const int NC = Klim/64;

  int c16 = tid&7, rt = tid>>3;
  uint32_t doff0 = (uint32_t)(rt*TPAD + c16*16);
  long aoff[4]; int apred[4];
  #pragma unroll
  for (int it=0; it<4; it++){
    int gm = row0 + rt + it*32;
    apred[it] = gm < Meff;
    long src = apred[it] ? ((GATHER||ADDR==3) ? (long)arow[gm] : (long)gm) : 0;
    aoff[it] = src*(long)lda + c16*8;
  }
  const u16* pb0 = Bh + (long)(col0 + rt)*ldb + c16*8;

  auto issue = [&](int c){
    uint32_t dst0 = sbase + (c%NST)*STB;
    int k0 = c*64;
    #pragma unroll
    for (int it=0; it<4; it++){
      uint32_t d = dst0 + doff0 + it*32*TPAD;
      int ssz = apred[it] ? 16 : 0;
      cp16(d, Ah + aoff[it] + k0, ssz);
      if (ASPLIT) cp16(d + MATB, Al + aoff[it] + k0, ssz);
      cp16f(d + BOFF, pb0 + (long)it*32*ldb + k0);
    }
    CP_COMMIT();
  };

  issue(0);
  if (NST >= 3 && NC > 1) issue(1);
  for (int c = 0; c < NC; c++){
    if (NST == 2){
      CP_WAIT(0);
    } else {
      if (c+1 < NC) { CP_WAIT(1); } else { CP_WAIT(0); }
    }
    __syncthreads();
    if (NST == 2){ if (c+1 < NC) issue(c+1); }
    else         { if (c+2 < NC) issue(c+2); }

    uint32_t st = sbase + (c%NST)*STB;
    #pragma unroll
    for (int ks = 0; ks < 4; ks++){
      uint32_t rowA = st + (uint32_t)((wm*64)*TPAD + ks*32) + laneA;
      uint32_t rowB = st + BOFF + (uint32_t)((wn*32)*TPAD + ks*32) + laneB4;
      uint32_t aH[4][4], bH[4][2];
      #pragma unroll
      for (int mf=0; mf<4; mf++) ldsm_x4(aH[mf], rowA + mf*16*TPAD);
      #pragma unroll
      for (int np=0; np<2; np++){
        uint32_t t4[4];
        ldsm_x4(t4, rowB + np*16*TPAD);
        bH[2*np][0]=t4[0]; bH[2*np][1]=t4[1];
        bH[2*np+1][0]=t4[2]; bH[2*np+1][1]=t4[3];
      }
      #pragma unroll
      for (int mf=0; mf<4; mf++)
        #pragma unroll
        for (int nf=0; nf<4; nf++) mma16816(acc[mf][nf], aH[mf], bH[nf]);
      if (ASPLIT){
        uint32_t aL[4][4];
        #pragma unroll
        for (int mf=0; mf<4; mf++) ldsm_x4(aL[mf], rowA + MATB + mf*16*TPAD);
        #pragma unroll
        for (int mf=0; mf<4; mf++)
          #pragma unroll
          for (int nf=0; nf<4; nf++) mma16816(acc[mf][nf], aL[mf], bH[nf]);
      }
    }
  }

  // ---- epilogue ----
  int g = lane>>2, tig = lane&3;
  u16* G = nullptr;
  if (EPI == 1) G = reinterpret_cast<u16*>(C) + (size_t)blockIdx.z*cstride;
  #pragma unroll
  for (int mf=0; mf<4; mf++){
    int ra = row0 + wm*64 + mf*16 + g;
    int rb = ra + 8;
    #pragma unroll
    for (int nf=0; nf<4; nf++){
      int col = col0 + wn*32 + nf*8 + tig*2;
      float* cacc = acc[mf][nf];
      if (EPI == 0){
        if (ra < Meff){
          float* p = C + (size_t)ra*ldc + col;
          p[0] = cacc[0]*alpha; p[1] = cacc[1]*alpha;
        }
        if (rb < Meff){
          float* p = C + (size_t)rb*ldc + col;
          p[0] = cacc[2]*alpha; p[1] = cacc[3]*alpha;
        }
      } else if (EPI == 1){
        int f = col >> 1;
        if (ra < Meff){
          float gg = cacc[0];
          G[(size_t)ra*(ldc>>1) + f] = h16((gg/(1.f+__expf(-gg)))*cacc[1]);
        }
        if (rb < Meff){
          float gg = cacc[2];
          G[(size_t)rb*(ldc>>1) + f] = h16((gg/(1.f+__expf(-gg)))*cacc[3]);
        }
      } else if (EPI == 2){
        if (ra < Meff){
          float* p = C + (size_t)ra*ldc + col;
          const float* hr = aw + (size_t)ra*ldc + col;
          p[0] = cacc[0]*alpha + hr[0]; p[1] = cacc[1]*alpha + hr[1];
        }
        if (rb < Meff){
          float* p = C + (size_t)rb*ldc + col;
          const float* hr = aw + (size_t)rb*ldc + col;
          p[0] = cacc[2]*alpha + hr[0]; p[1] = cacc[3]*alpha + hr[1];
        }
      } else {
        if (ra < Meff){
          float w = aw[ra];
          float* p = C + (size_t)arow[ra]*ldc + col;
          atomicAdd(p,   w*cacc[0]*alpha);
          atomicAdd(p+1, w*cacc[1]*alpha);
        }
        if (rb < Meff){
          float w = aw[rb];
          float* p = C + (size_t)arow[rb]*ldc + col;
          atomicAdd(p,   w*cacc[2]*alpha);
          atomicAdd(p+1, w*cacc[3]*alpha);
        }
      }
    }
  }
}

// ---------------- fused flash attention (single-fp16 Q, K, V, P) ----------
// grid (TBATCH*TH, 8): z = b*TH+h, qb descending. 8 warps x 16 q-rows.
// Tiles 128 rows x 128 fp16 (256B data); row stride FTP=272.
// Q single-fp16 in smem once; K/V double-buffered. S,P,O fp32 in registers.
// Output: fp16 hi/lo split -> ah/al (out-proj A stays split).
#define FTP 272
#define FMAT (128*FTP)            // 34816
#define FSM  (FMAT + 2*2*FMAT)    // Qh + 2 stages x (K,V) = 174080

__global__ __launch_bounds__(256,1) void flashattn(
    const u16* __restrict__ qh,
    const u16* __restrict__ vt,
    u16* __restrict__ oh, u16* __restrict__ ol)
{
  extern __shared__ __align__(16) char smem[];
  int z = blockIdx.x;
  int qb = (int)(gridDim.y - 1 - blockIdx.y);   // long blocks first
  int b = z/TH, h = z%TH;
  int NT = qb + 1;
  uint32_t sb = smem_u32(smem);
  int tid = threadIdx.x, wid = tid>>5, lane = tid&31;
  int g = lane>>2, tig = lane&3;

  const u16* Qsrc = qh + ((size_t)(b*TS_ + qb*128))*OQKV + h*THD;
  const u16* Ksrc = qh + (size_t)(b*TS_)*OQKV + (TH + h/REP)*THD;
  const u16* Vsrc = vt + ((size_t)(b*TKV + h/REP))*THD*TS_;

  int lr = tid & 127, lhalf = tid >> 7;   // row, 64-half selector

  // Q load (hi only), committed together with KV stage 0
  {
    uint32_t dq = sb + (uint32_t)(lr*FTP + lhalf*128);
    const u16* sq = Qsrc + (long)lr*OQKV + lhalf*64;
    #pragma unroll
    for (int i=0;i<8;i++)
      cp16f(dq + i*16, sq + i*8);
  }
  auto issueKV = [&](int t){
    uint32_t dst = sb + FMAT + (uint32_t)((t&1)*(2*FMAT));
    uint32_t dk = dst + (uint32_t)(lr*FTP + lhalf*128);
    const u16* sk = Ksrc + ((long)(t*128 + lr))*OQKV + lhalf*64;
    const u16* sv = Vsrc + (long)lr*TS_ + t*128 + lhalf*64;
    #pragma unroll
    for (int i=0;i<8;i++){
      cp16f(dk + i*16,        sk + i*8);
      cp16f(dk + FMAT + i*16, sv + i*8);
    }
    CP_COMMIT();
  };
  issueKV(0);

  float sacc[16][4], oacc[16][4];
  float m0=-1e30f, m1=-1e30f, l0=0.f, l1=0.f;
  #pragma unroll
  for (int i=0;i<16;i++){ oacc[i][0]=0.f; oacc[i][1]=0.f; oacc[i][2]=0.f; oacc[i][3]=0.f; }

  uint32_t laneA  = (uint32_t)((lane&15)*FTP) + (uint32_t)((lane>>4)*16);
  uint32_t laneB4 = (uint32_t)((lane&7)*FTP) + (uint32_t)(((lane>>3)&1)*16)
                  + (uint32_t)((lane>>4)*(8*FTP));
  uint32_t qbase = sb + (uint32_t)(wid*16*FTP) + laneA;

  for (int t=0; t<NT; t++){
    CP_WAIT(0);
    __syncthreads();
    if (t+1 < NT) issueKV(t+1);

    uint32_t kb = sb + FMAT + (uint32_t)((t&1)*(2*FMAT));
    uint32_t vb = kb + FMAT;

    // S = Q K^T (Q pre-scaled)
    #pragma unroll
    for (int i=0;i<16;i++){ sacc[i][0]=0.f; sacc[i][1]=0.f; sacc[i][2]=0.f; sacc[i][3]=0.f; }
    #pragma unroll
    for (int kg=0; kg<8; kg++){
      uint32_t aH[4];
      ldsm_x4(aH, qbase + kg*32);
      #pragma unroll
      for (int nf2=0; nf2<8; nf2++){
        uint32_t t4[4];
        ldsm_x4(t4, kb + laneB4 + nf2*16*FTP + kg*32);
        mma16816(sacc[2*nf2],   aH, t4);
        mma16816(sacc[2*nf2+1], aH, t4+2);
      }
    }

    // causal mask on diagonal tile
    if (t == qb){
      int r0 = wid*16 + g, r1 = r0 + 8;
      #pragma unroll
      for (int nf=0; nf<16; nf++){
        int c = nf*8 + 2*tig;
        if (c   > r0) sacc[nf][0] = -1e30f;
        if (c+1 > r0) sacc[nf][1] = -1e30f;
        if (c   > r1) sacc[nf][2] = -1e30f;
        if (c+1 > r1) sacc[nf][3] = -1e30f;
      }
    }

    // online softmax
    float mr0=-1e30f, mr1=-1e30f;
    #pragma unroll
    for (int nf=0; nf<16; nf++){
      mr0 = fmaxf(mr0, fmaxf(sacc[nf][0], sacc[nf][1]));
      mr1 = fmaxf(mr1, fmaxf(sacc[nf][2], sacc[nf][3]));
    }
    mr0 = fmaxf(mr0, __shfl_xor_sync(0xffffffffu, mr0, 1));
    mr0 = fmaxf(mr0, __shfl_xor_sync(0xffffffffu, mr0, 2));
    mr1 = fmaxf(mr1, __shfl_xor_sync(0xffffffffu, mr1, 1));
    mr1 = fmaxf(mr1, __shfl_xor_sync(0xffffffffu, mr1, 2));
    float mn0 = fmaxf(m0, mr0), mn1 = fmaxf(m1, mr1);
    float f0 = __expf(m0 - mn0), f1 = __expf(m1 - mn1);
    float s0 = 0.f, s1 = 0.f;
    #pragma unroll
    for (int nf=0; nf<16; nf++){
      sacc[nf][0] = __expf(sacc[nf][0] - mn0);
      sacc[nf][1] = __expf(sacc[nf][1] - mn0);
      sacc[nf][2] = __expf(sacc[nf][2] - mn1);
      sacc[nf][3] = __expf(sacc[nf][3] - mn1);
      s0 += sacc[nf][0] + sacc[nf][1];
      s1 += sacc[nf][2] + sacc[nf][3];
    }
    s0 += __shfl_xor_sync(0xffffffffu, s0, 1);
    s0 += __shfl_xor_sync(0xffffffffu, s0, 2);
    s1 += __shfl_xor_sync(0xffffffffu, s1, 1);
    s1 += __shfl_xor_sync(0xffffffffu, s1, 2);
    l0 = l0*f0 + s0; l1 = l1*f1 + s1;
    m0 = mn0; m1 = mn1;
    #pragma unroll
    for (int nf=0; nf<16; nf++){
      oacc[nf][0]*=f0; oacc[nf][1]*=f0; oacc[nf][2]*=f1; oacc[nf][3]*=f1;
    }

    // O += P @ V  (P packed hi-only from registers)
    #pragma unroll
    for (int kf=0; kf<8; kf++){
      uint32_t aH[4];
      {
        __half2 hh0 = __floats2half2_rn(sacc[2*kf][0],  sacc[2*kf][1]);
        __half2 hh1 = __floats2half2_rn(sacc[2*kf][2],  sacc[2*kf][3]);
        __half2 hh2 = __floats2half2_rn(sacc[2*kf+1][0],sacc[2*kf+1][1]);
        __half2 hh3 = __floats2half2_rn(sacc[2*kf+1][2],sacc[2*kf+1][3]);
        aH[0]=*reinterpret_cast<uint32_t*>(&hh0);
        aH[1]=*reinterpret_cast<uint32_t*>(&hh1);
        aH[2]=*reinterpret_cast<uint32_t*>(&hh2);
        aH[3]=*reinterpret_cast<uint32_t*>(&hh3);
      }
      #pragma unroll
      for (int nf2=0; nf2<8; nf2++){
        uint32_t t4[4];
        ldsm_x4(t4, vb + laneB4 + nf2*16*FTP + kf*32);
        mma16816(oacc[2*nf2],   aH, t4);
        mma16816(oacc[2*nf2+1], aH, t4+2);
      }
    }
  }

  // epilogue: O/l -> fp16 hi/lo split at [token][h*THD + hd]
  float inv0 = 1.f/l0, inv1 = 1.f/l1;
  int q0 = qb*128 + wid*16 + g;
  size_t base0 = ((size_t)(b*TS_) + q0)*(TH*THD) + (size_t)h*THD;
  size_t base1 = base0 + (size_t)8*(TH*THD);
  #pragma unroll
  for (int nf=0; nf<16; nf++){
    int c = nf*8 + 2*tig;
    float v0 = oacc[nf][0]*inv0, v1 = oacc[nf][1]*inv0;
    float w0 = oacc[nf][2]*inv1, w1 = oacc[nf][3]*inv1;
    u16 a0 = h16(v0), a1 = h16(v1), b0 = h16(w0), b1 = h16(w1);
    oh[base0+c] = a0; oh[base0+c+1] = a1;
    ol[base0+c] = h16(v0 - h2f(a0)); ol[base0+c+1] = h16(v1 - h2f(a1));
    oh[base1+c] = b0; oh[base1+c+1] = b1;
    ol[base1+c] = h16(w0 - h2f(b0)); ol[base1+c+1] = h16(w1 - h2f(b1));
  }
}

// ---------------- reduction helpers ----------------
__device__ __forceinline__ float warp_sum(float v){
  #pragma unroll
  for(int o=16;o;o>>=1) v += __shfl_xor_sync(0xffffffffu, v, o);
  return v;
}

// ---------------- LayerNorm ----------------
__global__ void ln_kernel(const float* __restrict__ x, const float* __restrict__ w,
                          float* __restrict__ y, u16* __restrict__ yh, u16* __restrict__ yl){
  int row = blockIdx.x;
  const float* xr = x + (size_t)row*TD;
  float s=0.f, s2=0.f;
  for(int d=threadIdx.x; d<TD; d+=blockDim.x){ float v=xr[d]; s+=v; s2+=v*v; }
  __shared__ float shs[8], shs2[8];
  int lane=threadIdx.x&31, wp=threadIdx.x>>5;
  s = warp_sum(s); s2 = warp_sum(s2);
  if(!lane){ shs[wp]=s; shs2[wp]=s2; }
  __syncthreads();
  if (threadIdx.x < 32){
    float a = (threadIdx.x<8)? shs[threadIdx.x] : 0.f;
    float b = (threadIdx.x<8)? shs2[threadIdx.x] : 0.f;
    a = warp_sum(a); b = warp_sum(b);
    if(!threadIdx.x){ shs[0]=a; shs2[0]=b; }
  }
  __syncthreads();
  float mu = shs[0]*(1.f/TD);
  float var = shs2[0]*(1.f/TD) - mu*mu;
  float rstd = rsqrtf(var + 1e-5f);
  for(int d=threadIdx.x; d<TD; d+=blockDim.x){
    float v = (xr[d]-mu)*rstd*w[d];
    if (y) y[(size_t)row*TD + d] = v;
    u16 h = h16(v);
    yh[(size_t)row*TD + d] = h;
    if (yl) yl[(size_t)row*TD + d] = h16(v - h2f(h));
  }
}

// ---------------- RoPE -> fp16 (q heads scaled by 1/sqrt(HD)) --------------
__global__ void rope_kernel(const float* __restrict__ qkv,
                            const float* __restrict__ cosb,
                            const float* __restrict__ sinb,
                            u16* __restrict__ qh){
  int idx = blockIdx.x*blockDim.x + threadIdx.x;
  const int total = TT*(TH+TKV)*(THD/2);
  if (idx >= total) return;
  int i  = idx & 63;
  int rest = idx >> 6;
  int hh = rest % (TH+TKV);
  int t  = rest / (TH+TKV);
  int s  = t % TS_;
  float c  = cosb[s*THD + i];
  float sn = sinb[s*THD + i];
  const float* p = qkv + (size_t)t*OQKV + hh*THD;
  float sc = (hh < TH) ? 0.088388347648318447f : 1.f;   // 1/sqrt(128)
  float x1 = p[i], x2 = p[i+64];
  size_t o = (size_t)t*OQKV + hh*THD;
  qh[o+i]    = h16((x1*c - x2*sn)*sc);
  qh[o+i+64] = h16((x2*c + x1*sn)*sc);
}

// ---------------- elementwise ----------------
__global__ void zero_kernel(float* __restrict__ p, int n){
  int i = blockIdx.x*blockDim.x + threadIdx.x;
  if (i<n) p[i]=0.f;
}
__global__ void zero_cnt_kernel(){
  if (threadIdx.x < TE) g_ecnt[threadIdx.x]=0;
}

// ---------------- router ----------------
__global__ void router_kernel(const float* __restrict__ x, const float* __restrict__ wr){
  int t = blockIdx.x;
  int tid = threadIdx.x;
  const float* xr = x + (size_t)t*TD;
  float acc[TE];
  #pragma unroll
  for(int e=0;e<TE;e++) acc[e]=0.f;
  for(int d=tid; d<TD; d+=128){
    float xv = xr[d];
    #pragma unroll
    for(int e=0;e<TE;e++) acc[e] += xv*wr[e*TD+d];
  }
  __shared__ float sh[TE][4];
  int lane=tid&31, wp=tid>>5;
  #pragma unroll
  for(int e=0;e<TE;e++){
    float v = warp_sum(acc[e]);
    if(!lane) sh[e][wp]=v;
  }
  __syncthreads();
  if (tid==0){
    float lg[TE];
    float mx=-1e30f;
    #pragma unroll
    for(int e=0;e<TE;e++){ lg[e]=sh[e][0]+sh[e][1]+sh[e][2]+sh[e][3]; mx=fmaxf(mx,lg[e]); }
    float p[TE]; float s=0.f;
    #pragma unroll
    for(int e=0;e<TE;e++){ p[e]=expf(lg[e]-mx); s+=p[e]; }
    float inv=1.f/s;
    #pragma unroll
    for(int e=0;e<TE;e++) p[e]*=inv;
    int e0=0;
    #pragma unroll
    for(int e=1;e<TE;e++) if (p[e]>p[e0]) e0=e;
    int e1=-1;
    #pragma unroll
    for(int e=0;e<TE;e++){ if(e==e0) continue; if (e1<0 || p[e]>p[e1]) e1=e; }
    float w0=p[e0], w1=p[e1];
    float tot = w0+w1;
    w0/=tot; w1/=tot;
    int pos = atomicAdd(&g_ecnt[e0],1);
    g_elist[e0*TT+pos]=t; g_ew[e0*TT+pos]=w0;
    pos = atomicAdd(&g_ecnt[e1],1);
    g_elist[e1*TT+pos]=t; g_ew[e1*TT+pos]=w1;
  }
}

// ---------------- launcher ----------------
extern "C" void kernel_launch(void* const* d_in, const int* in_sizes, int n_in,
                              void* d_out, int out_size){
  const float* hidden  = (const float*)d_in[0];
  const float* cosb    = (const float*)d_in[1];
  const float* sinb    = (const float*)d_in[2];
  const float* ln1w    = (const float*)d_in[3];
  const float* ln2w    = (const float*)d_in[4];
  const float* wqkv    = (const float*)d_in[5];
  const float* wout    = (const float*)d_in[6];
  const float* wrouter = (const float*)d_in[7];
  const float* wgate   = (const float*)d_in[8];
  const float* wup     = (const float*)d_in[9];
  const float* wdown   = (const float*)d_in[10];
  float* out = (float*)d_out;

  float *p_h,*p_qkv,*p_res,*p_ew;
  int *p_elist,*p_ecnt;
  u16 *p_wqkv,*p_wout,*p_wgu,*p_wd;
  u16 *p_xh,*p_xl,*p_ah,*p_al,*p_gh,*p_qh,*p_vt;
  cudaGetSymbolAddress((void**)&p_h, g_h);
  cudaGetSymbolAddress((void**)&p_qkv, g_qkv);
  cudaGetSymbolAddress((void**)&p_res, g_res);
  cudaGetSymbolAddress((void**)&p_ew, g_ew);
  cudaGetSymbolAddress((void**)&p_elist, g_elist);
  cudaGetSymbolAddress((void**)&p_ecnt, g_ecnt);
  cudaGetSymbolAddress((void**)&p_wqkv, g_wqkv_h);
  cudaGetSymbolAddress((void**)&p_wout, g_wout_h);
  cudaGetSymbolAddress((void**)&p_wgu, g_wgu_h);
  cudaGetSymbolAddress((void**)&p_wd, g_wd_h);
  cudaGetSymbolAddress((void**)&p_xh, g_xh);
  cudaGetSymbolAddress((void**)&p_xl, g_xl);
  cudaGetSymbolAddress((void**)&p_ah, g_ah);
  cudaGetSymbolAddress((void**)&p_al, g_al);
  cudaGetSymbolAddress((void**)&p_gh, g_gh);
  cudaGetSymbolAddress((void**)&p_qh, g_qh);
  cudaGetSymbolAddress((void**)&p_vt, g_vt);

  const int SMEM_S = 2*3*MATB;
  const int SMEM_N = 3*2*MATB;
  cudaFuncSetAttribute(tgemm<0,false,0,true>,  cudaFuncAttributeMaxDynamicSharedMemorySize, SMEM_S);
  cudaFuncSetAttribute(tgemm<2,false,0,true>,  cudaFuncAttributeMaxDynamicSharedMemorySize, SMEM_S);
  cudaFuncSetAttribute(tgemm<1,true,3,false>,  cudaFuncAttributeMaxDynamicSharedMemorySize, SMEM_N);
  cudaFuncSetAttribute(tgemm<3,false,4,false>, cudaFuncAttributeMaxDynamicSharedMemorySize, SMEM_N);
  cudaFuncSetAttribute(flashattn, cudaFuncAttributeMaxDynamicSharedMemorySize, FSM);

  const int n_td = TT*TD;
  float* resid = (out_size >= 2*n_td) ? (out + (size_t)n_td) : p_res;

  // ---- fork side stream for independent weight conversions + output zero ----
  cudaStream_t s2;
  cudaStreamCreate(&s2);
  cudaEvent_t evFork, evJoin;
  cudaEventCreateWithFlags(&evFork, cudaEventDisableTiming);
  cudaEventCreateWithFlags(&evJoin, cudaEventDisableTiming);
  cudaEventRecord(evFork, 0);
  cudaStreamWaitEvent(s2, evFork, 0);

  convhalf<<<(TD*TD/4+255)/256,256,0,s2>>>(wout, p_wout, TD*TD/4);
  transhalf<<<dim3(TF/32, TD/32, TE), dim3(32,8),0,s2>>>(wgate, p_wgu, TD, TF,
      (size_t)TD*TF, (size_t)2*TF*TD, 2, 0);
  transhalf<<<dim3(TF/32, TD/32, TE), dim3(32,8),0,s2>>>(wup, p_wgu, TD, TF,
      (size_t)TD*TF, (size_t)2*TF*TD, 2, 1);
  transhalf<<<dim3(TD/32, TF/32, TE), dim3(32,8),0,s2>>>(wdown, p_wd, TF, TD,
      (size_t)TF*TD, (size_t)TD*TF, 1, 0);
  zero_kernel<<<(n_td+255)/256,256,0,s2>>>(out, n_td);
  cudaEventRecord(evJoin, s2);

  // main stream: attention chain
  convhalf<<<(OQKV*TD/4+255)/256,256>>>(wqkv, p_wqkv, OQKV*TD/4);
  ln_kernel<<<TT,256>>>(hidden, ln1w, nullptr, p_xh, p_xl);
  tgemm<0,false,0,true><<<dim3(OQKV/128, TT/128), 256, SMEM_S>>>(
      TT, OQKV, TD, p_xh, p_xl, TD, p_wqkv, TD,
      p_qkv, OQKV, 1.f, nullptr, nullptr, nullptr, 0,0,0);
  {
    int total = TT*(TH+TKV)*(THD/2);
    rope_kernel<<<(total+255)/256,256>>>(p_qkv, cosb, sinb, p_qh);
  }
  vtrans<<<dim3(TS_/32, THD/32, TBATCH*TKV), dim3(32,8)>>>(p_qkv, p_vt);

  // fused flash attention -> ah/al (fp16 hi/lo)
  flashattn<<<dim3(TBATCH*TH, TS_/128), 256, FSM>>>(p_qh, p_vt, p_ah, p_al);

  // join side stream before out-proj
  cudaStreamWaitEvent(0, evJoin, 0);

  // out-proj (split A) with fused residual add -> resid
  tgemm<2,false,0,true><<<dim3(TD/128, TT/128), 256, SMEM_S>>>(
      TT, TD, TH*THD, p_ah, p_al, TH*THD, p_wout, TH*THD,
      resid, TD, 1.f, nullptr, hidden, nullptr, 0,0,0);

  // LN2 (fp32 h for router + hi only for MoE)
  ln_kernel<<<TT,256>>>(resid, ln2w, p_h, p_xh, nullptr);

  // router
  zero_cnt_kernel<<<1,32>>>();
  router_kernel<<<TT,128>>>(p_h, wrouter);

  // MoE: GU GEMM with fused silu -> gh (fp16), then down (atomic scatter)
  tgemm<1,true,3,false><<<dim3(2*TF/128, TT/128, TE), 256, SMEM_N>>>(
      TT, 2*TF, TD, p_xh, nullptr, TD, p_wgu, TD,
      (float*)p_gh, 2*TF, 1.f, p_elist, nullptr, p_ecnt,
      0, (size_t)2*TF*TD, (size_t)TT*TF);
  tgemm<3,false,4,false><<<dim3(TD/128, TT/128, TE), 256, SMEM_N>>>(
      TT, TD, TF, p_gh, nullptr, TF, p_wd, TF,
      out, TD, 1.f, p_elist, p_ew, p_ecnt,
      (size_t)TT*TF, (size_t)TD*TF, 0);

  cudaStreamDestroy(s2);
  cudaEventDestroy(evFork);
  cudaEventDestroy(evJoin);
}